// round 9
// baseline (speedup 1.0000x reference)
#include <cuda_runtime.h>
#include <cuda_fp16.h>
#include <math.h>
#include <stdint.h>

// ---------------- problem constants ----------------
#define BB 4
#define TT 4096
#define CC 1024
#define HH 16
#define NHD 64
#define QQ 256
#define NCK 16
#define MTOT (BB*TT)          // 16384
#define BTC (BB*TT*CC)        // 16777216
#define EPS_LN 1e-5f
#define EPS_GN (1e-5f*64.0f)

// ---------------- scratch ----------------
#define SCR_TOTAL (19ull*BTC + 8388608ull + 12582912ull)
__device__ float g_scratch[SCR_TOTAL];

#define OFF_XK   (1ull*BTC)      // fp16 buffers
#define OFF_XV   (2ull*BTC)
#define OFF_XR   (3ull*BTC)
#define OFF_XG   (4ull*BTC)
#define OFF_R    (5ull*BTC)      // fp32
#define OFF_K    (6ull*BTC)
#define OFF_V    (7ull*BTC)
#define OFF_G    (8ull*BTC)
#define OFF_Y    (9ull*BTC)
#define OFF_YG   (10ull*BTC)     // fp16
#define OFF_X1   (11ull*BTC)     // fp32
#define OFF_XK2  (13ull*BTC)     // fp16
#define OFF_XR2  (14ull*BTC)     // fp16
#define OFF_HV   (15ull*BTC)     // fp32
#define OFF_H    (16ull*BTC)     // fp16 [16384,3072]
#define OFF_S    (19ull*BTC)
#define OFF_ST   (19ull*BTC + 4194304ull)
#define OFF_WT   (19ull*BTC + 8388608ull)
#define OFF_WR_R  (OFF_WT + 0ull)
#define OFF_WK_R  (OFF_WT + 1048576ull)
#define OFF_WV_R  (OFF_WT + 2097152ull)
#define OFF_WG_R  (OFF_WT + 3145728ull)
#define OFF_WO_R  (OFF_WT + 4194304ull)
#define OFF_WCR_R (OFF_WT + 5242880ull)
#define OFF_WCK_R (OFF_WT + 6291456ull)
#define OFF_WCV_R (OFF_WT + 9437184ull)

// ---------------- helpers ----------------
__device__ __forceinline__ uint32_t smem_u32(const void* p) {
    uint32_t a;
    asm("{ .reg .u64 t; cvta.to.shared.u64 t, %1; cvt.u32.u64 %0, t; }" : "=r"(a) : "l"(p));
    return a;
}

__device__ __forceinline__ uint32_t pack_f16(float a, float b) {
    __half2 h = __floats2half2_rn(a, b);
    return *(uint32_t*)&h;
}

__device__ __forceinline__ void cp16(uint32_t dst, const void* src) {
    asm volatile("cp.async.cg.shared.global [%0], [%1], 16;" :: "r"(dst), "l"(src) : "memory");
}
#define CP_COMMIT() asm volatile("cp.async.commit_group;" ::: "memory")
#define CP_WAIT_2() asm volatile("cp.async.wait_group 2;" ::: "memory")

// ---------------- weight fp32 -> fp16 ----------------
__global__ __launch_bounds__(256) void cvt_w_kernel(const float* __restrict__ src,
                                                    __half* __restrict__ dst, int n4)
{
    int i = blockIdx.x * 256 + threadIdx.x;
    if (i < n4) {
        float4 v = ((const float4*)src)[i];
        uint2 o;
        o.x = pack_f16(v.x, v.y);
        o.y = pack_f16(v.z, v.w);
        ((uint2*)dst)[i] = o;
    }
}

// ---------------- fused LayerNorm + time-shift mix (fp16 outputs) ----------------
template<int NOUT>
__global__ __launch_bounds__(256) void ln_mix_kernel(const float* __restrict__ x,
                                                     const float* __restrict__ w,
                                                     const float* __restrict__ b,
                                                     const float* __restrict__ m0,
                                                     const float* __restrict__ m1,
                                                     const float* __restrict__ m2,
                                                     const float* __restrict__ m3,
                                                     __half* __restrict__ o0,
                                                     __half* __restrict__ o1,
                                                     __half* __restrict__ o2,
                                                     __half* __restrict__ o3)
{
    int row = blockIdx.x;
    int t = row % TT;
    int tid = threadIdx.x;
    size_t off = (size_t)row * CC;
    float4 cur = ((const float4*)(x + off))[tid];
    float4 prv = make_float4(0.f, 0.f, 0.f, 0.f);
    if (t > 0) prv = ((const float4*)(x + off - CC))[tid];

    float s0 = cur.x + cur.y + cur.z + cur.w;
    float q0 = cur.x*cur.x + cur.y*cur.y + cur.z*cur.z + cur.w*cur.w;
    float s1 = prv.x + prv.y + prv.z + prv.w;
    float q1 = prv.x*prv.x + prv.y*prv.y + prv.z*prv.z + prv.w*prv.w;
    #pragma unroll
    for (int o = 16; o >= 1; o >>= 1) {
        s0 += __shfl_xor_sync(0xffffffffu, s0, o);
        q0 += __shfl_xor_sync(0xffffffffu, q0, o);
        s1 += __shfl_xor_sync(0xffffffffu, s1, o);
        q1 += __shfl_xor_sync(0xffffffffu, q1, o);
    }
    __shared__ float red[4][8];
    int wid = tid >> 5, lane = tid & 31;
    if (lane == 0) { red[0][wid] = s0; red[1][wid] = q0; red[2][wid] = s1; red[3][wid] = q1; }
    __syncthreads();
    if (tid == 0) {
        float a0 = 0, a1 = 0, a2 = 0, a3 = 0;
        #pragma unroll
        for (int i = 0; i < 8; i++) { a0 += red[0][i]; a1 += red[1][i]; a2 += red[2][i]; a3 += red[3][i]; }
        red[0][0] = a0; red[1][0] = a1; red[2][0] = a2; red[3][0] = a3;
    }
    __syncthreads();
    float mu0 = red[0][0] * (1.0f / CC);
    float rs0 = rsqrtf(red[1][0] * (1.0f / CC) - mu0 * mu0 + EPS_LN);
    float mu1 = red[2][0] * (1.0f / CC);
    float rs1 = rsqrtf(red[3][0] * (1.0f / CC) - mu1 * mu1 + EPS_LN);

    float4 ww = ((const float4*)w)[tid];
    float4 bb = ((const float4*)b)[tid];
    float4 lc, lp;
    lc.x = (cur.x - mu0) * rs0 * ww.x + bb.x;
    lc.y = (cur.y - mu0) * rs0 * ww.y + bb.y;
    lc.z = (cur.z - mu0) * rs0 * ww.z + bb.z;
    lc.w = (cur.w - mu0) * rs0 * ww.w + bb.w;
    if (t > 0) {
        lp.x = (prv.x - mu1) * rs1 * ww.x + bb.x;
        lp.y = (prv.y - mu1) * rs1 * ww.y + bb.y;
        lp.z = (prv.z - mu1) * rs1 * ww.z + bb.z;
        lp.w = (prv.w - mu1) * rs1 * ww.w + bb.w;
    } else {
        lp = make_float4(0.f, 0.f, 0.f, 0.f);
    }
    float4 xx = make_float4(lp.x - lc.x, lp.y - lc.y, lp.z - lc.z, lp.w - lc.w);

    float4 a;
    uint2 o;
    a = ((const float4*)m0)[tid];
    o.x = pack_f16(lc.x + xx.x * a.x, lc.y + xx.y * a.y);
    o.y = pack_f16(lc.z + xx.z * a.z, lc.w + xx.w * a.w);
    ((uint2*)(o0 + off))[tid] = o;
    a = ((const float4*)m1)[tid];
    o.x = pack_f16(lc.x + xx.x * a.x, lc.y + xx.y * a.y);
    o.y = pack_f16(lc.z + xx.z * a.z, lc.w + xx.w * a.w);
    ((uint2*)(o1 + off))[tid] = o;
    if (NOUT == 4) {
        a = ((const float4*)m2)[tid];
        o.x = pack_f16(lc.x + xx.x * a.x, lc.y + xx.y * a.y);
        o.y = pack_f16(lc.z + xx.z * a.z, lc.w + xx.w * a.w);
        ((uint2*)(o2 + off))[tid] = o;
        a = ((const float4*)m3)[tid];
        o.x = pack_f16(lc.x + xx.x * a.x, lc.y + xx.y * a.y);
        o.y = pack_f16(lc.z + xx.z * a.z, lc.w + xx.w * a.w);
        ((uint2*)(o3 + off))[tid] = o;
    }
}

// ---------------- fp16 tensor-core GEMM (256x128 tiles, 512 thr, 3-stage, ldmatrix) ----------------
// Cout[M,Nn] = A[M,K] @ W[Nn,K]^T + epilogue.  A,W fp16; acc fp32.
// CTA tile 256(M) x 128(N), k-tile 64.  16 warps = 4x4, warp tile 64x32 = 4x4 m16n8k16.
// Stage: A rows 0..255 then W rows 0..127, 64 fp16/row, row stride 36 words (144B).
// epi: 0 plain, 1 silu, 2 relu^2 -> fp16 out, 3 sigmoid()*aux1+aux2, 4 +aux1
#define STG_WORDS 13824                       // 384 rows * 36 uint32
#define W_BASE_WORDS 9216                     // A = 256 rows * 36
#define GEMM_SMEM (3 * STG_WORDS * 4)         // 165888 bytes

__device__ __forceinline__ void mma_f16(float c[4],
                                        const uint32_t a[4],
                                        const uint32_t b[2])
{
    asm volatile(
        "mma.sync.aligned.m16n8k16.row.col.f32.f16.f16.f32 "
        "{%0,%1,%2,%3}, {%4,%5,%6,%7}, {%8,%9}, {%0,%1,%2,%3};\n"
        : "+f"(c[0]), "+f"(c[1]), "+f"(c[2]), "+f"(c[3])
        : "r"(a[0]), "r"(a[1]), "r"(a[2]), "r"(a[3]),
          "r"(b[0]), "r"(b[1]));
}

#define LDMATRIX_X4(r0, r1, r2, r3, addr) \
    asm volatile("ldmatrix.sync.aligned.m8n8.x4.shared.b16 {%0,%1,%2,%3}, [%4];" \
        : "=r"(r0), "=r"(r1), "=r"(r2), "=r"(r3) : "r"(addr))

__device__ __forceinline__ float gemm_epi(float vv, int epi, const float* aux1,
                                          const float* aux2, size_t o)
{
    if (epi == 1) {
        vv = vv / (1.f + expf(-vv));
    } else if (epi == 3) {
        vv = 1.f / (1.f + expf(-vv));
        vv = vv * aux1[o] + aux2[o];
    } else if (epi == 4) {
        vv = vv + aux1[o];
    }
    return vv;
}

__global__ void __launch_bounds__(512, 1)
gemm_hf_kernel(const __half* __restrict__ A, const __half* __restrict__ W,
               float* __restrict__ Co, __half* __restrict__ Coh,
               int Nn, int K, int epi,
               const float* __restrict__ aux1, const float* __restrict__ aux2)
{
    extern __shared__ uint32_t smw[];
    int tid = threadIdx.x;
    int n0 = blockIdx.x * 128;
    int m0 = blockIdx.y * 256;
    int wid = tid >> 5, lane = tid & 31;
    int wm = wid >> 2, wn = wid & 3;           // 4x4 warp grid
    int gid = lane >> 2, tg = lane & 3;

    // async-copy mapping: row 64 fp16 = 8 chunks of 16B; 512 thr -> 6 cp/thread
    int j  = tid & 7;
    int r0 = tid >> 3;           // 0..63
    const __half* pA = A + ((size_t)m0 + r0) * K + j * 8;
    const __half* pW = W + ((size_t)n0 + r0) * K + j * 8;
    uint32_t smb = smem_u32(smw);
    uint32_t dstA = smb + (uint32_t)(r0 * 36 + j * 4) * 4u;
    uint32_t dstW = smb + (uint32_t)(W_BASE_WORDS + r0 * 36 + j * 4) * 4u;

    // ldmatrix per-lane base addresses (stage 0, kk=0)
    uint32_t aAddr[4], bAddr[2];
    #pragma unroll
    for (int mi = 0; mi < 4; mi++)
        aAddr[mi] = smb + (uint32_t)((wm * 64 + mi * 16 + (lane & 15)) * 36) * 4u
                        + (uint32_t)(lane >> 4) * 16u;
    #pragma unroll
    for (int p = 0; p < 2; p++)
        bAddr[p] = smb + (uint32_t)W_BASE_WORDS * 4u
                 + (uint32_t)((wn * 32 + (p * 2 + (lane >> 4)) * 8 + (lane & 7)) * 36) * 4u
                 + (uint32_t)((lane >> 3) & 1) * 16u;

    float acc[4][4][4];
    #pragma unroll
    for (int mi = 0; mi < 4; mi++)
        #pragma unroll
        for (int ni = 0; ni < 4; ni++)
            #pragma unroll
            for (int e = 0; e < 4; e++) acc[mi][ni][e] = 0.f;

    int NC = K >> 6;

    // prologue: stages 0,1,2
    #pragma unroll
    for (int s = 0; s < 3; s++) {
        uint32_t so = (uint32_t)(s * STG_WORDS) * 4u;
        int kf = s * 64;
        #pragma unroll
        for (int i = 0; i < 4; i++)
            cp16(dstA + so + (uint32_t)(i * 64 * 36) * 4u, pA + (size_t)(i * 64) * K + kf);
        #pragma unroll
        for (int i = 0; i < 2; i++)
            cp16(dstW + so + (uint32_t)(i * 64 * 36) * 4u, pW + (size_t)(i * 64) * K + kf);
        CP_COMMIT();
    }

    for (int t = 0; t < NC; t++) {
        CP_WAIT_2();
        __syncthreads();
        uint32_t so = (uint32_t)((t % 3) * STG_WORDS) * 4u;

        #pragma unroll
        for (int kk = 0; kk < 4; kk++) {
            uint32_t ko = so + (uint32_t)kk * 32u;
            uint32_t af[4][4];
            uint32_t bf[4][2];
            #pragma unroll
            for (int mi = 0; mi < 4; mi++)
                LDMATRIX_X4(af[mi][0], af[mi][1], af[mi][2], af[mi][3], aAddr[mi] + ko);
            #pragma unroll
            for (int p = 0; p < 2; p++)
                LDMATRIX_X4(bf[2*p][0], bf[2*p][1], bf[2*p+1][0], bf[2*p+1][1], bAddr[p] + ko);
            #pragma unroll
            for (int mi = 0; mi < 4; mi++)
                #pragma unroll
                for (int ni = 0; ni < 4; ni++)
                    mma_f16(acc[mi][ni], af[mi], bf[ni]);
        }
        __syncthreads();

        int lc = t + 3;
        if (lc < NC) {
            uint32_t so2 = (uint32_t)((t % 3) * STG_WORDS) * 4u;
            int kf = lc * 64;
            #pragma unroll
            for (int i = 0; i < 4; i++)
                cp16(dstA + so2 + (uint32_t)(i * 64 * 36) * 4u, pA + (size_t)(i * 64) * K + kf);
            #pragma unroll
            for (int i = 0; i < 2; i++)
                cp16(dstW + so2 + (uint32_t)(i * 64 * 36) * 4u, pW + (size_t)(i * 64) * K + kf);
        }
        CP_COMMIT();
    }

    // epilogue
    #pragma unroll
    for (int mi = 0; mi < 4; mi++) {
        int row0 = m0 + wm * 64 + mi * 16 + gid;
        #pragma unroll
        for (int ni = 0; ni < 4; ni++) {
            int col0 = n0 + wn * 32 + ni * 8 + tg * 2;
            size_t o0 = (size_t)row0 * Nn + col0;
            size_t o1 = (size_t)(row0 + 8) * Nn + col0;
            if (epi == 2) {
                float a0 = fmaxf(acc[mi][ni][0], 0.f); a0 *= a0;
                float a1 = fmaxf(acc[mi][ni][1], 0.f); a1 *= a1;
                float a2 = fmaxf(acc[mi][ni][2], 0.f); a2 *= a2;
                float a3 = fmaxf(acc[mi][ni][3], 0.f); a3 *= a3;
                *(uint32_t*)(Coh + o0) = pack_f16(a0, a1);
                *(uint32_t*)(Coh + o1) = pack_f16(a2, a3);
            } else {
                float2 v0, v1;
                v0.x = gemm_epi(acc[mi][ni][0], epi, aux1, aux2, o0);
                v0.y = gemm_epi(acc[mi][ni][1], epi, aux1, aux2, o0 + 1);
                v1.x = gemm_epi(acc[mi][ni][2], epi, aux1, aux2, o1);
                v1.y = gemm_epi(acc[mi][ni][3], epi, aux1, aux2, o1 + 1);
                *(float2*)(Co + o0) = v0;
                *(float2*)(Co + o1) = v1;
            }
        }
    }
}

// ---------------- WKV: per-chunk state contribution S = (k*wk) @ v ----------------
__global__ __launch_bounds__(256) void wkv_s_kernel(const float* __restrict__ k,
                                                    const float* __restrict__ v,
                                                    const float* __restrict__ decay,
                                                    float* __restrict__ S)
{
    int blk = blockIdx.x;
    int c = blk % NCK;
    int h = (blk / NCK) % HH;
    int b = blk / (NCK * HH);
    __shared__ float ksm[64][64];
    __shared__ float vsm[64][64];
    __shared__ float wpow[256];
    int tid = threadIdx.x;
    float ew = expf(decay[h]);
    wpow[tid] = expf(-ew * (float)tid);
    int n  = tid >> 2;
    int mg = (tid & 3) * 16;
    float acc[16];
    #pragma unroll
    for (int jj = 0; jj < 16; jj++) acc[jj] = 0.f;

    size_t base = ((size_t)b * TT + (size_t)c * QQ) * CC + (size_t)h * NHD;

    for (int qc = 0; qc < 4; qc++) {
        __syncthreads();
        for (int l = tid; l < 64 * 16; l += 256) {
            int qq = l >> 4;
            int f  = (l & 15) * 4;
            *(float4*)&ksm[qq][f] = *(const float4*)(k + base + (size_t)(qc * 64 + qq) * CC + f);
            *(float4*)&vsm[qq][f] = *(const float4*)(v + base + (size_t)(qc * 64 + qq) * CC + f);
        }
        __syncthreads();
        #pragma unroll 4
        for (int qq = 0; qq < 64; qq++) {
            float kw = ksm[qq][n] * wpow[255 - (qc * 64 + qq)];
            const float4* vr = (const float4*)&vsm[qq][mg];
            float4 v0 = vr[0], v1 = vr[1], v2 = vr[2], v3 = vr[3];
            acc[0]  += kw * v0.x; acc[1]  += kw * v0.y; acc[2]  += kw * v0.z; acc[3]  += kw * v0.w;
            acc[4]  += kw * v1.x; acc[5]  += kw * v1.y; acc[6]  += kw * v1.z; acc[7]  += kw * v1.w;
            acc[8]  += kw * v2.x; acc[9]  += kw * v2.y; acc[10] += kw * v2.z; acc[11] += kw * v2.w;
            acc[12] += kw * v3.x; acc[13] += kw * v3.y; acc[14] += kw * v3.z; acc[15] += kw * v3.w;
        }
    }
    float* Sp = S + (size_t)blk * 4096 + n * 64 + mg;
    #pragma unroll
    for (int jj = 0; jj < 16; jj++) Sp[jj] = acc[jj];
}

// ---------------- WKV: inter-chunk prefix scan ----------------
__global__ __launch_bounds__(256) void wkv_scan_kernel(const float* __restrict__ S,
                                                       const float* __restrict__ decay,
                                                       float* __restrict__ ST)
{
    int bh = blockIdx.x;
    int h = bh % HH;
    float ws = expf(-expf(decay[h]) * 256.0f);
    int tid = threadIdx.x;
    size_t b0 = (size_t)bh * NCK * 4096;
    for (int r = 0; r < 16; r++) {
        int e = tid + r * 256;
        float st = 0.f;
        #pragma unroll
        for (int c = 0; c < NCK; c++) {
            ST[b0 + (size_t)c * 4096 + e] = st;
            st = ws * st + S[b0 + (size_t)c * 4096 + e];
        }
    }
}

// ---------------- WKV: per-chunk output ----------------
#define WKV_Y_SMEM ((256*64*2 + 4096 + 256) * 4)
__global__ __launch_bounds__(256) void wkv_y_kernel(const float* __restrict__ r,
                                                    const float* __restrict__ k,
                                                    const float* __restrict__ v,
                                                    const float* __restrict__ ST,
                                                    const float* __restrict__ decay,
                                                    const float* __restrict__ faaaa,
                                                    float* __restrict__ y)
{
    extern __shared__ float sm[];
    float* ksm  = sm;
    float* vsm  = sm + 16384;
    float* ssm  = sm + 32768;
    float* wpow = sm + 36864;

    int blk = blockIdx.x;
    int c = blk % NCK;
    int h = (blk / NCK) % HH;
    int b = blk / (NCK * HH);
    int tid = threadIdx.x;

    float ew = expf(decay[h]);
    float u  = faaaa[h];
    wpow[tid] = expf(-ew * (float)tid);

    size_t base = ((size_t)b * TT + (size_t)c * QQ) * CC + (size_t)h * NHD;

    for (int l = tid; l < 256 * 16; l += 256) {
        int qq = l >> 4;
        int f  = (l & 15) * 4;
        *(float4*)&ksm[qq * 64 + f] = *(const float4*)(k + base + (size_t)qq * CC + f);
        *(float4*)&vsm[qq * 64 + f] = *(const float4*)(v + base + (size_t)qq * CC + f);
    }
    size_t sbase = (size_t)blk * 4096;
    for (int l = tid; l < 1024; l += 256)
        *(float4*)&ssm[l * 4] = *(const float4*)(ST + sbase + (size_t)l * 4);
    __syncthreads();

    int q = tid;
    float rrow[64];
    {
        const float4* rg = (const float4*)(r + base + (size_t)q * CC);
        #pragma unroll
        for (int f = 0; f < 16; f++) {
            float4 t4 = rg[f];
            rrow[f * 4 + 0] = t4.x; rrow[f * 4 + 1] = t4.y;
            rrow[f * 4 + 2] = t4.z; rrow[f * 4 + 3] = t4.w;
        }
    }
    float acc[64];
    #pragma unroll
    for (int m = 0; m < 64; m++) acc[m] = 0.f;

    #pragma unroll 8
    for (int n = 0; n < 64; n++) {
        float rv = rrow[n];
        const float4* srow = (const float4*)&ssm[n * 64];
        #pragma unroll
        for (int m4 = 0; m4 < 16; m4++) {
            float4 s4 = srow[m4];
            acc[m4 * 4 + 0] += rv * s4.x;
            acc[m4 * 4 + 1] += rv * s4.y;
            acc[m4 * 4 + 2] += rv * s4.z;
            acc[m4 * 4 + 3] += rv * s4.w;
        }
    }
    float wbq = wpow[q];
    #pragma unroll
    for (int m = 0; m < 64; m++) acc[m] *= wbq;

    int jend = q | 31;
    for (int j = 0; j <= jend; j++) {
        float a = 0.f;
        const float4* krow = (const float4*)&ksm[j * 64];
        #pragma unroll
        for (int n4 = 0; n4 < 16; n4++) {
            float4 k4 = krow[n4];
            a += rrow[n4 * 4 + 0] * k4.x + rrow[n4 * 4 + 1] * k4.y
               + rrow[n4 * 4 + 2] * k4.z + rrow[n4 * 4 + 3] * k4.w;
        }
        float coef = (j < q) ? wpow[q - j - 1] : ((j == q) ? u : 0.0f);
        a *= coef;
        const float4* vrow = (const float4*)&vsm[j * 64];
        #pragma unroll
        for (int m4 = 0; m4 < 16; m4++) {
            float4 v4 = vrow[m4];
            acc[m4 * 4 + 0] += a * v4.x;
            acc[m4 * 4 + 1] += a * v4.y;
            acc[m4 * 4 + 2] += a * v4.z;
            acc[m4 * 4 + 3] += a * v4.w;
        }
    }

    float* yo = y + base + (size_t)q * CC;
    #pragma unroll
    for (int m4 = 0; m4 < 16; m4++) {
        float4 o4 = make_float4(acc[m4 * 4 + 0], acc[m4 * 4 + 1], acc[m4 * 4 + 2], acc[m4 * 4 + 3]);
        *(float4*)(yo + m4 * 4) = o4;
    }
}

// ---------------- GroupNorm * g (fp16 output: feeds Wo GEMM) ----------------
__global__ __launch_bounds__(256) void gn_mul_kernel(const float* __restrict__ y,
                                                     const float* __restrict__ gnw,
                                                     const float* __restrict__ gnb,
                                                     const float* __restrict__ g,
                                                     __half* __restrict__ yg)
{
    int row = blockIdx.x;
    int tid = threadIdx.x;
    size_t off = (size_t)row * CC;
    float4 v = ((const float4*)(y + off))[tid];
    float s  = v.x + v.y + v.z + v.w;
    float sq = v.x*v.x + v.y*v.y + v.z*v.z + v.w*v.w;
    #pragma unroll
    for (int o = 8; o >= 1; o >>= 1) {
        s  += __shfl_xor_sync(0xffffffffu, s,  o);
        sq += __shfl_xor_sync(0xffffffffu, sq, o);
    }
    float mu   = s * (1.0f / 64.0f);
    float var  = sq * (1.0f / 64.0f) - mu * mu;
    float rstd = rsqrtf(var + EPS_GN);
    float4 ww = ((const float4*)gnw)[tid];
    float4 bb = ((const float4*)gnb)[tid];
    float4 gg = ((const float4*)(g + off))[tid];
    uint2 o4;
    o4.x = pack_f16(((v.x - mu) * rstd * ww.x + bb.x) * gg.x,
                    ((v.y - mu) * rstd * ww.y + bb.y) * gg.y);
    o4.y = pack_f16(((v.z - mu) * rstd * ww.z + bb.z) * gg.z,
                    ((v.w - mu) * rstd * ww.w + bb.w) * gg.w);
    ((uint2*)(yg + off))[tid] = o4;
}

// ---------------- host launcher ----------------
extern "C" void kernel_launch(void* const* d_in, const int* in_sizes, int n_in,
                              void* d_out, int out_size)
{
    const float* x      = (const float*)d_in[0];
    const float* ln1w   = (const float*)d_in[1];
    const float* ln1b   = (const float*)d_in[2];
    const float* maak   = (const float*)d_in[3];
    const float* maav   = (const float*)d_in[4];
    const float* maar   = (const float*)d_in[5];
    const float* maag   = (const float*)d_in[6];
    const float* decay  = (const float*)d_in[7];
    const float* faaaa  = (const float*)d_in[8];
    const float* Wr     = (const float*)d_in[9];
    const float* Wk     = (const float*)d_in[10];
    const float* Wv     = (const float*)d_in[11];
    const float* Wg     = (const float*)d_in[12];
    const float* Wo     = (const float*)d_in[13];
    const float* gnw    = (const float*)d_in[14];
    const float* gnb    = (const float*)d_in[15];
    const float* ln2w   = (const float*)d_in[16];
    const float* ln2b   = (const float*)d_in[17];
    const float* cmaak  = (const float*)d_in[18];
    const float* cmaar  = (const float*)d_in[19];
    const float* Wck    = (const float*)d_in[20];
    const float* Wcv    = (const float*)d_in[21];
    const float* Wcr    = (const float*)d_in[22];
    float* out = (float*)d_out;

    float* sc = nullptr;
    cudaGetSymbolAddress((void**)&sc, g_scratch);

    __half* xk   = (__half*)(sc + OFF_XK);
    __half* xv   = (__half*)(sc + OFF_XV);
    __half* xr   = (__half*)(sc + OFF_XR);
    __half* xg   = (__half*)(sc + OFF_XG);
    float* rb   = sc + OFF_R;
    float* kb   = sc + OFF_K;
    float* vb   = sc + OFF_V;
    float* gb   = sc + OFF_G;
    float* yb   = sc + OFF_Y;
    __half* ygb = (__half*)(sc + OFF_YG);
    float* x1   = sc + OFF_X1;
    __half* xk2 = (__half*)(sc + OFF_XK2);
    __half* xr2 = (__half*)(sc + OFF_XR2);
    float* hv   = sc + OFF_HV;
    __half* hb  = (__half*)(sc + OFF_H);
    float* Sb   = sc + OFF_S;
    float* STb  = sc + OFF_ST;
    __half* WrR  = (__half*)(sc + OFF_WR_R);
    __half* WkR  = (__half*)(sc + OFF_WK_R);
    __half* WvR  = (__half*)(sc + OFF_WV_R);
    __half* WgR  = (__half*)(sc + OFF_WG_R);
    __half* WoR  = (__half*)(sc + OFF_WO_R);
    __half* WcrR = (__half*)(sc + OFF_WCR_R);
    __half* WckR = (__half*)(sc + OFF_WCK_R);
    __half* WcvR = (__half*)(sc + OFF_WCV_R);

    cudaFuncSetAttribute(wkv_y_kernel, cudaFuncAttributeMaxDynamicSharedMemorySize, WKV_Y_SMEM);
    cudaFuncSetAttribute(gemm_hf_kernel, cudaFuncAttributeMaxDynamicSharedMemorySize, GEMM_SMEM);

    dim3 g1024(1024 / 128, MTOT / 256);   // (8, 64)
    dim3 g3072(3072 / 128, MTOT / 256);   // (24, 64)
    int n4_1M = (CC * CC) / 4;
    int n4_3M = (3 * CC * CC) / 4;

    // ---- time mix ----
    ln_mix_kernel<4><<<MTOT, 256>>>(x, ln1w, ln1b, maak, maav, maar, maag, xk, xv, xr, xg);
    cvt_w_kernel<<<n4_1M / 256, 256>>>(Wr, WrR, n4_1M);
    cvt_w_kernel<<<n4_1M / 256, 256>>>(Wk, WkR, n4_1M);
    cvt_w_kernel<<<n4_1M / 256, 256>>>(Wv, WvR, n4_1M);
    cvt_w_kernel<<<n4_1M / 256, 256>>>(Wg, WgR, n4_1M);
    gemm_hf_kernel<<<g1024, 512, GEMM_SMEM>>>(xr, WrR, rb, nullptr, 1024, 1024, 0, nullptr, nullptr);
    gemm_hf_kernel<<<g1024, 512, GEMM_SMEM>>>(xk, WkR, kb, nullptr, 1024, 1024, 0, nullptr, nullptr);
    gemm_hf_kernel<<<g1024, 512, GEMM_SMEM>>>(xv, WvR, vb, nullptr, 1024, 1024, 0, nullptr, nullptr);
    gemm_hf_kernel<<<g1024, 512, GEMM_SMEM>>>(xg, WgR, gb, nullptr, 1024, 1024, 1, nullptr, nullptr); // silu

    wkv_s_kernel<<<BB * HH * NCK, 256>>>(kb, vb, decay, Sb);
    wkv_scan_kernel<<<BB * HH, 256>>>(Sb, decay, STb);
    wkv_y_kernel<<<BB * HH * NCK, 256, WKV_Y_SMEM>>>(rb, kb, vb, STb, decay, faaaa, yb);

    gn_mul_kernel<<<MTOT, 256>>>(yb, gnw, gnb, gb, ygb);
    cvt_w_kernel<<<n4_1M / 256, 256>>>(Wo, WoR, n4_1M);
    gemm_hf_kernel<<<g1024, 512, GEMM_SMEM>>>(ygb, WoR, x1, nullptr, 1024, 1024, 4, x, nullptr); // + residual

    // ---- channel mix ----
    ln_mix_kernel<2><<<MTOT, 256>>>(x1, ln2w, ln2b, cmaak, cmaar, nullptr, nullptr,
                                    xk2, xr2, nullptr, nullptr);
    cvt_w_kernel<<<n4_3M / 256, 256>>>(Wck, WckR, n4_3M);
    cvt_w_kernel<<<n4_3M / 256, 256>>>(Wcv, WcvR, n4_3M);
    cvt_w_kernel<<<n4_1M / 256, 256>>>(Wcr, WcrR, n4_1M);
    gemm_hf_kernel<<<g3072, 512, GEMM_SMEM>>>(xk2, WckR, nullptr, hb, 3072, 1024, 2, nullptr, nullptr); // relu^2 -> fp16
    gemm_hf_kernel<<<g1024, 512, GEMM_SMEM>>>(hb, WcvR, hv, nullptr, 1024, 3072, 0, nullptr, nullptr);
    gemm_hf_kernel<<<g1024, 512, GEMM_SMEM>>>(xr2, WcrR, out, nullptr, 1024, 1024, 3, hv, x1); // sigmoid*hv + x1
}

// round 10
// speedup vs baseline: 1.1593x; 1.1593x over previous
#include <cuda_runtime.h>
#include <cuda_fp16.h>
#include <math.h>
#include <stdint.h>

// ---------------- problem constants ----------------
#define BB 4
#define TT 4096
#define CC 1024
#define HH 16
#define NHD 64
#define QQ 256
#define NCK 16
#define MTOT (BB*TT)          // 16384
#define BTC (BB*TT*CC)        // 16777216
#define EPS_LN 1e-5f
#define EPS_GN (1e-5f*64.0f)

// ---------------- scratch ----------------
#define SCR_TOTAL (19ull*BTC + 8388608ull + 12582912ull)
__device__ float g_scratch[SCR_TOTAL];

#define OFF_XK   (1ull*BTC)      // fp16 buffers
#define OFF_XV   (2ull*BTC)
#define OFF_XR   (3ull*BTC)
#define OFF_XG   (4ull*BTC)
#define OFF_R    (5ull*BTC)      // fp32
#define OFF_K    (6ull*BTC)
#define OFF_V    (7ull*BTC)
#define OFF_G    (8ull*BTC)
#define OFF_Y    (9ull*BTC)
#define OFF_YG   (10ull*BTC)     // fp16
#define OFF_X1   (11ull*BTC)     // fp32
#define OFF_XK2  (13ull*BTC)     // fp16
#define OFF_XR2  (14ull*BTC)     // fp16
#define OFF_HV   (15ull*BTC)     // fp32
#define OFF_H    (16ull*BTC)     // fp16 [16384,3072]
#define OFF_S    (19ull*BTC)
#define OFF_ST   (19ull*BTC + 4194304ull)
#define OFF_WT   (19ull*BTC + 8388608ull)
#define OFF_WR_R  (OFF_WT + 0ull)
#define OFF_WK_R  (OFF_WT + 1048576ull)
#define OFF_WV_R  (OFF_WT + 2097152ull)
#define OFF_WG_R  (OFF_WT + 3145728ull)
#define OFF_WO_R  (OFF_WT + 4194304ull)
#define OFF_WCR_R (OFF_WT + 5242880ull)
#define OFF_WCK_R (OFF_WT + 6291456ull)
#define OFF_WCV_R (OFF_WT + 9437184ull)

// ---------------- helpers ----------------
__device__ __forceinline__ uint32_t smem_u32(const void* p) {
    uint32_t a;
    asm("{ .reg .u64 t; cvta.to.shared.u64 t, %1; cvt.u32.u64 %0, t; }" : "=r"(a) : "l"(p));
    return a;
}

__device__ __forceinline__ uint32_t pack_f16(float a, float b) {
    __half2 h = __floats2half2_rn(a, b);
    return *(uint32_t*)&h;
}

__device__ __forceinline__ void cp16(uint32_t dst, const void* src) {
    asm volatile("cp.async.cg.shared.global [%0], [%1], 16;" :: "r"(dst), "l"(src) : "memory");
}
#define CP_COMMIT() asm volatile("cp.async.commit_group;" ::: "memory")
#define CP_WAIT_1() asm volatile("cp.async.wait_group 1;" ::: "memory")

// ---------------- weight fp32 -> fp16 ----------------
__global__ __launch_bounds__(256) void cvt_w_kernel(const float* __restrict__ src,
                                                    __half* __restrict__ dst, int n4)
{
    int i = blockIdx.x * 256 + threadIdx.x;
    if (i < n4) {
        float4 v = ((const float4*)src)[i];
        uint2 o;
        o.x = pack_f16(v.x, v.y);
        o.y = pack_f16(v.z, v.w);
        ((uint2*)dst)[i] = o;
    }
}

// ---------------- fused LayerNorm + time-shift mix (fp16 outputs) ----------------
template<int NOUT>
__global__ __launch_bounds__(256) void ln_mix_kernel(const float* __restrict__ x,
                                                     const float* __restrict__ w,
                                                     const float* __restrict__ b,
                                                     const float* __restrict__ m0,
                                                     const float* __restrict__ m1,
                                                     const float* __restrict__ m2,
                                                     const float* __restrict__ m3,
                                                     __half* __restrict__ o0,
                                                     __half* __restrict__ o1,
                                                     __half* __restrict__ o2,
                                                     __half* __restrict__ o3)
{
    int row = blockIdx.x;
    int t = row % TT;
    int tid = threadIdx.x;
    size_t off = (size_t)row * CC;
    float4 cur = ((const float4*)(x + off))[tid];
    float4 prv = make_float4(0.f, 0.f, 0.f, 0.f);
    if (t > 0) prv = ((const float4*)(x + off - CC))[tid];

    float s0 = cur.x + cur.y + cur.z + cur.w;
    float q0 = cur.x*cur.x + cur.y*cur.y + cur.z*cur.z + cur.w*cur.w;
    float s1 = prv.x + prv.y + prv.z + prv.w;
    float q1 = prv.x*prv.x + prv.y*prv.y + prv.z*prv.z + prv.w*prv.w;
    #pragma unroll
    for (int o = 16; o >= 1; o >>= 1) {
        s0 += __shfl_xor_sync(0xffffffffu, s0, o);
        q0 += __shfl_xor_sync(0xffffffffu, q0, o);
        s1 += __shfl_xor_sync(0xffffffffu, s1, o);
        q1 += __shfl_xor_sync(0xffffffffu, q1, o);
    }
    __shared__ float red[4][8];
    int wid = tid >> 5, lane = tid & 31;
    if (lane == 0) { red[0][wid] = s0; red[1][wid] = q0; red[2][wid] = s1; red[3][wid] = q1; }
    __syncthreads();
    if (tid == 0) {
        float a0 = 0, a1 = 0, a2 = 0, a3 = 0;
        #pragma unroll
        for (int i = 0; i < 8; i++) { a0 += red[0][i]; a1 += red[1][i]; a2 += red[2][i]; a3 += red[3][i]; }
        red[0][0] = a0; red[1][0] = a1; red[2][0] = a2; red[3][0] = a3;
    }
    __syncthreads();
    float mu0 = red[0][0] * (1.0f / CC);
    float rs0 = rsqrtf(red[1][0] * (1.0f / CC) - mu0 * mu0 + EPS_LN);
    float mu1 = red[2][0] * (1.0f / CC);
    float rs1 = rsqrtf(red[3][0] * (1.0f / CC) - mu1 * mu1 + EPS_LN);

    float4 ww = ((const float4*)w)[tid];
    float4 bb = ((const float4*)b)[tid];
    float4 lc, lp;
    lc.x = (cur.x - mu0) * rs0 * ww.x + bb.x;
    lc.y = (cur.y - mu0) * rs0 * ww.y + bb.y;
    lc.z = (cur.z - mu0) * rs0 * ww.z + bb.z;
    lc.w = (cur.w - mu0) * rs0 * ww.w + bb.w;
    if (t > 0) {
        lp.x = (prv.x - mu1) * rs1 * ww.x + bb.x;
        lp.y = (prv.y - mu1) * rs1 * ww.y + bb.y;
        lp.z = (prv.z - mu1) * rs1 * ww.z + bb.z;
        lp.w = (prv.w - mu1) * rs1 * ww.w + bb.w;
    } else {
        lp = make_float4(0.f, 0.f, 0.f, 0.f);
    }
    float4 xx = make_float4(lp.x - lc.x, lp.y - lc.y, lp.z - lc.z, lp.w - lc.w);

    float4 a;
    uint2 o;
    a = ((const float4*)m0)[tid];
    o.x = pack_f16(lc.x + xx.x * a.x, lc.y + xx.y * a.y);
    o.y = pack_f16(lc.z + xx.z * a.z, lc.w + xx.w * a.w);
    ((uint2*)(o0 + off))[tid] = o;
    a = ((const float4*)m1)[tid];
    o.x = pack_f16(lc.x + xx.x * a.x, lc.y + xx.y * a.y);
    o.y = pack_f16(lc.z + xx.z * a.z, lc.w + xx.w * a.w);
    ((uint2*)(o1 + off))[tid] = o;
    if (NOUT == 4) {
        a = ((const float4*)m2)[tid];
        o.x = pack_f16(lc.x + xx.x * a.x, lc.y + xx.y * a.y);
        o.y = pack_f16(lc.z + xx.z * a.z, lc.w + xx.w * a.w);
        ((uint2*)(o2 + off))[tid] = o;
        a = ((const float4*)m3)[tid];
        o.x = pack_f16(lc.x + xx.x * a.x, lc.y + xx.y * a.y);
        o.y = pack_f16(lc.z + xx.z * a.z, lc.w + xx.w * a.w);
        ((uint2*)(o3 + off))[tid] = o;
    }
}

// ---------------- fp16 tensor-core GEMM (cp.async 2-stage, ldmatrix, k-tile 64) ----------------
// (round-8 config: 128x128 tiles, 256 thr, 2 CTAs/SM — at legacy HMMA roofline)
#define STG_WORDS 9216                        // 256 rows * 36 uint32
#define GEMM_SMEM (2 * STG_WORDS * 4)         // 73728 bytes

__device__ __forceinline__ void mma_f16(float c[4],
                                        const uint32_t a[4],
                                        const uint32_t b[2])
{
    asm volatile(
        "mma.sync.aligned.m16n8k16.row.col.f32.f16.f16.f32 "
        "{%0,%1,%2,%3}, {%4,%5,%6,%7}, {%8,%9}, {%0,%1,%2,%3};\n"
        : "+f"(c[0]), "+f"(c[1]), "+f"(c[2]), "+f"(c[3])
        : "r"(a[0]), "r"(a[1]), "r"(a[2]), "r"(a[3]),
          "r"(b[0]), "r"(b[1]));
}

#define LDMATRIX_X4(r0, r1, r2, r3, addr) \
    asm volatile("ldmatrix.sync.aligned.m8n8.x4.shared.b16 {%0,%1,%2,%3}, [%4];" \
        : "=r"(r0), "=r"(r1), "=r"(r2), "=r"(r3) : "r"(addr))

__device__ __forceinline__ float gemm_epi(float vv, int epi, const float* aux1,
                                          const float* aux2, size_t o)
{
    if (epi == 1) {
        vv = vv / (1.f + expf(-vv));
    } else if (epi == 3) {
        vv = 1.f / (1.f + expf(-vv));
        vv = vv * aux1[o] + aux2[o];
    } else if (epi == 4) {
        vv = vv + aux1[o];
    }
    return vv;
}

__global__ void __launch_bounds__(256, 2)
gemm_hf_kernel(const __half* __restrict__ A, const __half* __restrict__ W,
               float* __restrict__ Co, __half* __restrict__ Coh,
               int Nn, int K, int epi,
               const float* __restrict__ aux1, const float* __restrict__ aux2)
{
    extern __shared__ uint32_t smw[];
    int tid = threadIdx.x;
    int n0 = blockIdx.x * 128;
    int m0 = blockIdx.y * 128;
    int wid = tid >> 5, lane = tid & 31;
    int wm = wid >> 2, wn = wid & 3;
    int gid = lane >> 2, tg = lane & 3;

    int j  = tid & 7;
    int r0 = tid >> 3;
    const __half* pA = A + ((size_t)m0 + r0) * K + j * 8;
    const __half* pW = W + ((size_t)n0 + r0) * K + j * 8;
    uint32_t smb = smem_u32(smw);
    uint32_t dstA = smb + (uint32_t)(r0 * 36 + j * 4) * 4u;
    uint32_t dstW = dstA + 4608u * 4u;

    uint32_t aAddr[4], bAddr[2];
    #pragma unroll
    for (int mi = 0; mi < 4; mi++)
        aAddr[mi] = smb + (uint32_t)((wm * 64 + mi * 16 + (lane & 15)) * 36) * 4u
                        + (uint32_t)(lane >> 4) * 16u;
    #pragma unroll
    for (int p = 0; p < 2; p++)
        bAddr[p] = smb + 4608u * 4u
                 + (uint32_t)((wn * 32 + (p * 2 + (lane >> 4)) * 8 + (lane & 7)) * 36) * 4u
                 + (uint32_t)((lane >> 3) & 1) * 16u;

    float acc[4][4][4];
    #pragma unroll
    for (int mi = 0; mi < 4; mi++)
        #pragma unroll
        for (int ni = 0; ni < 4; ni++)
            #pragma unroll
            for (int e = 0; e < 4; e++) acc[mi][ni][e] = 0.f;

    int NC = K >> 6;

    #pragma unroll
    for (int s = 0; s < 2; s++) {
        uint32_t so = (uint32_t)(s * STG_WORDS) * 4u;
        int kf = s * 64;
        #pragma unroll
        for (int i = 0; i < 4; i++) {
            cp16(dstA + so + (uint32_t)(i * 32 * 36) * 4u, pA + (size_t)(i * 32) * K + kf);
            cp16(dstW + so + (uint32_t)(i * 32 * 36) * 4u, pW + (size_t)(i * 32) * K + kf);
        }
        CP_COMMIT();
    }

    for (int t = 0; t < NC; t++) {
        CP_WAIT_1();
        __syncthreads();
        uint32_t so = (uint32_t)((t & 1) * STG_WORDS) * 4u;

        #pragma unroll
        for (int kk = 0; kk < 4; kk++) {
            uint32_t ko = so + (uint32_t)kk * 32u;
            uint32_t af[4][4];
            uint32_t bf[4][2];
            #pragma unroll
            for (int mi = 0; mi < 4; mi++)
                LDMATRIX_X4(af[mi][0], af[mi][1], af[mi][2], af[mi][3], aAddr[mi] + ko);
            #pragma unroll
            for (int p = 0; p < 2; p++)
                LDMATRIX_X4(bf[2*p][0], bf[2*p][1], bf[2*p+1][0], bf[2*p+1][1], bAddr[p] + ko);
            #pragma unroll
            for (int mi = 0; mi < 4; mi++)
                #pragma unroll
                for (int ni = 0; ni < 4; ni++)
                    mma_f16(acc[mi][ni], af[mi], bf[ni]);
        }
        __syncthreads();

        int lc = t + 2;
        if (lc < NC) {
            uint32_t so2 = (uint32_t)((t & 1) * STG_WORDS) * 4u;
            int kf = lc * 64;
            #pragma unroll
            for (int i = 0; i < 4; i++) {
                cp16(dstA + so2 + (uint32_t)(i * 32 * 36) * 4u, pA + (size_t)(i * 32) * K + kf);
                cp16(dstW + so2 + (uint32_t)(i * 32 * 36) * 4u, pW + (size_t)(i * 32) * K + kf);
            }
        }
        CP_COMMIT();
    }

    #pragma unroll
    for (int mi = 0; mi < 4; mi++) {
        int row0 = m0 + wm * 64 + mi * 16 + gid;
        #pragma unroll
        for (int ni = 0; ni < 4; ni++) {
            int col0 = n0 + wn * 32 + ni * 8 + tg * 2;
            size_t o0 = (size_t)row0 * Nn + col0;
            size_t o1 = (size_t)(row0 + 8) * Nn + col0;
            if (epi == 2) {
                float a0 = fmaxf(acc[mi][ni][0], 0.f); a0 *= a0;
                float a1 = fmaxf(acc[mi][ni][1], 0.f); a1 *= a1;
                float a2 = fmaxf(acc[mi][ni][2], 0.f); a2 *= a2;
                float a3 = fmaxf(acc[mi][ni][3], 0.f); a3 *= a3;
                *(uint32_t*)(Coh + o0) = pack_f16(a0, a1);
                *(uint32_t*)(Coh + o1) = pack_f16(a2, a3);
            } else {
                float2 v0, v1;
                v0.x = gemm_epi(acc[mi][ni][0], epi, aux1, aux2, o0);
                v0.y = gemm_epi(acc[mi][ni][1], epi, aux1, aux2, o0 + 1);
                v1.x = gemm_epi(acc[mi][ni][2], epi, aux1, aux2, o1);
                v1.y = gemm_epi(acc[mi][ni][3], epi, aux1, aux2, o1 + 1);
                *(float2*)(Co + o0) = v0;
                *(float2*)(Co + o1) = v1;
            }
        }
    }
}

// ---------------- WKV: per-chunk state contribution S = (k*wk) @ v ----------------
__global__ __launch_bounds__(256) void wkv_s_kernel(const float* __restrict__ k,
                                                    const float* __restrict__ v,
                                                    const float* __restrict__ decay,
                                                    float* __restrict__ S)
{
    int blk = blockIdx.x;
    int c = blk % NCK;
    int h = (blk / NCK) % HH;
    int b = blk / (NCK * HH);
    __shared__ float ksm[64][64];
    __shared__ float vsm[64][64];
    __shared__ float wpow[256];
    int tid = threadIdx.x;
    float ew = expf(decay[h]);
    wpow[tid] = expf(-ew * (float)tid);
    int n  = tid >> 2;
    int mg = (tid & 3) * 16;
    float acc[16];
    #pragma unroll
    for (int jj = 0; jj < 16; jj++) acc[jj] = 0.f;

    size_t base = ((size_t)b * TT + (size_t)c * QQ) * CC + (size_t)h * NHD;

    for (int qc = 0; qc < 4; qc++) {
        __syncthreads();
        for (int l = tid; l < 64 * 16; l += 256) {
            int qq = l >> 4;
            int f  = (l & 15) * 4;
            *(float4*)&ksm[qq][f] = *(const float4*)(k + base + (size_t)(qc * 64 + qq) * CC + f);
            *(float4*)&vsm[qq][f] = *(const float4*)(v + base + (size_t)(qc * 64 + qq) * CC + f);
        }
        __syncthreads();
        #pragma unroll 4
        for (int qq = 0; qq < 64; qq++) {
            float kw = ksm[qq][n] * wpow[255 - (qc * 64 + qq)];
            const float4* vr = (const float4*)&vsm[qq][mg];
            float4 v0 = vr[0], v1 = vr[1], v2 = vr[2], v3 = vr[3];
            acc[0]  += kw * v0.x; acc[1]  += kw * v0.y; acc[2]  += kw * v0.z; acc[3]  += kw * v0.w;
            acc[4]  += kw * v1.x; acc[5]  += kw * v1.y; acc[6]  += kw * v1.z; acc[7]  += kw * v1.w;
            acc[8]  += kw * v2.x; acc[9]  += kw * v2.y; acc[10] += kw * v2.z; acc[11] += kw * v2.w;
            acc[12] += kw * v3.x; acc[13] += kw * v3.y; acc[14] += kw * v3.z; acc[15] += kw * v3.w;
        }
    }
    float* Sp = S + (size_t)blk * 4096 + n * 64 + mg;
    #pragma unroll
    for (int jj = 0; jj < 16; jj++) Sp[jj] = acc[jj];
}

// ---------------- WKV: inter-chunk prefix scan ----------------
__global__ __launch_bounds__(256) void wkv_scan_kernel(const float* __restrict__ S,
                                                       const float* __restrict__ decay,
                                                       float* __restrict__ ST)
{
    int bh = blockIdx.x;
    int h = bh % HH;
    float ws = expf(-expf(decay[h]) * 256.0f);
    int tid = threadIdx.x;
    size_t b0 = (size_t)bh * NCK * 4096;
    for (int r = 0; r < 16; r++) {
        int e = tid + r * 256;
        float st = 0.f;
        #pragma unroll
        for (int c = 0; c < NCK; c++) {
            ST[b0 + (size_t)c * 4096 + e] = st;
            st = ws * st + S[b0 + (size_t)c * 4096 + e];
        }
    }
}

// ---------------- WKV: per-chunk output (two-level sub-chunking, L=64) ----------------
// smem: ksm[256*64], vsm[256*64], sst[4][64*64], wpow[256]  (fp32)
// sst[0] = ST (inter-chunk state); sst[s] = w^64*sst[s-1] + (k_{s-1}*wk)^T @ v_{s-1}
// y(q=64s+ql) = wpow[ql]*(r_q @ sst[s]) + sum_{j<=ql in subchunk} coef * (r_q . k_j) v_j
#define WKV_Y_SMEM ((16384 + 16384 + 16384 + 256) * 4)   // 197632 bytes
__global__ __launch_bounds__(256) void wkv_y_kernel(const float* __restrict__ r,
                                                    const float* __restrict__ k,
                                                    const float* __restrict__ v,
                                                    const float* __restrict__ ST,
                                                    const float* __restrict__ decay,
                                                    const float* __restrict__ faaaa,
                                                    float* __restrict__ y)
{
    extern __shared__ float sm[];
    float* ksm  = sm;                  // 256*64
    float* vsm  = sm + 16384;          // 256*64
    float* sst  = sm + 32768;          // 4 * 64*64
    float* wpow = sm + 49152;          // 256

    int blk = blockIdx.x;
    int c = blk % NCK;
    int h = (blk / NCK) % HH;
    int b = blk / (NCK * HH);
    int tid = threadIdx.x;

    float ew = expf(decay[h]);
    float u  = faaaa[h];
    wpow[tid] = expf(-ew * (float)tid);

    size_t base = ((size_t)b * TT + (size_t)c * QQ) * CC + (size_t)h * NHD;

    for (int l = tid; l < 256 * 16; l += 256) {
        int qq = l >> 4;
        int f  = (l & 15) * 4;
        *(float4*)&ksm[qq * 64 + f] = *(const float4*)(k + base + (size_t)qq * CC + f);
        *(float4*)&vsm[qq * 64 + f] = *(const float4*)(v + base + (size_t)qq * CC + f);
    }
    size_t sbase = (size_t)blk * 4096;
    for (int l = tid; l < 1024; l += 256)
        *(float4*)&sst[l * 4] = *(const float4*)(ST + sbase + (size_t)l * 4);
    __syncthreads();

    // ---- precompute sub-chunk states sst[1..3] (no barriers needed between s) ----
    {
        int n  = tid >> 2;
        int mg = (tid & 3) * 16;
        float w64 = expf(-ew * 64.0f);
        float st_prev[16];
        #pragma unroll
        for (int e = 0; e < 16; e++) st_prev[e] = sst[n * 64 + mg + e];
        #pragma unroll 1
        for (int s = 1; s < 4; s++) {
            float tmp[16];
            #pragma unroll
            for (int e = 0; e < 16; e++) tmp[e] = w64 * st_prev[e];
            int j0 = (s - 1) * 64;
            #pragma unroll 4
            for (int jl = 0; jl < 64; jl++) {
                float kw = ksm[(j0 + jl) * 64 + n] * wpow[63 - jl];
                const float4* vr = (const float4*)&vsm[(j0 + jl) * 64 + mg];
                float4 v0 = vr[0], v1 = vr[1], v2 = vr[2], v3 = vr[3];
                tmp[0]  += kw * v0.x; tmp[1]  += kw * v0.y; tmp[2]  += kw * v0.z; tmp[3]  += kw * v0.w;
                tmp[4]  += kw * v1.x; tmp[5]  += kw * v1.y; tmp[6]  += kw * v1.z; tmp[7]  += kw * v1.w;
                tmp[8]  += kw * v2.x; tmp[9]  += kw * v2.y; tmp[10] += kw * v2.z; tmp[11] += kw * v2.w;
                tmp[12] += kw * v3.x; tmp[13] += kw * v3.y; tmp[14] += kw * v3.z; tmp[15] += kw * v3.w;
            }
            float* so = sst + s * 4096 + n * 64 + mg;
            #pragma unroll
            for (int e = 0; e < 16; e++) { so[e] = tmp[e]; st_prev[e] = tmp[e]; }
        }
    }
    __syncthreads();

    // ---- per-thread output ----
    int q  = tid;
    int qs = q >> 6;           // sub-chunk 0..3
    int ql = q & 63;           // local row
    float rrow[64];
    {
        const float4* rg = (const float4*)(r + base + (size_t)q * CC);
        #pragma unroll
        for (int f = 0; f < 16; f++) {
            float4 t4 = rg[f];
            rrow[f * 4 + 0] = t4.x; rrow[f * 4 + 1] = t4.y;
            rrow[f * 4 + 2] = t4.z; rrow[f * 4 + 3] = t4.w;
        }
    }
    float acc[64];
    #pragma unroll
    for (int m = 0; m < 64; m++) acc[m] = 0.f;

    // state part: r @ sst[qs], scaled by wpow[ql]
    const float* stq = sst + qs * 4096;
    #pragma unroll 8
    for (int n = 0; n < 64; n++) {
        float rv = rrow[n];
        const float4* srow = (const float4*)&stq[n * 64];
        #pragma unroll
        for (int m4 = 0; m4 < 16; m4++) {
            float4 s4 = srow[m4];
            acc[m4 * 4 + 0] += rv * s4.x;
            acc[m4 * 4 + 1] += rv * s4.y;
            acc[m4 * 4 + 2] += rv * s4.z;
            acc[m4 * 4 + 3] += rv * s4.w;
        }
    }
    float wbq = wpow[ql];
    #pragma unroll
    for (int m = 0; m < 64; m++) acc[m] *= wbq;

    // intra part within sub-chunk: j_l = 0..(ql|31)
    int j0 = qs * 64;
    int jend = ql | 31;
    for (int jl = 0; jl <= jend; jl++) {
        float a = 0.f;
        const float4* krow = (const float4*)&ksm[(j0 + jl) * 64];
        #pragma unroll
        for (int n4 = 0; n4 < 16; n4++) {
            float4 k4 = krow[n4];
            a += rrow[n4 * 4 + 0] * k4.x + rrow[n4 * 4 + 1] * k4.y
               + rrow[n4 * 4 + 2] * k4.z + rrow[n4 * 4 + 3] * k4.w;
        }
        float coef = (jl < ql) ? wpow[ql - jl - 1] : ((jl == ql) ? u : 0.0f);
        a *= coef;
        const float4* vrow = (const float4*)&vsm[(j0 + jl) * 64];
        #pragma unroll
        for (int m4 = 0; m4 < 16; m4++) {
            float4 v4 = vrow[m4];
            acc[m4 * 4 + 0] += a * v4.x;
            acc[m4 * 4 + 1] += a * v4.y;
            acc[m4 * 4 + 2] += a * v4.z;
            acc[m4 * 4 + 3] += a * v4.w;
        }
    }

    float* yo = y + base + (size_t)q * CC;
    #pragma unroll
    for (int m4 = 0; m4 < 16; m4++) {
        float4 o4 = make_float4(acc[m4 * 4 + 0], acc[m4 * 4 + 1], acc[m4 * 4 + 2], acc[m4 * 4 + 3]);
        *(float4*)(yo + m4 * 4) = o4;
    }
}

// ---------------- GroupNorm * g (fp16 output: feeds Wo GEMM) ----------------
__global__ __launch_bounds__(256) void gn_mul_kernel(const float* __restrict__ y,
                                                     const float* __restrict__ gnw,
                                                     const float* __restrict__ gnb,
                                                     const float* __restrict__ g,
                                                     __half* __restrict__ yg)
{
    int row = blockIdx.x;
    int tid = threadIdx.x;
    size_t off = (size_t)row * CC;
    float4 v = ((const float4*)(y + off))[tid];
    float s  = v.x + v.y + v.z + v.w;
    float sq = v.x*v.x + v.y*v.y + v.z*v.z + v.w*v.w;
    #pragma unroll
    for (int o = 8; o >= 1; o >>= 1) {
        s  += __shfl_xor_sync(0xffffffffu, s,  o);
        sq += __shfl_xor_sync(0xffffffffu, sq, o);
    }
    float mu   = s * (1.0f / 64.0f);
    float var  = sq * (1.0f / 64.0f) - mu * mu;
    float rstd = rsqrtf(var + EPS_GN);
    float4 ww = ((const float4*)gnw)[tid];
    float4 bb = ((const float4*)gnb)[tid];
    float4 gg = ((const float4*)(g + off))[tid];
    uint2 o4;
    o4.x = pack_f16(((v.x - mu) * rstd * ww.x + bb.x) * gg.x,
                    ((v.y - mu) * rstd * ww.y + bb.y) * gg.y);
    o4.y = pack_f16(((v.z - mu) * rstd * ww.z + bb.z) * gg.z,
                    ((v.w - mu) * rstd * ww.w + bb.w) * gg.w);
    ((uint2*)(yg + off))[tid] = o4;
}

// ---------------- host launcher ----------------
extern "C" void kernel_launch(void* const* d_in, const int* in_sizes, int n_in,
                              void* d_out, int out_size)
{
    const float* x      = (const float*)d_in[0];
    const float* ln1w   = (const float*)d_in[1];
    const float* ln1b   = (const float*)d_in[2];
    const float* maak   = (const float*)d_in[3];
    const float* maav   = (const float*)d_in[4];
    const float* maar   = (const float*)d_in[5];
    const float* maag   = (const float*)d_in[6];
    const float* decay  = (const float*)d_in[7];
    const float* faaaa  = (const float*)d_in[8];
    const float* Wr     = (const float*)d_in[9];
    const float* Wk     = (const float*)d_in[10];
    const float* Wv     = (const float*)d_in[11];
    const float* Wg     = (const float*)d_in[12];
    const float* Wo     = (const float*)d_in[13];
    const float* gnw    = (const float*)d_in[14];
    const float* gnb    = (const float*)d_in[15];
    const float* ln2w   = (const float*)d_in[16];
    const float* ln2b   = (const float*)d_in[17];
    const float* cmaak  = (const float*)d_in[18];
    const float* cmaar  = (const float*)d_in[19];
    const float* Wck    = (const float*)d_in[20];
    const float* Wcv    = (const float*)d_in[21];
    const float* Wcr    = (const float*)d_in[22];
    float* out = (float*)d_out;

    float* sc = nullptr;
    cudaGetSymbolAddress((void**)&sc, g_scratch);

    __half* xk   = (__half*)(sc + OFF_XK);
    __half* xv   = (__half*)(sc + OFF_XV);
    __half* xr   = (__half*)(sc + OFF_XR);
    __half* xg   = (__half*)(sc + OFF_XG);
    float* rb   = sc + OFF_R;
    float* kb   = sc + OFF_K;
    float* vb   = sc + OFF_V;
    float* gb   = sc + OFF_G;
    float* yb   = sc + OFF_Y;
    __half* ygb = (__half*)(sc + OFF_YG);
    float* x1   = sc + OFF_X1;
    __half* xk2 = (__half*)(sc + OFF_XK2);
    __half* xr2 = (__half*)(sc + OFF_XR2);
    float* hv   = sc + OFF_HV;
    __half* hb  = (__half*)(sc + OFF_H);
    float* Sb   = sc + OFF_S;
    float* STb  = sc + OFF_ST;
    __half* WrR  = (__half*)(sc + OFF_WR_R);
    __half* WkR  = (__half*)(sc + OFF_WK_R);
    __half* WvR  = (__half*)(sc + OFF_WV_R);
    __half* WgR  = (__half*)(sc + OFF_WG_R);
    __half* WoR  = (__half*)(sc + OFF_WO_R);
    __half* WcrR = (__half*)(sc + OFF_WCR_R);
    __half* WckR = (__half*)(sc + OFF_WCK_R);
    __half* WcvR = (__half*)(sc + OFF_WCV_R);

    cudaFuncSetAttribute(wkv_y_kernel, cudaFuncAttributeMaxDynamicSharedMemorySize, WKV_Y_SMEM);
    cudaFuncSetAttribute(gemm_hf_kernel, cudaFuncAttributeMaxDynamicSharedMemorySize, GEMM_SMEM);

    dim3 g1024(1024 / 128, MTOT / 128);   // (8, 128)
    dim3 g3072(3072 / 128, MTOT / 128);   // (24, 128)
    int n4_1M = (CC * CC) / 4;
    int n4_3M = (3 * CC * CC) / 4;

    // ---- time mix ----
    ln_mix_kernel<4><<<MTOT, 256>>>(x, ln1w, ln1b, maak, maav, maar, maag, xk, xv, xr, xg);
    cvt_w_kernel<<<n4_1M / 256, 256>>>(Wr, WrR, n4_1M);
    cvt_w_kernel<<<n4_1M / 256, 256>>>(Wk, WkR, n4_1M);
    cvt_w_kernel<<<n4_1M / 256, 256>>>(Wv, WvR, n4_1M);
    cvt_w_kernel<<<n4_1M / 256, 256>>>(Wg, WgR, n4_1M);
    gemm_hf_kernel<<<g1024, 256, GEMM_SMEM>>>(xr, WrR, rb, nullptr, 1024, 1024, 0, nullptr, nullptr);
    gemm_hf_kernel<<<g1024, 256, GEMM_SMEM>>>(xk, WkR, kb, nullptr, 1024, 1024, 0, nullptr, nullptr);
    gemm_hf_kernel<<<g1024, 256, GEMM_SMEM>>>(xv, WvR, vb, nullptr, 1024, 1024, 0, nullptr, nullptr);
    gemm_hf_kernel<<<g1024, 256, GEMM_SMEM>>>(xg, WgR, gb, nullptr, 1024, 1024, 1, nullptr, nullptr); // silu

    wkv_s_kernel<<<BB * HH * NCK, 256>>>(kb, vb, decay, Sb);
    wkv_scan_kernel<<<BB * HH, 256>>>(Sb, decay, STb);
    wkv_y_kernel<<<BB * HH * NCK, 256, WKV_Y_SMEM>>>(rb, kb, vb, STb, decay, faaaa, yb);

    gn_mul_kernel<<<MTOT, 256>>>(yb, gnw, gnb, gb, ygb);
    cvt_w_kernel<<<n4_1M / 256, 256>>>(Wo, WoR, n4_1M);
    gemm_hf_kernel<<<g1024, 256, GEMM_SMEM>>>(ygb, WoR, x1, nullptr, 1024, 1024, 4, x, nullptr); // + residual

    // ---- channel mix ----
    ln_mix_kernel<2><<<MTOT, 256>>>(x1, ln2w, ln2b, cmaak, cmaar, nullptr, nullptr,
                                    xk2, xr2, nullptr, nullptr);
    cvt_w_kernel<<<n4_3M / 256, 256>>>(Wck, WckR, n4_3M);
    cvt_w_kernel<<<n4_3M / 256, 256>>>(Wcv, WcvR, n4_3M);
    cvt_w_kernel<<<n4_1M / 256, 256>>>(Wcr, WcrR, n4_1M);
    gemm_hf_kernel<<<g3072, 256, GEMM_SMEM>>>(xk2, WckR, nullptr, hb, 3072, 1024, 2, nullptr, nullptr); // relu^2 -> fp16
    gemm_hf_kernel<<<g1024, 256, GEMM_SMEM>>>(hb, WcvR, hv, nullptr, 1024, 3072, 0, nullptr, nullptr);
    gemm_hf_kernel<<<g1024, 256, GEMM_SMEM>>>(xr2, WcrR, out, nullptr, 1024, 1024, 3, hv, x1); // sigmoid*hv + x1
}

// round 11
// speedup vs baseline: 1.1963x; 1.0319x over previous
#include <cuda_runtime.h>
#include <cuda_fp16.h>
#include <math.h>
#include <stdint.h>

// ---------------- problem constants ----------------
#define BB 4
#define TT 4096
#define CC 1024
#define HH 16
#define NHD 64
#define QQ 256
#define NCK 16
#define MTOT (BB*TT)          // 16384
#define BTC (BB*TT*CC)        // 16777216
#define EPS_LN 1e-5f
#define EPS_GN (1e-5f*64.0f)

// ---------------- scratch ----------------
#define SCR_TOTAL (19ull*BTC + 8388608ull + 12582912ull)
__device__ float g_scratch[SCR_TOTAL];

#define OFF_XK   (1ull*BTC)      // fp16
#define OFF_XV   (2ull*BTC)
#define OFF_XR   (3ull*BTC)
#define OFF_XG   (4ull*BTC)
#define OFF_R    (5ull*BTC)      // fp16 now
#define OFF_K    (6ull*BTC)      // fp16 now
#define OFF_V    (7ull*BTC)      // fp16 now
#define OFF_G    (8ull*BTC)      // fp16 now
#define OFF_Y    (9ull*BTC)      // fp32
#define OFF_YG   (10ull*BTC)     // fp16
#define OFF_X1   (11ull*BTC)     // fp32
#define OFF_XK2  (13ull*BTC)     // fp16
#define OFF_XR2  (14ull*BTC)     // fp16
#define OFF_HV   (15ull*BTC)     // fp32
#define OFF_H    (16ull*BTC)     // fp16 [16384,3072]
#define OFF_S    (19ull*BTC)
#define OFF_ST   (19ull*BTC + 4194304ull)
#define OFF_WT   (19ull*BTC + 8388608ull)
#define OFF_WR_R  (OFF_WT + 0ull)
#define OFF_WK_R  (OFF_WT + 1048576ull)
#define OFF_WV_R  (OFF_WT + 2097152ull)
#define OFF_WG_R  (OFF_WT + 3145728ull)
#define OFF_WO_R  (OFF_WT + 4194304ull)
#define OFF_WCR_R (OFF_WT + 5242880ull)
#define OFF_WCK_R (OFF_WT + 6291456ull)
#define OFF_WCV_R (OFF_WT + 9437184ull)

// ---------------- helpers ----------------
__device__ __forceinline__ uint32_t smem_u32(const void* p) {
    uint32_t a;
    asm("{ .reg .u64 t; cvta.to.shared.u64 t, %1; cvt.u32.u64 %0, t; }" : "=r"(a) : "l"(p));
    return a;
}

__device__ __forceinline__ uint32_t pack_f16(float a, float b) {
    __half2 h = __floats2half2_rn(a, b);
    return *(uint32_t*)&h;
}

__device__ __forceinline__ float2 h2f(uint32_t h) {
    __half2 v = *(__half2*)&h;
    return __half22float2(v);
}

__device__ __forceinline__ void cp16(uint32_t dst, const void* src) {
    asm volatile("cp.async.cg.shared.global [%0], [%1], 16;" :: "r"(dst), "l"(src) : "memory");
}
#define CP_COMMIT() asm volatile("cp.async.commit_group;" ::: "memory")
#define CP_WAIT_1() asm volatile("cp.async.wait_group 1;" ::: "memory")

// ---------------- all-weight fp32 -> fp16 (single launch) ----------------
struct CvtArgs {
    const float* src[8];
    __half* dst[8];
    int end4[8];          // cumulative end (float4 units)
};
__global__ __launch_bounds__(256) void cvt_all_kernel(CvtArgs a)
{
    int i = blockIdx.x * 256 + threadIdx.x;
    int seg = 0;
    #pragma unroll
    for (int s = 0; s < 7; s++) seg += (i >= a.end4[s]) ? 1 : 0;
    int base = (seg == 0) ? 0 : a.end4[seg - 1];
    int li = i - base;
    float4 v = ((const float4*)a.src[seg])[li];
    uint2 o;
    o.x = pack_f16(v.x, v.y);
    o.y = pack_f16(v.z, v.w);
    ((uint2*)a.dst[seg])[li] = o;
}

// ---------------- fused LayerNorm + time-shift mix (fp16 outputs) ----------------
template<int NOUT>
__global__ __launch_bounds__(256) void ln_mix_kernel(const float* __restrict__ x,
                                                     const float* __restrict__ w,
                                                     const float* __restrict__ b,
                                                     const float* __restrict__ m0,
                                                     const float* __restrict__ m1,
                                                     const float* __restrict__ m2,
                                                     const float* __restrict__ m3,
                                                     __half* __restrict__ o0,
                                                     __half* __restrict__ o1,
                                                     __half* __restrict__ o2,
                                                     __half* __restrict__ o3)
{
    int row = blockIdx.x;
    int t = row % TT;
    int tid = threadIdx.x;
    size_t off = (size_t)row * CC;
    float4 cur = ((const float4*)(x + off))[tid];
    float4 prv = make_float4(0.f, 0.f, 0.f, 0.f);
    if (t > 0) prv = ((const float4*)(x + off - CC))[tid];

    float s0 = cur.x + cur.y + cur.z + cur.w;
    float q0 = cur.x*cur.x + cur.y*cur.y + cur.z*cur.z + cur.w*cur.w;
    float s1 = prv.x + prv.y + prv.z + prv.w;
    float q1 = prv.x*prv.x + prv.y*prv.y + prv.z*prv.z + prv.w*prv.w;
    #pragma unroll
    for (int o = 16; o >= 1; o >>= 1) {
        s0 += __shfl_xor_sync(0xffffffffu, s0, o);
        q0 += __shfl_xor_sync(0xffffffffu, q0, o);
        s1 += __shfl_xor_sync(0xffffffffu, s1, o);
        q1 += __shfl_xor_sync(0xffffffffu, q1, o);
    }
    __shared__ float red[4][8];
    int wid = tid >> 5, lane = tid & 31;
    if (lane == 0) { red[0][wid] = s0; red[1][wid] = q0; red[2][wid] = s1; red[3][wid] = q1; }
    __syncthreads();
    if (tid == 0) {
        float a0 = 0, a1 = 0, a2 = 0, a3 = 0;
        #pragma unroll
        for (int i = 0; i < 8; i++) { a0 += red[0][i]; a1 += red[1][i]; a2 += red[2][i]; a3 += red[3][i]; }
        red[0][0] = a0; red[1][0] = a1; red[2][0] = a2; red[3][0] = a3;
    }
    __syncthreads();
    float mu0 = red[0][0] * (1.0f / CC);
    float rs0 = rsqrtf(red[1][0] * (1.0f / CC) - mu0 * mu0 + EPS_LN);
    float mu1 = red[2][0] * (1.0f / CC);
    float rs1 = rsqrtf(red[3][0] * (1.0f / CC) - mu1 * mu1 + EPS_LN);

    float4 ww = ((const float4*)w)[tid];
    float4 bb = ((const float4*)b)[tid];
    float4 lc, lp;
    lc.x = (cur.x - mu0) * rs0 * ww.x + bb.x;
    lc.y = (cur.y - mu0) * rs0 * ww.y + bb.y;
    lc.z = (cur.z - mu0) * rs0 * ww.z + bb.z;
    lc.w = (cur.w - mu0) * rs0 * ww.w + bb.w;
    if (t > 0) {
        lp.x = (prv.x - mu1) * rs1 * ww.x + bb.x;
        lp.y = (prv.y - mu1) * rs1 * ww.y + bb.y;
        lp.z = (prv.z - mu1) * rs1 * ww.z + bb.z;
        lp.w = (prv.w - mu1) * rs1 * ww.w + bb.w;
    } else {
        lp = make_float4(0.f, 0.f, 0.f, 0.f);
    }
    float4 xx = make_float4(lp.x - lc.x, lp.y - lc.y, lp.z - lc.z, lp.w - lc.w);

    float4 a;
    uint2 o;
    a = ((const float4*)m0)[tid];
    o.x = pack_f16(lc.x + xx.x * a.x, lc.y + xx.y * a.y);
    o.y = pack_f16(lc.z + xx.z * a.z, lc.w + xx.w * a.w);
    ((uint2*)(o0 + off))[tid] = o;
    a = ((const float4*)m1)[tid];
    o.x = pack_f16(lc.x + xx.x * a.x, lc.y + xx.y * a.y);
    o.y = pack_f16(lc.z + xx.z * a.z, lc.w + xx.w * a.w);
    ((uint2*)(o1 + off))[tid] = o;
    if (NOUT == 4) {
        a = ((const float4*)m2)[tid];
        o.x = pack_f16(lc.x + xx.x * a.x, lc.y + xx.y * a.y);
        o.y = pack_f16(lc.z + xx.z * a.z, lc.w + xx.w * a.w);
        ((uint2*)(o2 + off))[tid] = o;
        a = ((const float4*)m3)[tid];
        o.x = pack_f16(lc.x + xx.x * a.x, lc.y + xx.y * a.y);
        o.y = pack_f16(lc.z + xx.z * a.z, lc.w + xx.w * a.w);
        ((uint2*)(o3 + off))[tid] = o;
    }
}

// ---------------- fp16 tensor-core GEMM core (round-8 config) ----------------
#define STG_WORDS 9216
#define GEMM_SMEM (2 * STG_WORDS * 4)         // 73728 bytes

__device__ __forceinline__ void mma_f16(float c[4],
                                        const uint32_t a[4],
                                        const uint32_t b[2])
{
    asm volatile(
        "mma.sync.aligned.m16n8k16.row.col.f32.f16.f16.f32 "
        "{%0,%1,%2,%3}, {%4,%5,%6,%7}, {%8,%9}, {%0,%1,%2,%3};\n"
        : "+f"(c[0]), "+f"(c[1]), "+f"(c[2]), "+f"(c[3])
        : "r"(a[0]), "r"(a[1]), "r"(a[2]), "r"(a[3]),
          "r"(b[0]), "r"(b[1]));
}

#define LDMATRIX_X4(r0, r1, r2, r3, addr) \
    asm volatile("ldmatrix.sync.aligned.m8n8.x4.shared.b16 {%0,%1,%2,%3}, [%4];" \
        : "=r"(r0), "=r"(r1), "=r"(r2), "=r"(r3) : "r"(addr))

// Shared mainloop: computes acc for one 128x128 tile.
__device__ __forceinline__ void gemm_mainloop(const __half* __restrict__ A,
                                              const __half* __restrict__ W,
                                              int K, int m0, int n0,
                                              uint32_t* smw, int tid,
                                              float acc[4][4][4])
{
    int lane = tid & 31;
    int j  = tid & 7;
    int r0 = tid >> 3;
    const __half* pA = A + ((size_t)m0 + r0) * K + j * 8;
    const __half* pW = W + ((size_t)n0 + r0) * K + j * 8;
    uint32_t smb = smem_u32(smw);
    uint32_t dstA = smb + (uint32_t)(r0 * 36 + j * 4) * 4u;
    uint32_t dstW = dstA + 4608u * 4u;
    int wid = tid >> 5;
    int wm = wid >> 2, wn = wid & 3;

    uint32_t aAddr[4], bAddr[2];
    #pragma unroll
    for (int mi = 0; mi < 4; mi++)
        aAddr[mi] = smb + (uint32_t)((wm * 64 + mi * 16 + (lane & 15)) * 36) * 4u
                        + (uint32_t)(lane >> 4) * 16u;
    #pragma unroll
    for (int p = 0; p < 2; p++)
        bAddr[p] = smb + 4608u * 4u
                 + (uint32_t)((wn * 32 + (p * 2 + (lane >> 4)) * 8 + (lane & 7)) * 36) * 4u
                 + (uint32_t)((lane >> 3) & 1) * 16u;

    int NC = K >> 6;

    #pragma unroll
    for (int s = 0; s < 2; s++) {
        uint32_t so = (uint32_t)(s * STG_WORDS) * 4u;
        int kf = s * 64;
        #pragma unroll
        for (int i = 0; i < 4; i++) {
            cp16(dstA + so + (uint32_t)(i * 32 * 36) * 4u, pA + (size_t)(i * 32) * K + kf);
            cp16(dstW + so + (uint32_t)(i * 32 * 36) * 4u, pW + (size_t)(i * 32) * K + kf);
        }
        CP_COMMIT();
    }

    for (int t = 0; t < NC; t++) {
        CP_WAIT_1();
        __syncthreads();
        uint32_t so = (uint32_t)((t & 1) * STG_WORDS) * 4u;

        #pragma unroll
        for (int kk = 0; kk < 4; kk++) {
            uint32_t ko = so + (uint32_t)kk * 32u;
            uint32_t af[4][4];
            uint32_t bf[4][2];
            #pragma unroll
            for (int mi = 0; mi < 4; mi++)
                LDMATRIX_X4(af[mi][0], af[mi][1], af[mi][2], af[mi][3], aAddr[mi] + ko);
            #pragma unroll
            for (int p = 0; p < 2; p++)
                LDMATRIX_X4(bf[2*p][0], bf[2*p][1], bf[2*p+1][0], bf[2*p+1][1], bAddr[p] + ko);
            #pragma unroll
            for (int mi = 0; mi < 4; mi++)
                #pragma unroll
                for (int ni = 0; ni < 4; ni++)
                    mma_f16(acc[mi][ni], af[mi], bf[ni]);
        }
        __syncthreads();

        int lc = t + 2;
        if (lc < NC) {
            uint32_t so2 = (uint32_t)((t & 1) * STG_WORDS) * 4u;
            int kf = lc * 64;
            #pragma unroll
            for (int i = 0; i < 4; i++) {
                cp16(dstA + so2 + (uint32_t)(i * 32 * 36) * 4u, pA + (size_t)(i * 32) * K + kf);
                cp16(dstW + so2 + (uint32_t)(i * 32 * 36) * 4u, pW + (size_t)(i * 32) * K + kf);
            }
        }
        CP_COMMIT();
    }
}

__device__ __forceinline__ float gemm_epi(float vv, int epi, const float* aux1,
                                          const float* aux2, size_t o)
{
    if (epi == 1) {
        vv = vv / (1.f + expf(-vv));
    } else if (epi == 3) {
        vv = 1.f / (1.f + expf(-vv));
        vv = vv * aux1[o] + aux2[o];
    } else if (epi == 4) {
        vv = vv + aux1[o];
    }
    return vv;
}

// generic single-GEMM kernel (epi 0/1/3/4 -> fp32 out; epi 2 relu^2 -> fp16 out)
__global__ void __launch_bounds__(256, 2)
gemm_hf_kernel(const __half* __restrict__ A, const __half* __restrict__ W,
               float* __restrict__ Co, __half* __restrict__ Coh,
               int Nn, int K, int epi,
               const float* __restrict__ aux1, const float* __restrict__ aux2)
{
    extern __shared__ uint32_t smw[];
    int tid = threadIdx.x;
    int n0 = blockIdx.x * 128;
    int m0 = blockIdx.y * 128;
    int wid = tid >> 5, lane = tid & 31;
    int wm = wid >> 2, wn = wid & 3;
    int gid = lane >> 2, tg = lane & 3;

    float acc[4][4][4];
    #pragma unroll
    for (int mi = 0; mi < 4; mi++)
        #pragma unroll
        for (int ni = 0; ni < 4; ni++)
            #pragma unroll
            for (int e = 0; e < 4; e++) acc[mi][ni][e] = 0.f;

    gemm_mainloop(A, W, K, m0, n0, smw, tid, acc);

    #pragma unroll
    for (int mi = 0; mi < 4; mi++) {
        int row0 = m0 + wm * 64 + mi * 16 + gid;
        #pragma unroll
        for (int ni = 0; ni < 4; ni++) {
            int col0 = n0 + wn * 32 + ni * 8 + tg * 2;
            size_t o0 = (size_t)row0 * Nn + col0;
            size_t o1 = (size_t)(row0 + 8) * Nn + col0;
            if (epi == 2) {
                float a0 = fmaxf(acc[mi][ni][0], 0.f); a0 *= a0;
                float a1 = fmaxf(acc[mi][ni][1], 0.f); a1 *= a1;
                float a2 = fmaxf(acc[mi][ni][2], 0.f); a2 *= a2;
                float a3 = fmaxf(acc[mi][ni][3], 0.f); a3 *= a3;
                *(uint32_t*)(Coh + o0) = pack_f16(a0, a1);
                *(uint32_t*)(Coh + o1) = pack_f16(a2, a3);
            } else {
                float2 v0, v1;
                v0.x = gemm_epi(acc[mi][ni][0], epi, aux1, aux2, o0);
                v0.y = gemm_epi(acc[mi][ni][1], epi, aux1, aux2, o0 + 1);
                v1.x = gemm_epi(acc[mi][ni][2], epi, aux1, aux2, o1);
                v1.y = gemm_epi(acc[mi][ni][3], epi, aux1, aux2, o1 + 1);
                *(float2*)(Co + o0) = v0;
                *(float2*)(Co + o1) = v1;
            }
        }
    }
}

// merged 4-GEMM kernel for tmix (z selects A/W/out; fp16 outputs; silu flag per z)
struct Gemm4Args {
    const __half* A[4];
    const __half* W[4];
    __half* O[4];
    int silu[4];
};
__global__ void __launch_bounds__(256, 2)
gemm_hf4_kernel(Gemm4Args args)
{
    extern __shared__ uint32_t smw[];
    int z = blockIdx.z;
    const __half* A = args.A[z];
    const __half* W = args.W[z];
    __half* O = args.O[z];
    int silu = args.silu[z];

    int tid = threadIdx.x;
    int n0 = blockIdx.x * 128;
    int m0 = blockIdx.y * 128;
    int wid = tid >> 5, lane = tid & 31;
    int wm = wid >> 2, wn = wid & 3;
    int gid = lane >> 2, tg = lane & 3;

    float acc[4][4][4];
    #pragma unroll
    for (int mi = 0; mi < 4; mi++)
        #pragma unroll
        for (int ni = 0; ni < 4; ni++)
            #pragma unroll
            for (int e = 0; e < 4; e++) acc[mi][ni][e] = 0.f;

    gemm_mainloop(A, W, 1024, m0, n0, smw, tid, acc);

    #pragma unroll
    for (int mi = 0; mi < 4; mi++) {
        int row0 = m0 + wm * 64 + mi * 16 + gid;
        #pragma unroll
        for (int ni = 0; ni < 4; ni++) {
            int col0 = n0 + wn * 32 + ni * 8 + tg * 2;
            size_t o0 = (size_t)row0 * 1024 + col0;
            size_t o1 = (size_t)(row0 + 8) * 1024 + col0;
            float a0 = acc[mi][ni][0], a1 = acc[mi][ni][1];
            float a2 = acc[mi][ni][2], a3 = acc[mi][ni][3];
            if (silu) {
                a0 = a0 / (1.f + expf(-a0));
                a1 = a1 / (1.f + expf(-a1));
                a2 = a2 / (1.f + expf(-a2));
                a3 = a3 / (1.f + expf(-a3));
            }
            *(uint32_t*)(O + o0) = pack_f16(a0, a1);
            *(uint32_t*)(O + o1) = pack_f16(a2, a3);
        }
    }
}

// ---------------- WKV: per-chunk state contribution S = (k*wk) @ v (fp16 in) ----------------
__global__ __launch_bounds__(256) void wkv_s_kernel(const __half* __restrict__ k,
                                                    const __half* __restrict__ v,
                                                    const float* __restrict__ decay,
                                                    float* __restrict__ S)
{
    int blk = blockIdx.x;
    int c = blk % NCK;
    int h = (blk / NCK) % HH;
    int b = blk / (NCK * HH);
    __shared__ float ksm[64][64];
    __shared__ float vsm[64][64];
    __shared__ float wpow[256];
    int tid = threadIdx.x;
    float ew = expf(decay[h]);
    wpow[tid] = expf(-ew * (float)tid);
    int n  = tid >> 2;
    int mg = (tid & 3) * 16;
    float acc[16];
    #pragma unroll
    for (int jj = 0; jj < 16; jj++) acc[jj] = 0.f;

    size_t base = ((size_t)b * TT + (size_t)c * QQ) * CC + (size_t)h * NHD;

    for (int qc = 0; qc < 4; qc++) {
        __syncthreads();
        for (int l = tid; l < 64 * 16; l += 256) {
            int qq = l >> 4;
            int f  = (l & 15) * 4;
            uint2 kk = *(const uint2*)(k + base + (size_t)(qc * 64 + qq) * CC + f);
            uint2 vv = *(const uint2*)(v + base + (size_t)(qc * 64 + qq) * CC + f);
            float2 ka = h2f(kk.x), kb2 = h2f(kk.y);
            float2 va = h2f(vv.x), vb2 = h2f(vv.y);
            ksm[qq][f] = ka.x; ksm[qq][f+1] = ka.y; ksm[qq][f+2] = kb2.x; ksm[qq][f+3] = kb2.y;
            vsm[qq][f] = va.x; vsm[qq][f+1] = va.y; vsm[qq][f+2] = vb2.x; vsm[qq][f+3] = vb2.y;
        }
        __syncthreads();
        #pragma unroll 4
        for (int qq = 0; qq < 64; qq++) {
            float kw = ksm[qq][n] * wpow[255 - (qc * 64 + qq)];
            const float4* vr = (const float4*)&vsm[qq][mg];
            float4 v0 = vr[0], v1 = vr[1], v2 = vr[2], v3 = vr[3];
            acc[0]  += kw * v0.x; acc[1]  += kw * v0.y; acc[2]  += kw * v0.z; acc[3]  += kw * v0.w;
            acc[4]  += kw * v1.x; acc[5]  += kw * v1.y; acc[6]  += kw * v1.z; acc[7]  += kw * v1.w;
            acc[8]  += kw * v2.x; acc[9]  += kw * v2.y; acc[10] += kw * v2.z; acc[11] += kw * v2.w;
            acc[12] += kw * v3.x; acc[13] += kw * v3.y; acc[14] += kw * v3.z; acc[15] += kw * v3.w;
        }
    }
    float* Sp = S + (size_t)blk * 4096 + n * 64 + mg;
    #pragma unroll
    for (int jj = 0; jj < 16; jj++) Sp[jj] = acc[jj];
}

// ---------------- WKV: inter-chunk prefix scan (wide grid) ----------------
__global__ __launch_bounds__(256) void wkv_scan_kernel(const float* __restrict__ S,
                                                       const float* __restrict__ decay,
                                                       float* __restrict__ ST)
{
    int bh = blockIdx.x >> 4;          // (b,h)
    int part = blockIdx.x & 15;
    int h = bh % HH;
    float ws = expf(-expf(decay[h]) * 256.0f);
    int e = part * 256 + threadIdx.x;  // 0..4095
    size_t b0 = (size_t)bh * NCK * 4096;
    float st = 0.f;
    #pragma unroll
    for (int c = 0; c < NCK; c++) {
        ST[b0 + (size_t)c * 4096 + e] = st;
        st = ws * st + S[b0 + (size_t)c * 4096 + e];
    }
}

// ---------------- WKV: per-chunk output (sub-chunking L=64, fp16 in) ----------------
#define WKV_Y_SMEM ((16384 + 16384 + 16384 + 256) * 4)   // 197632 bytes
__global__ __launch_bounds__(256) void wkv_y_kernel(const __half* __restrict__ r,
                                                    const __half* __restrict__ k,
                                                    const __half* __restrict__ v,
                                                    const float* __restrict__ ST,
                                                    const float* __restrict__ decay,
                                                    const float* __restrict__ faaaa,
                                                    float* __restrict__ y)
{
    extern __shared__ float sm[];
    float* ksm  = sm;
    float* vsm  = sm + 16384;
    float* sst  = sm + 32768;
    float* wpow = sm + 49152;

    int blk = blockIdx.x;
    int c = blk % NCK;
    int h = (blk / NCK) % HH;
    int b = blk / (NCK * HH);
    int tid = threadIdx.x;

    float ew = expf(decay[h]);
    float u  = faaaa[h];
    wpow[tid] = expf(-ew * (float)tid);

    size_t base = ((size_t)b * TT + (size_t)c * QQ) * CC + (size_t)h * NHD;

    for (int l = tid; l < 256 * 16; l += 256) {
        int qq = l >> 4;
        int f  = (l & 15) * 4;
        uint2 kk = *(const uint2*)(k + base + (size_t)qq * CC + f);
        uint2 vv = *(const uint2*)(v + base + (size_t)qq * CC + f);
        float2 ka = h2f(kk.x), kb2 = h2f(kk.y);
        float2 va = h2f(vv.x), vb2 = h2f(vv.y);
        ksm[qq * 64 + f] = ka.x; ksm[qq * 64 + f + 1] = ka.y;
        ksm[qq * 64 + f + 2] = kb2.x; ksm[qq * 64 + f + 3] = kb2.y;
        vsm[qq * 64 + f] = va.x; vsm[qq * 64 + f + 1] = va.y;
        vsm[qq * 64 + f + 2] = vb2.x; vsm[qq * 64 + f + 3] = vb2.y;
    }
    size_t sbase = (size_t)blk * 4096;
    for (int l = tid; l < 1024; l += 256)
        *(float4*)&sst[l * 4] = *(const float4*)(ST + sbase + (size_t)l * 4);
    __syncthreads();

    // precompute sub-chunk states sst[1..3]
    {
        int n  = tid >> 2;
        int mg = (tid & 3) * 16;
        float w64 = expf(-ew * 64.0f);
        float st_prev[16];
        #pragma unroll
        for (int e = 0; e < 16; e++) st_prev[e] = sst[n * 64 + mg + e];
        #pragma unroll 1
        for (int s = 1; s < 4; s++) {
            float tmp[16];
            #pragma unroll
            for (int e = 0; e < 16; e++) tmp[e] = w64 * st_prev[e];
            int j0 = (s - 1) * 64;
            #pragma unroll 4
            for (int jl = 0; jl < 64; jl++) {
                float kw = ksm[(j0 + jl) * 64 + n] * wpow[63 - jl];
                const float4* vr = (const float4*)&vsm[(j0 + jl) * 64 + mg];
                float4 v0 = vr[0], v1 = vr[1], v2 = vr[2], v3 = vr[3];
                tmp[0]  += kw * v0.x; tmp[1]  += kw * v0.y; tmp[2]  += kw * v0.z; tmp[3]  += kw * v0.w;
                tmp[4]  += kw * v1.x; tmp[5]  += kw * v1.y; tmp[6]  += kw * v1.z; tmp[7]  += kw * v1.w;
                tmp[8]  += kw * v2.x; tmp[9]  += kw * v2.y; tmp[10] += kw * v2.z; tmp[11] += kw * v2.w;
                tmp[12] += kw * v3.x; tmp[13] += kw * v3.y; tmp[14] += kw * v3.z; tmp[15] += kw * v3.w;
            }
            float* so = sst + s * 4096 + n * 64 + mg;
            #pragma unroll
            for (int e = 0; e < 16; e++) { so[e] = tmp[e]; st_prev[e] = tmp[e]; }
        }
    }
    __syncthreads();

    int q  = tid;
    int qs = q >> 6;
    int ql = q & 63;
    float rrow[64];
    {
        const uint4* rg = (const uint4*)(r + base + (size_t)q * CC);
        #pragma unroll
        for (int f = 0; f < 8; f++) {
            uint4 t4 = rg[f];
            float2 p0 = h2f(t4.x), p1 = h2f(t4.y), p2 = h2f(t4.z), p3 = h2f(t4.w);
            rrow[f * 8 + 0] = p0.x; rrow[f * 8 + 1] = p0.y;
            rrow[f * 8 + 2] = p1.x; rrow[f * 8 + 3] = p1.y;
            rrow[f * 8 + 4] = p2.x; rrow[f * 8 + 5] = p2.y;
            rrow[f * 8 + 6] = p3.x; rrow[f * 8 + 7] = p3.y;
        }
    }
    float acc[64];
    #pragma unroll
    for (int m = 0; m < 64; m++) acc[m] = 0.f;

    const float* stq = sst + qs * 4096;
    #pragma unroll 8
    for (int n = 0; n < 64; n++) {
        float rv = rrow[n];
        const float4* srow = (const float4*)&stq[n * 64];
        #pragma unroll
        for (int m4 = 0; m4 < 16; m4++) {
            float4 s4 = srow[m4];
            acc[m4 * 4 + 0] += rv * s4.x;
            acc[m4 * 4 + 1] += rv * s4.y;
            acc[m4 * 4 + 2] += rv * s4.z;
            acc[m4 * 4 + 3] += rv * s4.w;
        }
    }
    float wbq = wpow[ql];
    #pragma unroll
    for (int m = 0; m < 64; m++) acc[m] *= wbq;

    int j0 = qs * 64;
    int jend = ql | 31;
    for (int jl = 0; jl <= jend; jl++) {
        float a = 0.f;
        const float4* krow = (const float4*)&ksm[(j0 + jl) * 64];
        #pragma unroll
        for (int n4 = 0; n4 < 16; n4++) {
            float4 k4 = krow[n4];
            a += rrow[n4 * 4 + 0] * k4.x + rrow[n4 * 4 + 1] * k4.y
               + rrow[n4 * 4 + 2] * k4.z + rrow[n4 * 4 + 3] * k4.w;
        }
        float coef = (jl < ql) ? wpow[ql - jl - 1] : ((jl == ql) ? u : 0.0f);
        a *= coef;
        const float4* vrow = (const float4*)&vsm[(j0 + jl) * 64];
        #pragma unroll
        for (int m4 = 0; m4 < 16; m4++) {
            float4 v4 = vrow[m4];
            acc[m4 * 4 + 0] += a * v4.x;
            acc[m4 * 4 + 1] += a * v4.y;
            acc[m4 * 4 + 2] += a * v4.z;
            acc[m4 * 4 + 3] += a * v4.w;
        }
    }

    float* yo = y + base + (size_t)q * CC;
    #pragma unroll
    for (int m4 = 0; m4 < 16; m4++) {
        float4 o4 = make_float4(acc[m4 * 4 + 0], acc[m4 * 4 + 1], acc[m4 * 4 + 2], acc[m4 * 4 + 3]);
        *(float4*)(yo + m4 * 4) = o4;
    }
}

// ---------------- GroupNorm * g (fp16 g input, fp16 output) ----------------
__global__ __launch_bounds__(256) void gn_mul_kernel(const float* __restrict__ y,
                                                     const float* __restrict__ gnw,
                                                     const float* __restrict__ gnb,
                                                     const __half* __restrict__ g,
                                                     __half* __restrict__ yg)
{
    int row = blockIdx.x;
    int tid = threadIdx.x;
    size_t off = (size_t)row * CC;
    float4 v = ((const float4*)(y + off))[tid];
    float s  = v.x + v.y + v.z + v.w;
    float sq = v.x*v.x + v.y*v.y + v.z*v.z + v.w*v.w;
    #pragma unroll
    for (int o = 8; o >= 1; o >>= 1) {
        s  += __shfl_xor_sync(0xffffffffu, s,  o);
        sq += __shfl_xor_sync(0xffffffffu, sq, o);
    }
    float mu   = s * (1.0f / 64.0f);
    float var  = sq * (1.0f / 64.0f) - mu * mu;
    float rstd = rsqrtf(var + EPS_GN);
    float4 ww = ((const float4*)gnw)[tid];
    float4 bb = ((const float4*)gnb)[tid];
    uint2 gg2 = ((const uint2*)(g + off))[tid];
    float2 g0 = h2f(gg2.x), g1 = h2f(gg2.y);
    uint2 o4;
    o4.x = pack_f16(((v.x - mu) * rstd * ww.x + bb.x) * g0.x,
                    ((v.y - mu) * rstd * ww.y + bb.y) * g0.y);
    o4.y = pack_f16(((v.z - mu) * rstd * ww.z + bb.z) * g1.x,
                    ((v.w - mu) * rstd * ww.w + bb.w) * g1.y);
    ((uint2*)(yg + off))[tid] = o4;
}

// ---------------- host launcher ----------------
extern "C" void kernel_launch(void* const* d_in, const int* in_sizes, int n_in,
                              void* d_out, int out_size)
{
    const float* x      = (const float*)d_in[0];
    const float* ln1w   = (const float*)d_in[1];
    const float* ln1b   = (const float*)d_in[2];
    const float* maak   = (const float*)d_in[3];
    const float* maav   = (const float*)d_in[4];
    const float* maar   = (const float*)d_in[5];
    const float* maag   = (const float*)d_in[6];
    const float* decay  = (const float*)d_in[7];
    const float* faaaa  = (const float*)d_in[8];
    const float* Wr     = (const float*)d_in[9];
    const float* Wk     = (const float*)d_in[10];
    const float* Wv     = (const float*)d_in[11];
    const float* Wg     = (const float*)d_in[12];
    const float* Wo     = (const float*)d_in[13];
    const float* gnw    = (const float*)d_in[14];
    const float* gnb    = (const float*)d_in[15];
    const float* ln2w   = (const float*)d_in[16];
    const float* ln2b   = (const float*)d_in[17];
    const float* cmaak  = (const float*)d_in[18];
    const float* cmaar  = (const float*)d_in[19];
    const float* Wck    = (const float*)d_in[20];
    const float* Wcv    = (const float*)d_in[21];
    const float* Wcr    = (const float*)d_in[22];
    float* out = (float*)d_out;

    float* sc = nullptr;
    cudaGetSymbolAddress((void**)&sc, g_scratch);

    __half* xk   = (__half*)(sc + OFF_XK);
    __half* xv   = (__half*)(sc + OFF_XV);
    __half* xr   = (__half*)(sc + OFF_XR);
    __half* xg   = (__half*)(sc + OFF_XG);
    __half* rb   = (__half*)(sc + OFF_R);
    __half* kb   = (__half*)(sc + OFF_K);
    __half* vb   = (__half*)(sc + OFF_V);
    __half* gb   = (__half*)(sc + OFF_G);
    float* yb   = sc + OFF_Y;
    __half* ygb = (__half*)(sc + OFF_YG);
    float* x1   = sc + OFF_X1;
    __half* xk2 = (__half*)(sc + OFF_XK2);
    __half* xr2 = (__half*)(sc + OFF_XR2);
    float* hv   = sc + OFF_HV;
    __half* hb  = (__half*)(sc + OFF_H);
    float* Sb   = sc + OFF_S;
    float* STb  = sc + OFF_ST;
    __half* WrR  = (__half*)(sc + OFF_WR_R);
    __half* WkR  = (__half*)(sc + OFF_WK_R);
    __half* WvR  = (__half*)(sc + OFF_WV_R);
    __half* WgR  = (__half*)(sc + OFF_WG_R);
    __half* WoR  = (__half*)(sc + OFF_WO_R);
    __half* WcrR = (__half*)(sc + OFF_WCR_R);
    __half* WckR = (__half*)(sc + OFF_WCK_R);
    __half* WcvR = (__half*)(sc + OFF_WCV_R);

    cudaFuncSetAttribute(wkv_y_kernel, cudaFuncAttributeMaxDynamicSharedMemorySize, WKV_Y_SMEM);
    cudaFuncSetAttribute(gemm_hf_kernel, cudaFuncAttributeMaxDynamicSharedMemorySize, GEMM_SMEM);
    cudaFuncSetAttribute(gemm_hf4_kernel, cudaFuncAttributeMaxDynamicSharedMemorySize, GEMM_SMEM);

    dim3 g1024(1024 / 128, MTOT / 128);        // (8, 128)
    dim3 g1024z4(1024 / 128, MTOT / 128, 4);   // (8, 128, 4)
    dim3 g3072(3072 / 128, MTOT / 128);        // (24, 128)

    // ---- weight conversion: single launch ----
    {
        CvtArgs ca;
        const float* srcs[8] = {Wr, Wk, Wv, Wg, Wo, Wcr, Wck, Wcv};
        __half* dsts[8] = {WrR, WkR, WvR, WgR, WoR, WcrR, WckR, WcvR};
        int sz4[8] = {262144, 262144, 262144, 262144, 262144, 262144, 786432, 786432};
        int acc4 = 0;
        for (int i = 0; i < 8; i++) { ca.src[i] = srcs[i]; ca.dst[i] = dsts[i]; acc4 += sz4[i]; ca.end4[i] = acc4; }
        cvt_all_kernel<<<acc4 / 256, 256>>>(ca);
    }

    // ---- time mix ----
    ln_mix_kernel<4><<<MTOT, 256>>>(x, ln1w, ln1b, maak, maav, maar, maag, xk, xv, xr, xg);
    {
        Gemm4Args ga;
        ga.A[0] = xr; ga.W[0] = WrR; ga.O[0] = rb; ga.silu[0] = 0;
        ga.A[1] = xk; ga.W[1] = WkR; ga.O[1] = kb; ga.silu[1] = 0;
        ga.A[2] = xv; ga.W[2] = WvR; ga.O[2] = vb; ga.silu[2] = 0;
        ga.A[3] = xg; ga.W[3] = WgR; ga.O[3] = gb; ga.silu[3] = 1;
        gemm_hf4_kernel<<<g1024z4, 256, GEMM_SMEM>>>(ga);
    }

    wkv_s_kernel<<<BB * HH * NCK, 256>>>(kb, vb, decay, Sb);
    wkv_scan_kernel<<<BB * HH * 16, 256>>>(Sb, decay, STb);
    wkv_y_kernel<<<BB * HH * NCK, 256, WKV_Y_SMEM>>>(rb, kb, vb, STb, decay, faaaa, yb);

    gn_mul_kernel<<<MTOT, 256>>>(yb, gnw, gnb, gb, ygb);
    gemm_hf_kernel<<<g1024, 256, GEMM_SMEM>>>(ygb, WoR, x1, nullptr, 1024, 1024, 4, x, nullptr); // + residual

    // ---- channel mix ----
    ln_mix_kernel<2><<<MTOT, 256>>>(x1, ln2w, ln2b, cmaak, cmaar, nullptr, nullptr,
                                    xk2, xr2, nullptr, nullptr);
    gemm_hf_kernel<<<g3072, 256, GEMM_SMEM>>>(xk2, WckR, nullptr, hb, 3072, 1024, 2, nullptr, nullptr); // relu^2 -> fp16
    gemm_hf_kernel<<<g1024, 256, GEMM_SMEM>>>(hb, WcvR, hv, nullptr, 1024, 3072, 0, nullptr, nullptr);
    gemm_hf_kernel<<<g1024, 256, GEMM_SMEM>>>(xr2, WcrR, out, nullptr, 1024, 1024, 3, hv, x1); // sigmoid*hv + x1
}

// round 12
// speedup vs baseline: 1.4147x; 1.1826x over previous
#include <cuda_runtime.h>
#include <cuda_fp16.h>
#include <math.h>
#include <stdint.h>

// ---------------- problem constants ----------------
#define BB 4
#define TT 4096
#define CC 1024
#define HH 16
#define NHD 64
#define QQ 256
#define NCK 16
#define MTOT (BB*TT)          // 16384
#define BTC (BB*TT*CC)        // 16777216
#define EPS_LN 1e-5f
#define EPS_GN (1e-5f*64.0f)

// ---------------- scratch ----------------
#define SCR_TOTAL (19ull*BTC + 8388608ull + 12582912ull)
__device__ float g_scratch[SCR_TOTAL];

#define OFF_XK   (1ull*BTC)      // fp16
#define OFF_XV   (2ull*BTC)
#define OFF_XR   (3ull*BTC)
#define OFF_XG   (4ull*BTC)
#define OFF_R    (5ull*BTC)      // fp16
#define OFF_K    (6ull*BTC)      // fp16
#define OFF_V    (7ull*BTC)      // fp16
#define OFF_G    (8ull*BTC)      // fp16
#define OFF_Y    (9ull*BTC)      // fp32
#define OFF_YG   (10ull*BTC)     // fp16
#define OFF_X1   (11ull*BTC)     // fp32
#define OFF_XK2  (13ull*BTC)     // fp16
#define OFF_XR2  (14ull*BTC)     // fp16
#define OFF_HV   (15ull*BTC)     // fp32
#define OFF_H    (16ull*BTC)     // fp16 [16384,3072]
#define OFF_S    (19ull*BTC)
#define OFF_ST   (19ull*BTC + 4194304ull)
#define OFF_WT   (19ull*BTC + 8388608ull)
#define OFF_WR_R  (OFF_WT + 0ull)
#define OFF_WK_R  (OFF_WT + 1048576ull)
#define OFF_WV_R  (OFF_WT + 2097152ull)
#define OFF_WG_R  (OFF_WT + 3145728ull)
#define OFF_WO_R  (OFF_WT + 4194304ull)
#define OFF_WCR_R (OFF_WT + 5242880ull)
#define OFF_WCK_R (OFF_WT + 6291456ull)
#define OFF_WCV_R (OFF_WT + 9437184ull)

// ---------------- helpers ----------------
__device__ __forceinline__ uint32_t smem_u32(const void* p) {
    uint32_t a;
    asm("{ .reg .u64 t; cvta.to.shared.u64 t, %1; cvt.u32.u64 %0, t; }" : "=r"(a) : "l"(p));
    return a;
}

__device__ __forceinline__ uint32_t pack_f16(float a, float b) {
    __half2 h = __floats2half2_rn(a, b);
    return *(uint32_t*)&h;
}

__device__ __forceinline__ float2 h2f(uint32_t h) {
    __half2 v = *(__half2*)&h;
    return __half22float2(v);
}

__device__ __forceinline__ void cp16(uint32_t dst, const void* src) {
    asm volatile("cp.async.cg.shared.global [%0], [%1], 16;" :: "r"(dst), "l"(src) : "memory");
}
#define CP_COMMIT() asm volatile("cp.async.commit_group;" ::: "memory")
#define CP_WAIT_1() asm volatile("cp.async.wait_group 1;" ::: "memory")

// ---------------- all-weight fp32 -> fp16 (single launch) ----------------
struct CvtArgs {
    const float* src[8];
    __half* dst[8];
    int end4[8];
};
__global__ __launch_bounds__(256) void cvt_all_kernel(CvtArgs a)
{
    int i = blockIdx.x * 256 + threadIdx.x;
    int seg = 0;
    #pragma unroll
    for (int s = 0; s < 7; s++) seg += (i >= a.end4[s]) ? 1 : 0;
    int base = (seg == 0) ? 0 : a.end4[seg - 1];
    int li = i - base;
    float4 v = ((const float4*)a.src[seg])[li];
    uint2 o;
    o.x = pack_f16(v.x, v.y);
    o.y = pack_f16(v.z, v.w);
    ((uint2*)a.dst[seg])[li] = o;
}

// ---------------- fused LayerNorm + time-shift mix (fp16 outputs) ----------------
template<int NOUT>
__global__ __launch_bounds__(256) void ln_mix_kernel(const float* __restrict__ x,
                                                     const float* __restrict__ w,
                                                     const float* __restrict__ b,
                                                     const float* __restrict__ m0,
                                                     const float* __restrict__ m1,
                                                     const float* __restrict__ m2,
                                                     const float* __restrict__ m3,
                                                     __half* __restrict__ o0,
                                                     __half* __restrict__ o1,
                                                     __half* __restrict__ o2,
                                                     __half* __restrict__ o3)
{
    int row = blockIdx.x;
    int t = row % TT;
    int tid = threadIdx.x;
    size_t off = (size_t)row * CC;
    float4 cur = ((const float4*)(x + off))[tid];
    float4 prv = make_float4(0.f, 0.f, 0.f, 0.f);
    if (t > 0) prv = ((const float4*)(x + off - CC))[tid];

    float s0 = cur.x + cur.y + cur.z + cur.w;
    float q0 = cur.x*cur.x + cur.y*cur.y + cur.z*cur.z + cur.w*cur.w;
    float s1 = prv.x + prv.y + prv.z + prv.w;
    float q1 = prv.x*prv.x + prv.y*prv.y + prv.z*prv.z + prv.w*prv.w;
    #pragma unroll
    for (int o = 16; o >= 1; o >>= 1) {
        s0 += __shfl_xor_sync(0xffffffffu, s0, o);
        q0 += __shfl_xor_sync(0xffffffffu, q0, o);
        s1 += __shfl_xor_sync(0xffffffffu, s1, o);
        q1 += __shfl_xor_sync(0xffffffffu, q1, o);
    }
    __shared__ float red[4][8];
    int wid = tid >> 5, lane = tid & 31;
    if (lane == 0) { red[0][wid] = s0; red[1][wid] = q0; red[2][wid] = s1; red[3][wid] = q1; }
    __syncthreads();
    if (tid == 0) {
        float a0 = 0, a1 = 0, a2 = 0, a3 = 0;
        #pragma unroll
        for (int i = 0; i < 8; i++) { a0 += red[0][i]; a1 += red[1][i]; a2 += red[2][i]; a3 += red[3][i]; }
        red[0][0] = a0; red[1][0] = a1; red[2][0] = a2; red[3][0] = a3;
    }
    __syncthreads();
    float mu0 = red[0][0] * (1.0f / CC);
    float rs0 = rsqrtf(red[1][0] * (1.0f / CC) - mu0 * mu0 + EPS_LN);
    float mu1 = red[2][0] * (1.0f / CC);
    float rs1 = rsqrtf(red[3][0] * (1.0f / CC) - mu1 * mu1 + EPS_LN);

    float4 ww = ((const float4*)w)[tid];
    float4 bb = ((const float4*)b)[tid];
    float4 lc, lp;
    lc.x = (cur.x - mu0) * rs0 * ww.x + bb.x;
    lc.y = (cur.y - mu0) * rs0 * ww.y + bb.y;
    lc.z = (cur.z - mu0) * rs0 * ww.z + bb.z;
    lc.w = (cur.w - mu0) * rs0 * ww.w + bb.w;
    if (t > 0) {
        lp.x = (prv.x - mu1) * rs1 * ww.x + bb.x;
        lp.y = (prv.y - mu1) * rs1 * ww.y + bb.y;
        lp.z = (prv.z - mu1) * rs1 * ww.z + bb.z;
        lp.w = (prv.w - mu1) * rs1 * ww.w + bb.w;
    } else {
        lp = make_float4(0.f, 0.f, 0.f, 0.f);
    }
    float4 xx = make_float4(lp.x - lc.x, lp.y - lc.y, lp.z - lc.z, lp.w - lc.w);

    float4 a;
    uint2 o;
    a = ((const float4*)m0)[tid];
    o.x = pack_f16(lc.x + xx.x * a.x, lc.y + xx.y * a.y);
    o.y = pack_f16(lc.z + xx.z * a.z, lc.w + xx.w * a.w);
    ((uint2*)(o0 + off))[tid] = o;
    a = ((const float4*)m1)[tid];
    o.x = pack_f16(lc.x + xx.x * a.x, lc.y + xx.y * a.y);
    o.y = pack_f16(lc.z + xx.z * a.z, lc.w + xx.w * a.w);
    ((uint2*)(o1 + off))[tid] = o;
    if (NOUT == 4) {
        a = ((const float4*)m2)[tid];
        o.x = pack_f16(lc.x + xx.x * a.x, lc.y + xx.y * a.y);
        o.y = pack_f16(lc.z + xx.z * a.z, lc.w + xx.w * a.w);
        ((uint2*)(o2 + off))[tid] = o;
        a = ((const float4*)m3)[tid];
        o.x = pack_f16(lc.x + xx.x * a.x, lc.y + xx.y * a.y);
        o.y = pack_f16(lc.z + xx.z * a.z, lc.w + xx.w * a.w);
        ((uint2*)(o3 + off))[tid] = o;
    }
}

// ---------------- fp16 tensor-core GEMM core ----------------
#define STG_WORDS 9216
#define GEMM_SMEM (2 * STG_WORDS * 4)

__device__ __forceinline__ void mma_f16(float c[4],
                                        const uint32_t a[4],
                                        const uint32_t b[2])
{
    asm volatile(
        "mma.sync.aligned.m16n8k16.row.col.f32.f16.f16.f32 "
        "{%0,%1,%2,%3}, {%4,%5,%6,%7}, {%8,%9}, {%0,%1,%2,%3};\n"
        : "+f"(c[0]), "+f"(c[1]), "+f"(c[2]), "+f"(c[3])
        : "r"(a[0]), "r"(a[1]), "r"(a[2]), "r"(a[3]),
          "r"(b[0]), "r"(b[1]));
}

#define LDMATRIX_X4(r0, r1, r2, r3, addr) \
    asm volatile("ldmatrix.sync.aligned.m8n8.x4.shared.b16 {%0,%1,%2,%3}, [%4];" \
        : "=r"(r0), "=r"(r1), "=r"(r2), "=r"(r3) : "r"(addr))

__device__ __forceinline__ void gemm_mainloop(const __half* __restrict__ A,
                                              const __half* __restrict__ W,
                                              int K, int m0, int n0,
                                              uint32_t* smw, int tid,
                                              float acc[4][4][4])
{
    int lane = tid & 31;
    int j  = tid & 7;
    int r0 = tid >> 3;
    const __half* pA = A + ((size_t)m0 + r0) * K + j * 8;
    const __half* pW = W + ((size_t)n0 + r0) * K + j * 8;
    uint32_t smb = smem_u32(smw);
    uint32_t dstA = smb + (uint32_t)(r0 * 36 + j * 4) * 4u;
    uint32_t dstW = dstA + 4608u * 4u;
    int wid = tid >> 5;
    int wm = wid >> 2, wn = wid & 3;

    uint32_t aAddr[4], bAddr[2];
    #pragma unroll
    for (int mi = 0; mi < 4; mi++)
        aAddr[mi] = smb + (uint32_t)((wm * 64 + mi * 16 + (lane & 15)) * 36) * 4u
                        + (uint32_t)(lane >> 4) * 16u;
    #pragma unroll
    for (int p = 0; p < 2; p++)
        bAddr[p] = smb + 4608u * 4u
                 + (uint32_t)((wn * 32 + (p * 2 + (lane >> 4)) * 8 + (lane & 7)) * 36) * 4u
                 + (uint32_t)((lane >> 3) & 1) * 16u;

    int NC = K >> 6;

    #pragma unroll
    for (int s = 0; s < 2; s++) {
        uint32_t so = (uint32_t)(s * STG_WORDS) * 4u;
        int kf = s * 64;
        #pragma unroll
        for (int i = 0; i < 4; i++) {
            cp16(dstA + so + (uint32_t)(i * 32 * 36) * 4u, pA + (size_t)(i * 32) * K + kf);
            cp16(dstW + so + (uint32_t)(i * 32 * 36) * 4u, pW + (size_t)(i * 32) * K + kf);
        }
        CP_COMMIT();
    }

    for (int t = 0; t < NC; t++) {
        CP_WAIT_1();
        __syncthreads();
        uint32_t so = (uint32_t)((t & 1) * STG_WORDS) * 4u;

        #pragma unroll
        for (int kk = 0; kk < 4; kk++) {
            uint32_t ko = so + (uint32_t)kk * 32u;
            uint32_t af[4][4];
            uint32_t bf[4][2];
            #pragma unroll
            for (int mi = 0; mi < 4; mi++)
                LDMATRIX_X4(af[mi][0], af[mi][1], af[mi][2], af[mi][3], aAddr[mi] + ko);
            #pragma unroll
            for (int p = 0; p < 2; p++)
                LDMATRIX_X4(bf[2*p][0], bf[2*p][1], bf[2*p+1][0], bf[2*p+1][1], bAddr[p] + ko);
            #pragma unroll
            for (int mi = 0; mi < 4; mi++)
                #pragma unroll
                for (int ni = 0; ni < 4; ni++)
                    mma_f16(acc[mi][ni], af[mi], bf[ni]);
        }
        __syncthreads();

        int lc = t + 2;
        if (lc < NC) {
            uint32_t so2 = (uint32_t)((t & 1) * STG_WORDS) * 4u;
            int kf = lc * 64;
            #pragma unroll
            for (int i = 0; i < 4; i++) {
                cp16(dstA + so2 + (uint32_t)(i * 32 * 36) * 4u, pA + (size_t)(i * 32) * K + kf);
                cp16(dstW + so2 + (uint32_t)(i * 32 * 36) * 4u, pW + (size_t)(i * 32) * K + kf);
            }
        }
        CP_COMMIT();
    }
}

__device__ __forceinline__ float gemm_epi(float vv, int epi, const float* aux1,
                                          const float* aux2, size_t o)
{
    if (epi == 1) {
        vv = vv / (1.f + expf(-vv));
    } else if (epi == 3) {
        vv = 1.f / (1.f + expf(-vv));
        vv = vv * aux1[o] + aux2[o];
    } else if (epi == 4) {
        vv = vv + aux1[o];
    }
    return vv;
}

__global__ void __launch_bounds__(256, 2)
gemm_hf_kernel(const __half* __restrict__ A, const __half* __restrict__ W,
               float* __restrict__ Co, __half* __restrict__ Coh,
               int Nn, int K, int epi,
               const float* __restrict__ aux1, const float* __restrict__ aux2)
{
    extern __shared__ uint32_t smw[];
    int tid = threadIdx.x;
    int n0 = blockIdx.x * 128;
    int m0 = blockIdx.y * 128;
    int wid = tid >> 5, lane = tid & 31;
    int wm = wid >> 2, wn = wid & 3;
    int gid = lane >> 2, tg = lane & 3;

    float acc[4][4][4];
    #pragma unroll
    for (int mi = 0; mi < 4; mi++)
        #pragma unroll
        for (int ni = 0; ni < 4; ni++)
            #pragma unroll
            for (int e = 0; e < 4; e++) acc[mi][ni][e] = 0.f;

    gemm_mainloop(A, W, K, m0, n0, smw, tid, acc);

    #pragma unroll
    for (int mi = 0; mi < 4; mi++) {
        int row0 = m0 + wm * 64 + mi * 16 + gid;
        #pragma unroll
        for (int ni = 0; ni < 4; ni++) {
            int col0 = n0 + wn * 32 + ni * 8 + tg * 2;
            size_t o0 = (size_t)row0 * Nn + col0;
            size_t o1 = (size_t)(row0 + 8) * Nn + col0;
            if (epi == 2) {
                float a0 = fmaxf(acc[mi][ni][0], 0.f); a0 *= a0;
                float a1 = fmaxf(acc[mi][ni][1], 0.f); a1 *= a1;
                float a2 = fmaxf(acc[mi][ni][2], 0.f); a2 *= a2;
                float a3 = fmaxf(acc[mi][ni][3], 0.f); a3 *= a3;
                *(uint32_t*)(Coh + o0) = pack_f16(a0, a1);
                *(uint32_t*)(Coh + o1) = pack_f16(a2, a3);
            } else {
                float2 v0, v1;
                v0.x = gemm_epi(acc[mi][ni][0], epi, aux1, aux2, o0);
                v0.y = gemm_epi(acc[mi][ni][1], epi, aux1, aux2, o0 + 1);
                v1.x = gemm_epi(acc[mi][ni][2], epi, aux1, aux2, o1);
                v1.y = gemm_epi(acc[mi][ni][3], epi, aux1, aux2, o1 + 1);
                *(float2*)(Co + o0) = v0;
                *(float2*)(Co + o1) = v1;
            }
        }
    }
}

// merged 4-GEMM kernel for tmix
struct Gemm4Args {
    const __half* A[4];
    const __half* W[4];
    __half* O[4];
    int silu[4];
};
__global__ void __launch_bounds__(256, 2)
gemm_hf4_kernel(Gemm4Args args)
{
    extern __shared__ uint32_t smw[];
    int z = blockIdx.z;
    const __half* A = args.A[z];
    const __half* W = args.W[z];
    __half* O = args.O[z];
    int silu = args.silu[z];

    int tid = threadIdx.x;
    int n0 = blockIdx.x * 128;
    int m0 = blockIdx.y * 128;
    int wid = tid >> 5, lane = tid & 31;
    int wm = wid >> 2, wn = wid & 3;
    int gid = lane >> 2, tg = lane & 3;

    float acc[4][4][4];
    #pragma unroll
    for (int mi = 0; mi < 4; mi++)
        #pragma unroll
        for (int ni = 0; ni < 4; ni++)
            #pragma unroll
            for (int e = 0; e < 4; e++) acc[mi][ni][e] = 0.f;

    gemm_mainloop(A, W, 1024, m0, n0, smw, tid, acc);

    #pragma unroll
    for (int mi = 0; mi < 4; mi++) {
        int row0 = m0 + wm * 64 + mi * 16 + gid;
        #pragma unroll
        for (int ni = 0; ni < 4; ni++) {
            int col0 = n0 + wn * 32 + ni * 8 + tg * 2;
            size_t o0 = (size_t)row0 * 1024 + col0;
            size_t o1 = (size_t)(row0 + 8) * 1024 + col0;
            float a0 = acc[mi][ni][0], a1 = acc[mi][ni][1];
            float a2 = acc[mi][ni][2], a3 = acc[mi][ni][3];
            if (silu) {
                a0 = a0 / (1.f + expf(-a0));
                a1 = a1 / (1.f + expf(-a1));
                a2 = a2 / (1.f + expf(-a2));
                a3 = a3 / (1.f + expf(-a3));
            }
            *(uint32_t*)(O + o0) = pack_f16(a0, a1);
            *(uint32_t*)(O + o1) = pack_f16(a2, a3);
        }
    }
}

// ---------------- WKV: per-chunk state contribution S = (k*wk) @ v ----------------
// 4x4 register tile per thread: n0 = 4*(tid>>4), m0 = 4*(tid&15).
// Per qq: 2 LDS.128 (8 words) feed 16 FMA — 2.1x less smem traffic than 1x16 mapping.
__global__ __launch_bounds__(256) void wkv_s_kernel(const __half* __restrict__ k,
                                                    const __half* __restrict__ v,
                                                    const float* __restrict__ decay,
                                                    float* __restrict__ S)
{
    int blk = blockIdx.x;
    int c = blk % NCK;
    int h = (blk / NCK) % HH;
    int b = blk / (NCK * HH);
    __shared__ float ksm[64][64];
    __shared__ float vsm[64][64];
    __shared__ float wpow[256];
    int tid = threadIdx.x;
    float ew = expf(decay[h]);
    wpow[tid] = expf(-ew * (float)tid);
    int n0 = (tid >> 4) * 4;
    int m0 = (tid & 15) * 4;
    float acc[4][4];
    #pragma unroll
    for (int i = 0; i < 4; i++)
        #pragma unroll
        for (int jj = 0; jj < 4; jj++) acc[i][jj] = 0.f;

    size_t base = ((size_t)b * TT + (size_t)c * QQ) * CC + (size_t)h * NHD;

    for (int qc = 0; qc < 4; qc++) {
        __syncthreads();
        for (int l = tid; l < 64 * 16; l += 256) {
            int qq = l >> 4;
            int f  = (l & 15) * 4;
            uint2 kk = *(const uint2*)(k + base + (size_t)(qc * 64 + qq) * CC + f);
            uint2 vv = *(const uint2*)(v + base + (size_t)(qc * 64 + qq) * CC + f);
            float2 ka = h2f(kk.x), kb2 = h2f(kk.y);
            float2 va = h2f(vv.x), vb2 = h2f(vv.y);
            ksm[qq][f] = ka.x; ksm[qq][f+1] = ka.y; ksm[qq][f+2] = kb2.x; ksm[qq][f+3] = kb2.y;
            vsm[qq][f] = va.x; vsm[qq][f+1] = va.y; vsm[qq][f+2] = vb2.x; vsm[qq][f+3] = vb2.y;
        }
        __syncthreads();
        #pragma unroll 4
        for (int qq = 0; qq < 64; qq++) {
            float wq = wpow[255 - (qc * 64 + qq)];
            float4 kk = *(const float4*)&ksm[qq][n0];
            float4 vv = *(const float4*)&vsm[qq][m0];
            float k0 = kk.x * wq, k1 = kk.y * wq, k2 = kk.z * wq, k3 = kk.w * wq;
            acc[0][0] += k0 * vv.x; acc[0][1] += k0 * vv.y; acc[0][2] += k0 * vv.z; acc[0][3] += k0 * vv.w;
            acc[1][0] += k1 * vv.x; acc[1][1] += k1 * vv.y; acc[1][2] += k1 * vv.z; acc[1][3] += k1 * vv.w;
            acc[2][0] += k2 * vv.x; acc[2][1] += k2 * vv.y; acc[2][2] += k2 * vv.z; acc[2][3] += k2 * vv.w;
            acc[3][0] += k3 * vv.x; acc[3][1] += k3 * vv.y; acc[3][2] += k3 * vv.z; acc[3][3] += k3 * vv.w;
        }
    }
    float* Sp = S + (size_t)blk * 4096;
    #pragma unroll
    for (int i = 0; i < 4; i++) {
        float4 o4 = make_float4(acc[i][0], acc[i][1], acc[i][2], acc[i][3]);
        *(float4*)(Sp + (n0 + i) * 64 + m0) = o4;
    }
}

// ---------------- WKV: inter-chunk prefix scan (wide grid) ----------------
__global__ __launch_bounds__(256) void wkv_scan_kernel(const float* __restrict__ S,
                                                       const float* __restrict__ decay,
                                                       float* __restrict__ ST)
{
    int bh = blockIdx.x >> 4;
    int part = blockIdx.x & 15;
    int h = bh % HH;
    float ws = expf(-expf(decay[h]) * 256.0f);
    int e = part * 256 + threadIdx.x;
    size_t b0 = (size_t)bh * NCK * 4096;
    float st = 0.f;
    #pragma unroll
    for (int c = 0; c < NCK; c++) {
        ST[b0 + (size_t)c * 4096 + e] = st;
        st = ws * st + S[b0 + (size_t)c * 4096 + e];
    }
}

// ---------------- WKV: per-chunk output (sub-chunking L=64, fp16 in) ----------------
#define WKV_Y_SMEM ((16384 + 16384 + 16384 + 256) * 4)   // 197632 bytes
__global__ __launch_bounds__(256) void wkv_y_kernel(const __half* __restrict__ r,
                                                    const __half* __restrict__ k,
                                                    const __half* __restrict__ v,
                                                    const float* __restrict__ ST,
                                                    const float* __restrict__ decay,
                                                    const float* __restrict__ faaaa,
                                                    float* __restrict__ y)
{
    extern __shared__ float sm[];
    float* ksm  = sm;
    float* vsm  = sm + 16384;
    float* sst  = sm + 32768;
    float* wpow = sm + 49152;

    int blk = blockIdx.x;
    int c = blk % NCK;
    int h = (blk / NCK) % HH;
    int b = blk / (NCK * HH);
    int tid = threadIdx.x;

    float ew = expf(decay[h]);
    float u  = faaaa[h];
    wpow[tid] = expf(-ew * (float)tid);

    size_t base = ((size_t)b * TT + (size_t)c * QQ) * CC + (size_t)h * NHD;

    for (int l = tid; l < 256 * 16; l += 256) {
        int qq = l >> 4;
        int f  = (l & 15) * 4;
        uint2 kk = *(const uint2*)(k + base + (size_t)qq * CC + f);
        uint2 vv = *(const uint2*)(v + base + (size_t)qq * CC + f);
        float2 ka = h2f(kk.x), kb2 = h2f(kk.y);
        float2 va = h2f(vv.x), vb2 = h2f(vv.y);
        ksm[qq * 64 + f] = ka.x; ksm[qq * 64 + f + 1] = ka.y;
        ksm[qq * 64 + f + 2] = kb2.x; ksm[qq * 64 + f + 3] = kb2.y;
        vsm[qq * 64 + f] = va.x; vsm[qq * 64 + f + 1] = va.y;
        vsm[qq * 64 + f + 2] = vb2.x; vsm[qq * 64 + f + 3] = vb2.y;
    }
    size_t sbase = (size_t)blk * 4096;
    for (int l = tid; l < 1024; l += 256)
        *(float4*)&sst[l * 4] = *(const float4*)(ST + sbase + (size_t)l * 4);
    __syncthreads();

    // precompute sub-chunk states sst[1..3] with 4x4 register tiles
    {
        int n0 = (tid >> 4) * 4;
        int m0 = (tid & 15) * 4;
        float w64 = expf(-ew * 64.0f);
        float st_prev[4][4];
        #pragma unroll
        for (int i = 0; i < 4; i++) {
            float4 s4 = *(const float4*)&sst[(n0 + i) * 64 + m0];
            st_prev[i][0] = s4.x; st_prev[i][1] = s4.y; st_prev[i][2] = s4.z; st_prev[i][3] = s4.w;
        }
        #pragma unroll 1
        for (int s = 1; s < 4; s++) {
            float tmp[4][4];
            #pragma unroll
            for (int i = 0; i < 4; i++)
                #pragma unroll
                for (int jj = 0; jj < 4; jj++) tmp[i][jj] = w64 * st_prev[i][jj];
            int j0 = (s - 1) * 64;
            #pragma unroll 4
            for (int jl = 0; jl < 64; jl++) {
                float wq = wpow[63 - jl];
                float4 kk = *(const float4*)&ksm[(j0 + jl) * 64 + n0];
                float4 vv = *(const float4*)&vsm[(j0 + jl) * 64 + m0];
                float k0 = kk.x * wq, k1 = kk.y * wq, k2 = kk.z * wq, k3 = kk.w * wq;
                tmp[0][0] += k0 * vv.x; tmp[0][1] += k0 * vv.y; tmp[0][2] += k0 * vv.z; tmp[0][3] += k0 * vv.w;
                tmp[1][0] += k1 * vv.x; tmp[1][1] += k1 * vv.y; tmp[1][2] += k1 * vv.z; tmp[1][3] += k1 * vv.w;
                tmp[2][0] += k2 * vv.x; tmp[2][1] += k2 * vv.y; tmp[2][2] += k2 * vv.z; tmp[2][3] += k2 * vv.w;
                tmp[3][0] += k3 * vv.x; tmp[3][1] += k3 * vv.y; tmp[3][2] += k3 * vv.z; tmp[3][3] += k3 * vv.w;
            }
            #pragma unroll
            for (int i = 0; i < 4; i++) {
                float4 o4 = make_float4(tmp[i][0], tmp[i][1], tmp[i][2], tmp[i][3]);
                *(float4*)&sst[s * 4096 + (n0 + i) * 64 + m0] = o4;
                st_prev[i][0] = tmp[i][0]; st_prev[i][1] = tmp[i][1];
                st_prev[i][2] = tmp[i][2]; st_prev[i][3] = tmp[i][3];
            }
        }
    }
    __syncthreads();

    int q  = tid;
    int qs = q >> 6;
    int ql = q & 63;
    float rrow[64];
    {
        const uint4* rg = (const uint4*)(r + base + (size_t)q * CC);
        #pragma unroll
        for (int f = 0; f < 8; f++) {
            uint4 t4 = rg[f];
            float2 p0 = h2f(t4.x), p1 = h2f(t4.y), p2 = h2f(t4.z), p3 = h2f(t4.w);
            rrow[f * 8 + 0] = p0.x; rrow[f * 8 + 1] = p0.y;
            rrow[f * 8 + 2] = p1.x; rrow[f * 8 + 3] = p1.y;
            rrow[f * 8 + 4] = p2.x; rrow[f * 8 + 5] = p2.y;
            rrow[f * 8 + 6] = p3.x; rrow[f * 8 + 7] = p3.y;
        }
    }
    float acc[64];
    #pragma unroll
    for (int m = 0; m < 64; m++) acc[m] = 0.f;

    const float* stq = sst + qs * 4096;
    #pragma unroll 8
    for (int n = 0; n < 64; n++) {
        float rv = rrow[n];
        const float4* srow = (const float4*)&stq[n * 64];
        #pragma unroll
        for (int m4 = 0; m4 < 16; m4++) {
            float4 s4 = srow[m4];
            acc[m4 * 4 + 0] += rv * s4.x;
            acc[m4 * 4 + 1] += rv * s4.y;
            acc[m4 * 4 + 2] += rv * s4.z;
            acc[m4 * 4 + 3] += rv * s4.w;
        }
    }
    float wbq = wpow[ql];
    #pragma unroll
    for (int m = 0; m < 64; m++) acc[m] *= wbq;

    int j0 = qs * 64;
    int jend = ql | 31;
    for (int jl = 0; jl <= jend; jl++) {
        float a = 0.f;
        const float4* krow = (const float4*)&ksm[(j0 + jl) * 64];
        #pragma unroll
        for (int n4 = 0; n4 < 16; n4++) {
            float4 k4 = krow[n4];
            a += rrow[n4 * 4 + 0] * k4.x + rrow[n4 * 4 + 1] * k4.y
               + rrow[n4 * 4 + 2] * k4.z + rrow[n4 * 4 + 3] * k4.w;
        }
        float coef = (jl < ql) ? wpow[ql - jl - 1] : ((jl == ql) ? u : 0.0f);
        a *= coef;
        const float4* vrow = (const float4*)&vsm[(j0 + jl) * 64];
        #pragma unroll
        for (int m4 = 0; m4 < 16; m4++) {
            float4 v4 = vrow[m4];
            acc[m4 * 4 + 0] += a * v4.x;
            acc[m4 * 4 + 1] += a * v4.y;
            acc[m4 * 4 + 2] += a * v4.z;
            acc[m4 * 4 + 3] += a * v4.w;
        }
    }

    float* yo = y + base + (size_t)q * CC;
    #pragma unroll
    for (int m4 = 0; m4 < 16; m4++) {
        float4 o4 = make_float4(acc[m4 * 4 + 0], acc[m4 * 4 + 1], acc[m4 * 4 + 2], acc[m4 * 4 + 3]);
        *(float4*)(yo + m4 * 4) = o4;
    }
}

// ---------------- GroupNorm * g (fp16 g input, fp16 output) ----------------
__global__ __launch_bounds__(256) void gn_mul_kernel(const float* __restrict__ y,
                                                     const float* __restrict__ gnw,
                                                     const float* __restrict__ gnb,
                                                     const __half* __restrict__ g,
                                                     __half* __restrict__ yg)
{
    int row = blockIdx.x;
    int tid = threadIdx.x;
    size_t off = (size_t)row * CC;
    float4 v = ((const float4*)(y + off))[tid];
    float s  = v.x + v.y + v.z + v.w;
    float sq = v.x*v.x + v.y*v.y + v.z*v.z + v.w*v.w;
    #pragma unroll
    for (int o = 8; o >= 1; o >>= 1) {
        s  += __shfl_xor_sync(0xffffffffu, s,  o);
        sq += __shfl_xor_sync(0xffffffffu, sq, o);
    }
    float mu   = s * (1.0f / 64.0f);
    float var  = sq * (1.0f / 64.0f) - mu * mu;
    float rstd = rsqrtf(var + EPS_GN);
    float4 ww = ((const float4*)gnw)[tid];
    float4 bb = ((const float4*)gnb)[tid];
    uint2 gg2 = ((const uint2*)(g + off))[tid];
    float2 g0 = h2f(gg2.x), g1 = h2f(gg2.y);
    uint2 o4;
    o4.x = pack_f16(((v.x - mu) * rstd * ww.x + bb.x) * g0.x,
                    ((v.y - mu) * rstd * ww.y + bb.y) * g0.y);
    o4.y = pack_f16(((v.z - mu) * rstd * ww.z + bb.z) * g1.x,
                    ((v.w - mu) * rstd * ww.w + bb.w) * g1.y);
    ((uint2*)(yg + off))[tid] = o4;
}

// ---------------- host launcher ----------------
extern "C" void kernel_launch(void* const* d_in, const int* in_sizes, int n_in,
                              void* d_out, int out_size)
{
    const float* x      = (const float*)d_in[0];
    const float* ln1w   = (const float*)d_in[1];
    const float* ln1b   = (const float*)d_in[2];
    const float* maak   = (const float*)d_in[3];
    const float* maav   = (const float*)d_in[4];
    const float* maar   = (const float*)d_in[5];
    const float* maag   = (const float*)d_in[6];
    const float* decay  = (const float*)d_in[7];
    const float* faaaa  = (const float*)d_in[8];
    const float* Wr     = (const float*)d_in[9];
    const float* Wk     = (const float*)d_in[10];
    const float* Wv     = (const float*)d_in[11];
    const float* Wg     = (const float*)d_in[12];
    const float* Wo     = (const float*)d_in[13];
    const float* gnw    = (const float*)d_in[14];
    const float* gnb    = (const float*)d_in[15];
    const float* ln2w   = (const float*)d_in[16];
    const float* ln2b   = (const float*)d_in[17];
    const float* cmaak  = (const float*)d_in[18];
    const float* cmaar  = (const float*)d_in[19];
    const float* Wck    = (const float*)d_in[20];
    const float* Wcv    = (const float*)d_in[21];
    const float* Wcr    = (const float*)d_in[22];
    float* out = (float*)d_out;

    float* sc = nullptr;
    cudaGetSymbolAddress((void**)&sc, g_scratch);

    __half* xk   = (__half*)(sc + OFF_XK);
    __half* xv   = (__half*)(sc + OFF_XV);
    __half* xr   = (__half*)(sc + OFF_XR);
    __half* xg   = (__half*)(sc + OFF_XG);
    __half* rb   = (__half*)(sc + OFF_R);
    __half* kb   = (__half*)(sc + OFF_K);
    __half* vb   = (__half*)(sc + OFF_V);
    __half* gb   = (__half*)(sc + OFF_G);
    float* yb   = sc + OFF_Y;
    __half* ygb = (__half*)(sc + OFF_YG);
    float* x1   = sc + OFF_X1;
    __half* xk2 = (__half*)(sc + OFF_XK2);
    __half* xr2 = (__half*)(sc + OFF_XR2);
    float* hv   = sc + OFF_HV;
    __half* hb  = (__half*)(sc + OFF_H);
    float* Sb   = sc + OFF_S;
    float* STb  = sc + OFF_ST;
    __half* WrR  = (__half*)(sc + OFF_WR_R);
    __half* WkR  = (__half*)(sc + OFF_WK_R);
    __half* WvR  = (__half*)(sc + OFF_WV_R);
    __half* WgR  = (__half*)(sc + OFF_WG_R);
    __half* WoR  = (__half*)(sc + OFF_WO_R);
    __half* WcrR = (__half*)(sc + OFF_WCR_R);
    __half* WckR = (__half*)(sc + OFF_WCK_R);
    __half* WcvR = (__half*)(sc + OFF_WCV_R);

    cudaFuncSetAttribute(wkv_y_kernel, cudaFuncAttributeMaxDynamicSharedMemorySize, WKV_Y_SMEM);
    cudaFuncSetAttribute(gemm_hf_kernel, cudaFuncAttributeMaxDynamicSharedMemorySize, GEMM_SMEM);
    cudaFuncSetAttribute(gemm_hf4_kernel, cudaFuncAttributeMaxDynamicSharedMemorySize, GEMM_SMEM);

    dim3 g1024(1024 / 128, MTOT / 128);
    dim3 g1024z4(1024 / 128, MTOT / 128, 4);
    dim3 g3072(3072 / 128, MTOT / 128);

    // ---- weight conversion: single launch ----
    {
        CvtArgs ca;
        const float* srcs[8] = {Wr, Wk, Wv, Wg, Wo, Wcr, Wck, Wcv};
        __half* dsts[8] = {WrR, WkR, WvR, WgR, WoR, WcrR, WckR, WcvR};
        int sz4[8] = {262144, 262144, 262144, 262144, 262144, 262144, 786432, 786432};
        int acc4 = 0;
        for (int i = 0; i < 8; i++) { ca.src[i] = srcs[i]; ca.dst[i] = dsts[i]; acc4 += sz4[i]; ca.end4[i] = acc4; }
        cvt_all_kernel<<<acc4 / 256, 256>>>(ca);
    }

    // ---- time mix ----
    ln_mix_kernel<4><<<MTOT, 256>>>(x, ln1w, ln1b, maak, maav, maar, maag, xk, xv, xr, xg);
    {
        Gemm4Args ga;
        ga.A[0] = xr; ga.W[0] = WrR; ga.O[0] = rb; ga.silu[0] = 0;
        ga.A[1] = xk; ga.W[1] = WkR; ga.O[1] = kb; ga.silu[1] = 0;
        ga.A[2] = xv; ga.W[2] = WvR; ga.O[2] = vb; ga.silu[2] = 0;
        ga.A[3] = xg; ga.W[3] = WgR; ga.O[3] = gb; ga.silu[3] = 1;
        gemm_hf4_kernel<<<g1024z4, 256, GEMM_SMEM>>>(ga);
    }

    wkv_s_kernel<<<BB * HH * NCK, 256>>>(kb, vb, decay, Sb);
    wkv_scan_kernel<<<BB * HH * 16, 256>>>(Sb, decay, STb);
    wkv_y_kernel<<<BB * HH * NCK, 256, WKV_Y_SMEM>>>(rb, kb, vb, STb, decay, faaaa, yb);

    gn_mul_kernel<<<MTOT, 256>>>(yb, gnw, gnb, gb, ygb);
    gemm_hf_kernel<<<g1024, 256, GEMM_SMEM>>>(ygb, WoR, x1, nullptr, 1024, 1024, 4, x, nullptr); // + residual

    // ---- channel mix ----
    ln_mix_kernel<2><<<MTOT, 256>>>(x1, ln2w, ln2b, cmaak, cmaar, nullptr, nullptr,
                                    xk2, xr2, nullptr, nullptr);
    gemm_hf_kernel<<<g3072, 256, GEMM_SMEM>>>(xk2, WckR, nullptr, hb, 3072, 1024, 2, nullptr, nullptr); // relu^2
    gemm_hf_kernel<<<g1024, 256, GEMM_SMEM>>>(hb, WcvR, hv, nullptr, 1024, 3072, 0, nullptr, nullptr);
    gemm_hf_kernel<<<g1024, 256, GEMM_SMEM>>>(xr2, WcrR, out, nullptr, 1024, 1024, 3, hv, x1); // sigmoid*hv + x1
}

// round 13
// speedup vs baseline: 1.4243x; 1.0068x over previous
#include <cuda_runtime.h>
#include <cuda_fp16.h>
#include <math.h>
#include <stdint.h>

// ---------------- problem constants ----------------
#define BB 4
#define TT 4096
#define CC 1024
#define HH 16
#define NHD 64
#define QQ 256
#define NCK 16
#define MTOT (BB*TT)          // 16384
#define BTC (BB*TT*CC)        // 16777216
#define EPS_LN 1e-5f
#define EPS_GN (1e-5f*64.0f)

// ---------------- scratch ----------------
#define SCR_TOTAL (19ull*BTC + 8388608ull + 12582912ull + 12582912ull)
__device__ float g_scratch[SCR_TOTAL];

#define OFF_XK   (1ull*BTC)      // fp16
#define OFF_XV   (2ull*BTC)
#define OFF_XR   (3ull*BTC)
#define OFF_XG   (4ull*BTC)
#define OFF_R    (5ull*BTC)      // fp16
#define OFF_K    (6ull*BTC)      // fp16
#define OFF_V    (7ull*BTC)      // fp16
#define OFF_G    (8ull*BTC)      // fp16
#define OFF_Y    (9ull*BTC)      // fp32
#define OFF_YG   (10ull*BTC)     // fp16
#define OFF_X1   (11ull*BTC)     // fp32
#define OFF_XK2  (13ull*BTC)     // fp16
#define OFF_XR2  (14ull*BTC)     // fp16
#define OFF_HV   (15ull*BTC)     // fp32
#define OFF_H    (16ull*BTC)     // fp16 [16384,3072]
#define OFF_S    (19ull*BTC)
#define OFF_ST   (19ull*BTC + 4194304ull)
#define OFF_C    (19ull*BTC + 8388608ull)                 // 12582912 floats (3 sub-states per block)
#define OFF_WT   (19ull*BTC + 8388608ull + 12582912ull)
#define OFF_WR_R  (OFF_WT + 0ull)
#define OFF_WK_R  (OFF_WT + 1048576ull)
#define OFF_WV_R  (OFF_WT + 2097152ull)
#define OFF_WG_R  (OFF_WT + 3145728ull)
#define OFF_WO_R  (OFF_WT + 4194304ull)
#define OFF_WCR_R (OFF_WT + 5242880ull)
#define OFF_WCK_R (OFF_WT + 6291456ull)
#define OFF_WCV_R (OFF_WT + 9437184ull)

// ---------------- helpers ----------------
__device__ __forceinline__ uint32_t smem_u32(const void* p) {
    uint32_t a;
    asm("{ .reg .u64 t; cvta.to.shared.u64 t, %1; cvt.u32.u64 %0, t; }" : "=r"(a) : "l"(p));
    return a;
}

__device__ __forceinline__ uint32_t pack_f16(float a, float b) {
    __half2 h = __floats2half2_rn(a, b);
    return *(uint32_t*)&h;
}

__device__ __forceinline__ float2 h2f(uint32_t h) {
    __half2 v = *(__half2*)&h;
    return __half22float2(v);
}

// ---- packed f32x2 math (Blackwell FFMA2) ----
__device__ __forceinline__ uint64_t bcast2(float s) {
    uint64_t r;
    asm("mov.b64 %0, {%1, %1};" : "=l"(r) : "r"(__float_as_uint(s)));
    return r;
}
__device__ __forceinline__ void fma2(uint64_t& d, uint64_t a, uint64_t b) {
    asm("fma.rn.f32x2 %0, %1, %2, %0;" : "+l"(d) : "l"(a), "l"(b));
}
__device__ __forceinline__ void fma2w(uint64_t& d, uint64_t w, uint64_t c) {
    asm("fma.rn.f32x2 %0, %0, %1, %2;" : "+l"(d) : "l"(w), "l"(c));   // d = d*w + c
}
__device__ __forceinline__ void mul2(uint64_t& d, uint64_t b) {
    asm("mul.rn.f32x2 %0, %0, %1;" : "+l"(d) : "l"(b));
}
__device__ __forceinline__ float2 unpk2(uint64_t v) {
    float lo, hi;
    asm("mov.b64 {%0, %1}, %2;" : "=f"(lo), "=f"(hi) : "l"(v));
    return make_float2(lo, hi);
}

__device__ __forceinline__ void cp16(uint32_t dst, const void* src) {
    asm volatile("cp.async.cg.shared.global [%0], [%1], 16;" :: "r"(dst), "l"(src) : "memory");
}
#define CP_COMMIT() asm volatile("cp.async.commit_group;" ::: "memory")
#define CP_WAIT_1() asm volatile("cp.async.wait_group 1;" ::: "memory")

// ---------------- all-weight fp32 -> fp16 (single launch) ----------------
struct CvtArgs {
    const float* src[8];
    __half* dst[8];
    int end4[8];
};
__global__ __launch_bounds__(256) void cvt_all_kernel(CvtArgs a)
{
    int i = blockIdx.x * 256 + threadIdx.x;
    int seg = 0;
    #pragma unroll
    for (int s = 0; s < 7; s++) seg += (i >= a.end4[s]) ? 1 : 0;
    int base = (seg == 0) ? 0 : a.end4[seg - 1];
    int li = i - base;
    float4 v = ((const float4*)a.src[seg])[li];
    uint2 o;
    o.x = pack_f16(v.x, v.y);
    o.y = pack_f16(v.z, v.w);
    ((uint2*)a.dst[seg])[li] = o;
}

// ---------------- fused LayerNorm + time-shift mix (fp16 outputs) ----------------
template<int NOUT>
__global__ __launch_bounds__(256) void ln_mix_kernel(const float* __restrict__ x,
                                                     const float* __restrict__ w,
                                                     const float* __restrict__ b,
                                                     const float* __restrict__ m0,
                                                     const float* __restrict__ m1,
                                                     const float* __restrict__ m2,
                                                     const float* __restrict__ m3,
                                                     __half* __restrict__ o0,
                                                     __half* __restrict__ o1,
                                                     __half* __restrict__ o2,
                                                     __half* __restrict__ o3)
{
    int row = blockIdx.x;
    int t = row % TT;
    int tid = threadIdx.x;
    size_t off = (size_t)row * CC;
    float4 cur = ((const float4*)(x + off))[tid];
    float4 prv = make_float4(0.f, 0.f, 0.f, 0.f);
    if (t > 0) prv = ((const float4*)(x + off - CC))[tid];

    float s0 = cur.x + cur.y + cur.z + cur.w;
    float q0 = cur.x*cur.x + cur.y*cur.y + cur.z*cur.z + cur.w*cur.w;
    float s1 = prv.x + prv.y + prv.z + prv.w;
    float q1 = prv.x*prv.x + prv.y*prv.y + prv.z*prv.z + prv.w*prv.w;
    #pragma unroll
    for (int o = 16; o >= 1; o >>= 1) {
        s0 += __shfl_xor_sync(0xffffffffu, s0, o);
        q0 += __shfl_xor_sync(0xffffffffu, q0, o);
        s1 += __shfl_xor_sync(0xffffffffu, s1, o);
        q1 += __shfl_xor_sync(0xffffffffu, q1, o);
    }
    __shared__ float red[4][8];
    int wid = tid >> 5, lane = tid & 31;
    if (lane == 0) { red[0][wid] = s0; red[1][wid] = q0; red[2][wid] = s1; red[3][wid] = q1; }
    __syncthreads();
    if (tid == 0) {
        float a0 = 0, a1 = 0, a2 = 0, a3 = 0;
        #pragma unroll
        for (int i = 0; i < 8; i++) { a0 += red[0][i]; a1 += red[1][i]; a2 += red[2][i]; a3 += red[3][i]; }
        red[0][0] = a0; red[1][0] = a1; red[2][0] = a2; red[3][0] = a3;
    }
    __syncthreads();
    float mu0 = red[0][0] * (1.0f / CC);
    float rs0 = rsqrtf(red[1][0] * (1.0f / CC) - mu0 * mu0 + EPS_LN);
    float mu1 = red[2][0] * (1.0f / CC);
    float rs1 = rsqrtf(red[3][0] * (1.0f / CC) - mu1 * mu1 + EPS_LN);

    float4 ww = ((const float4*)w)[tid];
    float4 bb = ((const float4*)b)[tid];
    float4 lc, lp;
    lc.x = (cur.x - mu0) * rs0 * ww.x + bb.x;
    lc.y = (cur.y - mu0) * rs0 * ww.y + bb.y;
    lc.z = (cur.z - mu0) * rs0 * ww.z + bb.z;
    lc.w = (cur.w - mu0) * rs0 * ww.w + bb.w;
    if (t > 0) {
        lp.x = (prv.x - mu1) * rs1 * ww.x + bb.x;
        lp.y = (prv.y - mu1) * rs1 * ww.y + bb.y;
        lp.z = (prv.z - mu1) * rs1 * ww.z + bb.z;
        lp.w = (prv.w - mu1) * rs1 * ww.w + bb.w;
    } else {
        lp = make_float4(0.f, 0.f, 0.f, 0.f);
    }
    float4 xx = make_float4(lp.x - lc.x, lp.y - lc.y, lp.z - lc.z, lp.w - lc.w);

    float4 a;
    uint2 o;
    a = ((const float4*)m0)[tid];
    o.x = pack_f16(lc.x + xx.x * a.x, lc.y + xx.y * a.y);
    o.y = pack_f16(lc.z + xx.z * a.z, lc.w + xx.w * a.w);
    ((uint2*)(o0 + off))[tid] = o;
    a = ((const float4*)m1)[tid];
    o.x = pack_f16(lc.x + xx.x * a.x, lc.y + xx.y * a.y);
    o.y = pack_f16(lc.z + xx.z * a.z, lc.w + xx.w * a.w);
    ((uint2*)(o1 + off))[tid] = o;
    if (NOUT == 4) {
        a = ((const float4*)m2)[tid];
        o.x = pack_f16(lc.x + xx.x * a.x, lc.y + xx.y * a.y);
        o.y = pack_f16(lc.z + xx.z * a.z, lc.w + xx.w * a.w);
        ((uint2*)(o2 + off))[tid] = o;
        a = ((const float4*)m3)[tid];
        o.x = pack_f16(lc.x + xx.x * a.x, lc.y + xx.y * a.y);
        o.y = pack_f16(lc.z + xx.z * a.z, lc.w + xx.w * a.w);
        ((uint2*)(o3 + off))[tid] = o;
    }
}

// ---------------- fp16 tensor-core GEMM core ----------------
#define STG_WORDS 9216
#define GEMM_SMEM (2 * STG_WORDS * 4)

__device__ __forceinline__ void mma_f16(float c[4],
                                        const uint32_t a[4],
                                        const uint32_t b[2])
{
    asm volatile(
        "mma.sync.aligned.m16n8k16.row.col.f32.f16.f16.f32 "
        "{%0,%1,%2,%3}, {%4,%5,%6,%7}, {%8,%9}, {%0,%1,%2,%3};\n"
        : "+f"(c[0]), "+f"(c[1]), "+f"(c[2]), "+f"(c[3])
        : "r"(a[0]), "r"(a[1]), "r"(a[2]), "r"(a[3]),
          "r"(b[0]), "r"(b[1]));
}

#define LDMATRIX_X4(r0, r1, r2, r3, addr) \
    asm volatile("ldmatrix.sync.aligned.m8n8.x4.shared.b16 {%0,%1,%2,%3}, [%4];" \
        : "=r"(r0), "=r"(r1), "=r"(r2), "=r"(r3) : "r"(addr))

__device__ __forceinline__ void gemm_mainloop(const __half* __restrict__ A,
                                              const __half* __restrict__ W,
                                              int K, int m0, int n0,
                                              uint32_t* smw, int tid,
                                              float acc[4][4][4])
{
    int lane = tid & 31;
    int j  = tid & 7;
    int r0 = tid >> 3;
    const __half* pA = A + ((size_t)m0 + r0) * K + j * 8;
    const __half* pW = W + ((size_t)n0 + r0) * K + j * 8;
    uint32_t smb = smem_u32(smw);
    uint32_t dstA = smb + (uint32_t)(r0 * 36 + j * 4) * 4u;
    uint32_t dstW = dstA + 4608u * 4u;
    int wid = tid >> 5;
    int wm = wid >> 2, wn = wid & 3;

    uint32_t aAddr[4], bAddr[2];
    #pragma unroll
    for (int mi = 0; mi < 4; mi++)
        aAddr[mi] = smb + (uint32_t)((wm * 64 + mi * 16 + (lane & 15)) * 36) * 4u
                        + (uint32_t)(lane >> 4) * 16u;
    #pragma unroll
    for (int p = 0; p < 2; p++)
        bAddr[p] = smb + 4608u * 4u
                 + (uint32_t)((wn * 32 + (p * 2 + (lane >> 4)) * 8 + (lane & 7)) * 36) * 4u
                 + (uint32_t)((lane >> 3) & 1) * 16u;

    int NC = K >> 6;

    #pragma unroll
    for (int s = 0; s < 2; s++) {
        uint32_t so = (uint32_t)(s * STG_WORDS) * 4u;
        int kf = s * 64;
        #pragma unroll
        for (int i = 0; i < 4; i++) {
            cp16(dstA + so + (uint32_t)(i * 32 * 36) * 4u, pA + (size_t)(i * 32) * K + kf);
            cp16(dstW + so + (uint32_t)(i * 32 * 36) * 4u, pW + (size_t)(i * 32) * K + kf);
        }
        CP_COMMIT();
    }

    for (int t = 0; t < NC; t++) {
        CP_WAIT_1();
        __syncthreads();
        uint32_t so = (uint32_t)((t & 1) * STG_WORDS) * 4u;

        #pragma unroll
        for (int kk = 0; kk < 4; kk++) {
            uint32_t ko = so + (uint32_t)kk * 32u;
            uint32_t af[4][4];
            uint32_t bf[4][2];
            #pragma unroll
            for (int mi = 0; mi < 4; mi++)
                LDMATRIX_X4(af[mi][0], af[mi][1], af[mi][2], af[mi][3], aAddr[mi] + ko);
            #pragma unroll
            for (int p = 0; p < 2; p++)
                LDMATRIX_X4(bf[2*p][0], bf[2*p][1], bf[2*p+1][0], bf[2*p+1][1], bAddr[p] + ko);
            #pragma unroll
            for (int mi = 0; mi < 4; mi++)
                #pragma unroll
                for (int ni = 0; ni < 4; ni++)
                    mma_f16(acc[mi][ni], af[mi], bf[ni]);
        }
        __syncthreads();

        int lc = t + 2;
        if (lc < NC) {
            uint32_t so2 = (uint32_t)((t & 1) * STG_WORDS) * 4u;
            int kf = lc * 64;
            #pragma unroll
            for (int i = 0; i < 4; i++) {
                cp16(dstA + so2 + (uint32_t)(i * 32 * 36) * 4u, pA + (size_t)(i * 32) * K + kf);
                cp16(dstW + so2 + (uint32_t)(i * 32 * 36) * 4u, pW + (size_t)(i * 32) * K + kf);
            }
        }
        CP_COMMIT();
    }
}

__device__ __forceinline__ float gemm_epi(float vv, int epi, const float* aux1,
                                          const float* aux2, size_t o)
{
    if (epi == 1) {
        vv = vv / (1.f + expf(-vv));
    } else if (epi == 3) {
        vv = 1.f / (1.f + expf(-vv));
        vv = vv * aux1[o] + aux2[o];
    } else if (epi == 4) {
        vv = vv + aux1[o];
    }
    return vv;
}

__global__ void __launch_bounds__(256, 2)
gemm_hf_kernel(const __half* __restrict__ A, const __half* __restrict__ W,
               float* __restrict__ Co, __half* __restrict__ Coh,
               int Nn, int K, int epi,
               const float* __restrict__ aux1, const float* __restrict__ aux2)
{
    extern __shared__ uint32_t smw[];
    int tid = threadIdx.x;
    int n0 = blockIdx.x * 128;
    int m0 = blockIdx.y * 128;
    int wid = tid >> 5, lane = tid & 31;
    int wm = wid >> 2, wn = wid & 3;
    int gid = lane >> 2, tg = lane & 3;

    float acc[4][4][4];
    #pragma unroll
    for (int mi = 0; mi < 4; mi++)
        #pragma unroll
        for (int ni = 0; ni < 4; ni++)
            #pragma unroll
            for (int e = 0; e < 4; e++) acc[mi][ni][e] = 0.f;

    gemm_mainloop(A, W, K, m0, n0, smw, tid, acc);

    #pragma unroll
    for (int mi = 0; mi < 4; mi++) {
        int row0 = m0 + wm * 64 + mi * 16 + gid;
        #pragma unroll
        for (int ni = 0; ni < 4; ni++) {
            int col0 = n0 + wn * 32 + ni * 8 + tg * 2;
            size_t o0 = (size_t)row0 * Nn + col0;
            size_t o1 = (size_t)(row0 + 8) * Nn + col0;
            if (epi == 2) {
                float a0 = fmaxf(acc[mi][ni][0], 0.f); a0 *= a0;
                float a1 = fmaxf(acc[mi][ni][1], 0.f); a1 *= a1;
                float a2 = fmaxf(acc[mi][ni][2], 0.f); a2 *= a2;
                float a3 = fmaxf(acc[mi][ni][3], 0.f); a3 *= a3;
                *(uint32_t*)(Coh + o0) = pack_f16(a0, a1);
                *(uint32_t*)(Coh + o1) = pack_f16(a2, a3);
            } else {
                float2 v0, v1;
                v0.x = gemm_epi(acc[mi][ni][0], epi, aux1, aux2, o0);
                v0.y = gemm_epi(acc[mi][ni][1], epi, aux1, aux2, o0 + 1);
                v1.x = gemm_epi(acc[mi][ni][2], epi, aux1, aux2, o1);
                v1.y = gemm_epi(acc[mi][ni][3], epi, aux1, aux2, o1 + 1);
                *(float2*)(Co + o0) = v0;
                *(float2*)(Co + o1) = v1;
            }
        }
    }
}

// merged 4-GEMM kernel for tmix
struct Gemm4Args {
    const __half* A[4];
    const __half* W[4];
    __half* O[4];
    int silu[4];
};
__global__ void __launch_bounds__(256, 2)
gemm_hf4_kernel(Gemm4Args args)
{
    extern __shared__ uint32_t smw[];
    int z = blockIdx.z;
    const __half* A = args.A[z];
    const __half* W = args.W[z];
    __half* O = args.O[z];
    int silu = args.silu[z];

    int tid = threadIdx.x;
    int n0 = blockIdx.x * 128;
    int m0 = blockIdx.y * 128;
    int wid = tid >> 5, lane = tid & 31;
    int wm = wid >> 2, wn = wid & 3;
    int gid = lane >> 2, tg = lane & 3;

    float acc[4][4][4];
    #pragma unroll
    for (int mi = 0; mi < 4; mi++)
        #pragma unroll
        for (int ni = 0; ni < 4; ni++)
            #pragma unroll
            for (int e = 0; e < 4; e++) acc[mi][ni][e] = 0.f;

    gemm_mainloop(A, W, 1024, m0, n0, smw, tid, acc);

    #pragma unroll
    for (int mi = 0; mi < 4; mi++) {
        int row0 = m0 + wm * 64 + mi * 16 + gid;
        #pragma unroll
        for (int ni = 0; ni < 4; ni++) {
            int col0 = n0 + wn * 32 + ni * 8 + tg * 2;
            size_t o0 = (size_t)row0 * 1024 + col0;
            size_t o1 = (size_t)(row0 + 8) * 1024 + col0;
            float a0 = acc[mi][ni][0], a1 = acc[mi][ni][1];
            float a2 = acc[mi][ni][2], a3 = acc[mi][ni][3];
            if (silu) {
                a0 = a0 / (1.f + expf(-a0));
                a1 = a1 / (1.f + expf(-a1));
                a2 = a2 / (1.f + expf(-a2));
                a3 = a3 / (1.f + expf(-a3));
            }
            *(uint32_t*)(O + o0) = pack_f16(a0, a1);
            *(uint32_t*)(O + o1) = pack_f16(a2, a3);
        }
    }
}

// ---------------- WKV: per-subchunk contributions + chunk state ----------------
// Computes C_s (sub-chunk contributions, s=0..2, local decay weights) and
// S = ((C0*w64 + C1)*w64 + C2)*w64 + C3 for the inter-chunk scan.
// 4x4 register tile per thread; FFMA2 packed math (exact fp32).
__global__ __launch_bounds__(256) void wkv_s_kernel(const __half* __restrict__ k,
                                                    const __half* __restrict__ v,
                                                    const float* __restrict__ decay,
                                                    float* __restrict__ S,
                                                    float* __restrict__ C)
{
    int blk = blockIdx.x;
    int c = blk % NCK;
    int h = (blk / NCK) % HH;
    int b = blk / (NCK * HH);
    __shared__ float ksm[64][64];
    __shared__ float vsm[64][64];
    __shared__ float wpow[128];
    int tid = threadIdx.x;
    float ew = expf(decay[h]);
    if (tid < 128) wpow[tid] = expf(-ew * (float)tid);
    int n0 = (tid >> 4) * 4;
    int m0 = (tid & 15) * 4;
    uint64_t Sacc[4][2];
    #pragma unroll
    for (int i = 0; i < 4; i++) { Sacc[i][0] = 0; Sacc[i][1] = 0; }

    size_t base = ((size_t)b * TT + (size_t)c * QQ) * CC + (size_t)h * NHD;
    float w64 = 0.f;

    for (int qc = 0; qc < 4; qc++) {
        __syncthreads();
        for (int l = tid; l < 64 * 16; l += 256) {
            int qq = l >> 4;
            int f  = (l & 15) * 4;
            uint2 kk = *(const uint2*)(k + base + (size_t)(qc * 64 + qq) * CC + f);
            uint2 vv = *(const uint2*)(v + base + (size_t)(qc * 64 + qq) * CC + f);
            float2 ka = h2f(kk.x), kb2 = h2f(kk.y);
            float2 va = h2f(vv.x), vb2 = h2f(vv.y);
            ksm[qq][f] = ka.x; ksm[qq][f+1] = ka.y; ksm[qq][f+2] = kb2.x; ksm[qq][f+3] = kb2.y;
            vsm[qq][f] = va.x; vsm[qq][f+1] = va.y; vsm[qq][f+2] = vb2.x; vsm[qq][f+3] = vb2.y;
        }
        __syncthreads();
        if (qc == 0) w64 = wpow[64];

        uint64_t acc2[4][2];
        #pragma unroll
        for (int i = 0; i < 4; i++) { acc2[i][0] = 0; acc2[i][1] = 0; }

        #pragma unroll 4
        for (int jl = 0; jl < 64; jl++) {
            float wq = wpow[63 - jl];
            float4 kk = *(const float4*)&ksm[jl][n0];
            ulonglong2 vp = *(const ulonglong2*)&vsm[jl][m0];
            uint64_t kb0 = bcast2(kk.x * wq);
            uint64_t kb1 = bcast2(kk.y * wq);
            uint64_t kb2 = bcast2(kk.z * wq);
            uint64_t kb3 = bcast2(kk.w * wq);
            fma2(acc2[0][0], kb0, vp.x); fma2(acc2[0][1], kb0, vp.y);
            fma2(acc2[1][0], kb1, vp.x); fma2(acc2[1][1], kb1, vp.y);
            fma2(acc2[2][0], kb2, vp.x); fma2(acc2[2][1], kb2, vp.y);
            fma2(acc2[3][0], kb3, vp.x); fma2(acc2[3][1], kb3, vp.y);
        }

        uint64_t wb = bcast2(w64);
        #pragma unroll
        for (int i = 0; i < 4; i++) {
            fma2w(Sacc[i][0], wb, acc2[i][0]);
            fma2w(Sacc[i][1], wb, acc2[i][1]);
        }

        if (qc < 3) {
            float* Cp = C + (size_t)blk * 12288 + (size_t)qc * 4096;
            #pragma unroll
            for (int i = 0; i < 4; i++) {
                float2 p0 = unpk2(acc2[i][0]);
                float2 p1 = unpk2(acc2[i][1]);
                *(float4*)(Cp + (n0 + i) * 64 + m0) = make_float4(p0.x, p0.y, p1.x, p1.y);
            }
        }
    }

    float* Sp = S + (size_t)blk * 4096;
    #pragma unroll
    for (int i = 0; i < 4; i++) {
        float2 p0 = unpk2(Sacc[i][0]);
        float2 p1 = unpk2(Sacc[i][1]);
        *(float4*)(Sp + (n0 + i) * 64 + m0) = make_float4(p0.x, p0.y, p1.x, p1.y);
    }
}

// ---------------- WKV: inter-chunk prefix scan (wide grid) ----------------
__global__ __launch_bounds__(256) void wkv_scan_kernel(const float* __restrict__ S,
                                                       const float* __restrict__ decay,
                                                       float* __restrict__ ST)
{
    int bh = blockIdx.x >> 4;
    int part = blockIdx.x & 15;
    int h = bh % HH;
    float ws = expf(-expf(decay[h]) * 256.0f);
    int e = part * 256 + threadIdx.x;
    size_t b0 = (size_t)bh * NCK * 4096;
    float st = 0.f;
    #pragma unroll
    for (int c = 0; c < NCK; c++) {
        ST[b0 + (size_t)c * 4096 + e] = st;
        st = ws * st + S[b0 + (size_t)c * 4096 + e];
    }
}

// ---------------- WKV: per-chunk output (sub-chunking L=64, FFMA2, C-precomputed) ----------------
#define WKV_Y_SMEM ((16384 + 16384 + 16384 + 256) * 4)   // 197632 bytes
__global__ __launch_bounds__(256) void wkv_y_kernel(const __half* __restrict__ r,
                                                    const __half* __restrict__ k,
                                                    const __half* __restrict__ v,
                                                    const float* __restrict__ ST,
                                                    const float* __restrict__ C,
                                                    const float* __restrict__ decay,
                                                    const float* __restrict__ faaaa,
                                                    float* __restrict__ y)
{
    extern __shared__ float sm[];
    float* ksm  = sm;
    float* vsm  = sm + 16384;
    float* sst  = sm + 32768;
    float* wpow = sm + 49152;

    int blk = blockIdx.x;
    int c = blk % NCK;
    int h = (blk / NCK) % HH;
    int b = blk / (NCK * HH);
    int tid = threadIdx.x;

    float ew = expf(decay[h]);
    float u  = faaaa[h];
    wpow[tid] = expf(-ew * (float)tid);

    size_t base = ((size_t)b * TT + (size_t)c * QQ) * CC + (size_t)h * NHD;

    for (int l = tid; l < 256 * 16; l += 256) {
        int qq = l >> 4;
        int f  = (l & 15) * 4;
        uint2 kk = *(const uint2*)(k + base + (size_t)qq * CC + f);
        uint2 vv = *(const uint2*)(v + base + (size_t)qq * CC + f);
        float2 ka = h2f(kk.x), kb2 = h2f(kk.y);
        float2 va = h2f(vv.x), vb2 = h2f(vv.y);
        ksm[qq * 64 + f] = ka.x; ksm[qq * 64 + f + 1] = ka.y;
        ksm[qq * 64 + f + 2] = kb2.x; ksm[qq * 64 + f + 3] = kb2.y;
        vsm[qq * 64 + f] = va.x; vsm[qq * 64 + f + 1] = va.y;
        vsm[qq * 64 + f + 2] = vb2.x; vsm[qq * 64 + f + 3] = vb2.y;
    }
    size_t sbase = (size_t)blk * 4096;
    for (int l = tid; l < 1024; l += 256)
        *(float4*)&sst[l * 4] = *(const float4*)(ST + sbase + (size_t)l * 4);
    __syncthreads();

    // build sub-chunk states: sst[s] = w64*sst[s-1] + C[s-1]  (same-thread index chain)
    {
        float w64v = wpow[64];
        const float* Cp = C + (size_t)blk * 12288;
        #pragma unroll
        for (int s = 1; s < 4; s++) {
            for (int l = tid; l < 1024; l += 256) {
                float4 p4 = *(const float4*)&sst[(s - 1) * 4096 + l * 4];
                float4 c4 = *(const float4*)(Cp + (size_t)(s - 1) * 4096 + l * 4);
                float4 o4 = make_float4(w64v * p4.x + c4.x, w64v * p4.y + c4.y,
                                        w64v * p4.z + c4.z, w64v * p4.w + c4.w);
                *(float4*)&sst[s * 4096 + l * 4] = o4;
            }
        }
    }
    __syncthreads();

    int q  = tid;
    int qs = q >> 6;
    int ql = q & 63;
    float rrow[64];
    {
        const uint4* rg = (const uint4*)(r + base + (size_t)q * CC);
        #pragma unroll
        for (int f = 0; f < 8; f++) {
            uint4 t4 = rg[f];
            float2 p0 = h2f(t4.x), p1 = h2f(t4.y), p2 = h2f(t4.z), p3 = h2f(t4.w);
            rrow[f * 8 + 0] = p0.x; rrow[f * 8 + 1] = p0.y;
            rrow[f * 8 + 2] = p1.x; rrow[f * 8 + 3] = p1.y;
            rrow[f * 8 + 4] = p2.x; rrow[f * 8 + 5] = p2.y;
            rrow[f * 8 + 6] = p3.x; rrow[f * 8 + 7] = p3.y;
        }
    }
    uint64_t acc2[32];
    #pragma unroll
    for (int m = 0; m < 32; m++) acc2[m] = 0;

    // state part: acc += r_n * sst[qs][n][*]   (FFMA2 pairs along m)
    const float* stq = sst + qs * 4096;
    #pragma unroll 8
    for (int n = 0; n < 64; n++) {
        uint64_t rb = bcast2(rrow[n]);
        const ulonglong2* srow = (const ulonglong2*)&stq[n * 64];
        #pragma unroll
        for (int m2 = 0; m2 < 16; m2++) {
            ulonglong2 s2 = srow[m2];
            fma2(acc2[2 * m2],     rb, s2.x);
            fma2(acc2[2 * m2 + 1], rb, s2.y);
        }
    }
    {
        uint64_t wb = bcast2(wpow[ql]);
        #pragma unroll
        for (int m = 0; m < 32; m++) mul2(acc2[m], wb);
    }

    // intra part within sub-chunk
    int j0 = qs * 64;
    int jend = ql | 31;
    for (int jl = 0; jl <= jend; jl++) {
        float a = 0.f;
        const float4* krow = (const float4*)&ksm[(j0 + jl) * 64];
        #pragma unroll
        for (int n4 = 0; n4 < 16; n4++) {
            float4 k4 = krow[n4];
            a += rrow[n4 * 4 + 0] * k4.x + rrow[n4 * 4 + 1] * k4.y
               + rrow[n4 * 4 + 2] * k4.z + rrow[n4 * 4 + 3] * k4.w;
        }
        float coef = (jl < ql) ? wpow[ql - jl - 1] : ((jl == ql) ? u : 0.0f);
        uint64_t ab = bcast2(a * coef);
        const ulonglong2* vrow = (const ulonglong2*)&vsm[(j0 + jl) * 64];
        #pragma unroll
        for (int m2 = 0; m2 < 16; m2++) {
            ulonglong2 v2 = vrow[m2];
            fma2(acc2[2 * m2],     ab, v2.x);
            fma2(acc2[2 * m2 + 1], ab, v2.y);
        }
    }

    float* yo = y + base + (size_t)q * CC;
    #pragma unroll
    for (int m2 = 0; m2 < 16; m2++) {
        float2 p0 = unpk2(acc2[2 * m2]);
        float2 p1 = unpk2(acc2[2 * m2 + 1]);
        *(float4*)(yo + m2 * 4) = make_float4(p0.x, p0.y, p1.x, p1.y);
    }
}

// ---------------- GroupNorm * g (fp16 g input, fp16 output) ----------------
__global__ __launch_bounds__(256) void gn_mul_kernel(const float* __restrict__ y,
                                                     const float* __restrict__ gnw,
                                                     const float* __restrict__ gnb,
                                                     const __half* __restrict__ g,
                                                     __half* __restrict__ yg)
{
    int row = blockIdx.x;
    int tid = threadIdx.x;
    size_t off = (size_t)row * CC;
    float4 v = ((const float4*)(y + off))[tid];
    float s  = v.x + v.y + v.z + v.w;
    float sq = v.x*v.x + v.y*v.y + v.z*v.z + v.w*v.w;
    #pragma unroll
    for (int o = 8; o >= 1; o >>= 1) {
        s  += __shfl_xor_sync(0xffffffffu, s,  o);
        sq += __shfl_xor_sync(0xffffffffu, sq, o);
    }
    float mu   = s * (1.0f / 64.0f);
    float var  = sq * (1.0f / 64.0f) - mu * mu;
    float rstd = rsqrtf(var + EPS_GN);
    float4 ww = ((const float4*)gnw)[tid];
    float4 bb = ((const float4*)gnb)[tid];
    uint2 gg2 = ((const uint2*)(g + off))[tid];
    float2 g0 = h2f(gg2.x), g1 = h2f(gg2.y);
    uint2 o4;
    o4.x = pack_f16(((v.x - mu) * rstd * ww.x + bb.x) * g0.x,
                    ((v.y - mu) * rstd * ww.y + bb.y) * g0.y);
    o4.y = pack_f16(((v.z - mu) * rstd * ww.z + bb.z) * g1.x,
                    ((v.w - mu) * rstd * ww.w + bb.w) * g1.y);
    ((uint2*)(yg + off))[tid] = o4;
}

// ---------------- host launcher ----------------
extern "C" void kernel_launch(void* const* d_in, const int* in_sizes, int n_in,
                              void* d_out, int out_size)
{
    const float* x      = (const float*)d_in[0];
    const float* ln1w   = (const float*)d_in[1];
    const float* ln1b   = (const float*)d_in[2];
    const float* maak   = (const float*)d_in[3];
    const float* maav   = (const float*)d_in[4];
    const float* maar   = (const float*)d_in[5];
    const float* maag   = (const float*)d_in[6];
    const float* decay  = (const float*)d_in[7];
    const float* faaaa  = (const float*)d_in[8];
    const float* Wr     = (const float*)d_in[9];
    const float* Wk     = (const float*)d_in[10];
    const float* Wv     = (const float*)d_in[11];
    const float* Wg     = (const float*)d_in[12];
    const float* Wo     = (const float*)d_in[13];
    const float* gnw    = (const float*)d_in[14];
    const float* gnb    = (const float*)d_in[15];
    const float* ln2w   = (const float*)d_in[16];
    const float* ln2b   = (const float*)d_in[17];
    const float* cmaak  = (const float*)d_in[18];
    const float* cmaar  = (const float*)d_in[19];
    const float* Wck    = (const float*)d_in[20];
    const float* Wcv    = (const float*)d_in[21];
    const float* Wcr    = (const float*)d_in[22];
    float* out = (float*)d_out;

    float* sc = nullptr;
    cudaGetSymbolAddress((void**)&sc, g_scratch);

    __half* xk   = (__half*)(sc + OFF_XK);
    __half* xv   = (__half*)(sc + OFF_XV);
    __half* xr   = (__half*)(sc + OFF_XR);
    __half* xg   = (__half*)(sc + OFF_XG);
    __half* rb   = (__half*)(sc + OFF_R);
    __half* kb   = (__half*)(sc + OFF_K);
    __half* vb   = (__half*)(sc + OFF_V);
    __half* gb   = (__half*)(sc + OFF_G);
    float* yb   = sc + OFF_Y;
    __half* ygb = (__half*)(sc + OFF_YG);
    float* x1   = sc + OFF_X1;
    __half* xk2 = (__half*)(sc + OFF_XK2);
    __half* xr2 = (__half*)(sc + OFF_XR2);
    float* hv   = sc + OFF_HV;
    __half* hb  = (__half*)(sc + OFF_H);
    float* Sb   = sc + OFF_S;
    float* STb  = sc + OFF_ST;
    float* Cb   = sc + OFF_C;
    __half* WrR  = (__half*)(sc + OFF_WR_R);
    __half* WkR  = (__half*)(sc + OFF_WK_R);
    __half* WvR  = (__half*)(sc + OFF_WV_R);
    __half* WgR  = (__half*)(sc + OFF_WG_R);
    __half* WoR  = (__half*)(sc + OFF_WO_R);
    __half* WcrR = (__half*)(sc + OFF_WCR_R);
    __half* WckR = (__half*)(sc + OFF_WCK_R);
    __half* WcvR = (__half*)(sc + OFF_WCV_R);

    cudaFuncSetAttribute(wkv_y_kernel, cudaFuncAttributeMaxDynamicSharedMemorySize, WKV_Y_SMEM);
    cudaFuncSetAttribute(gemm_hf_kernel, cudaFuncAttributeMaxDynamicSharedMemorySize, GEMM_SMEM);
    cudaFuncSetAttribute(gemm_hf4_kernel, cudaFuncAttributeMaxDynamicSharedMemorySize, GEMM_SMEM);

    dim3 g1024(1024 / 128, MTOT / 128);
    dim3 g1024z4(1024 / 128, MTOT / 128, 4);
    dim3 g3072(3072 / 128, MTOT / 128);

    // ---- weight conversion: single launch ----
    {
        CvtArgs ca;
        const float* srcs[8] = {Wr, Wk, Wv, Wg, Wo, Wcr, Wck, Wcv};
        __half* dsts[8] = {WrR, WkR, WvR, WgR, WoR, WcrR, WckR, WcvR};
        int sz4[8] = {262144, 262144, 262144, 262144, 262144, 262144, 786432, 786432};
        int acc4 = 0;
        for (int i = 0; i < 8; i++) { ca.src[i] = srcs[i]; ca.dst[i] = dsts[i]; acc4 += sz4[i]; ca.end4[i] = acc4; }
        cvt_all_kernel<<<acc4 / 256, 256>>>(ca);
    }

    // ---- time mix ----
    ln_mix_kernel<4><<<MTOT, 256>>>(x, ln1w, ln1b, maak, maav, maar, maag, xk, xv, xr, xg);
    {
        Gemm4Args ga;
        ga.A[0] = xr; ga.W[0] = WrR; ga.O[0] = rb; ga.silu[0] = 0;
        ga.A[1] = xk; ga.W[1] = WkR; ga.O[1] = kb; ga.silu[1] = 0;
        ga.A[2] = xv; ga.W[2] = WvR; ga.O[2] = vb; ga.silu[2] = 0;
        ga.A[3] = xg; ga.W[3] = WgR; ga.O[3] = gb; ga.silu[3] = 1;
        gemm_hf4_kernel<<<g1024z4, 256, GEMM_SMEM>>>(ga);
    }

    wkv_s_kernel<<<BB * HH * NCK, 256>>>(kb, vb, decay, Sb, Cb);
    wkv_scan_kernel<<<BB * HH * 16, 256>>>(Sb, decay, STb);
    wkv_y_kernel<<<BB * HH * NCK, 256, WKV_Y_SMEM>>>(rb, kb, vb, STb, Cb, decay, faaaa, yb);

    gn_mul_kernel<<<MTOT, 256>>>(yb, gnw, gnb, gb, ygb);
    gemm_hf_kernel<<<g1024, 256, GEMM_SMEM>>>(ygb, WoR, x1, nullptr, 1024, 1024, 4, x, nullptr); // + residual

    // ---- channel mix ----
    ln_mix_kernel<2><<<MTOT, 256>>>(x1, ln2w, ln2b, cmaak, cmaar, nullptr, nullptr,
                                    xk2, xr2, nullptr, nullptr);
    gemm_hf_kernel<<<g3072, 256, GEMM_SMEM>>>(xk2, WckR, nullptr, hb, 3072, 1024, 2, nullptr, nullptr); // relu^2
    gemm_hf_kernel<<<g1024, 256, GEMM_SMEM>>>(hb, WcvR, hv, nullptr, 1024, 3072, 0, nullptr, nullptr);
    gemm_hf_kernel<<<g1024, 256, GEMM_SMEM>>>(xr2, WcrR, out, nullptr, 1024, 1024, 3, hv, x1); // sigmoid*hv + x1
}

// round 14
// speedup vs baseline: 1.4278x; 1.0025x over previous
#include <cuda_runtime.h>
#include <cuda_fp16.h>
#include <math.h>
#include <stdint.h>

// ---------------- problem constants ----------------
#define BB 4
#define TT 4096
#define CC 1024
#define HH 16
#define NHD 64
#define QQ 256
#define NCK 16
#define MTOT (BB*TT)          // 16384
#define BTC (BB*TT*CC)        // 16777216
#define EPS_LN 1e-5f
#define EPS_GN (1e-5f*64.0f)

// ---------------- scratch ----------------
#define SCR_TOTAL (19ull*BTC + 8388608ull + 12582912ull + 12582912ull)
__device__ float g_scratch[SCR_TOTAL];

#define OFF_XK   (1ull*BTC)      // fp16
#define OFF_XV   (2ull*BTC)
#define OFF_XR   (3ull*BTC)
#define OFF_XG   (4ull*BTC)
#define OFF_R    (5ull*BTC)      // fp16
#define OFF_K    (6ull*BTC)      // fp16
#define OFF_V    (7ull*BTC)      // fp16
#define OFF_G    (8ull*BTC)      // fp16
#define OFF_YG   (10ull*BTC)     // fp16
#define OFF_X1   (11ull*BTC)     // fp32
#define OFF_XK2  (13ull*BTC)     // fp16
#define OFF_XR2  (14ull*BTC)     // fp16
#define OFF_HV   (15ull*BTC)     // fp32
#define OFF_H    (16ull*BTC)     // fp16 [16384,3072]
#define OFF_S    (19ull*BTC)
#define OFF_ST   (19ull*BTC + 4194304ull)
#define OFF_C    (19ull*BTC + 8388608ull)
#define OFF_WT   (19ull*BTC + 8388608ull + 12582912ull)
#define OFF_WR_R  (OFF_WT + 0ull)
#define OFF_WK_R  (OFF_WT + 1048576ull)
#define OFF_WV_R  (OFF_WT + 2097152ull)
#define OFF_WG_R  (OFF_WT + 3145728ull)
#define OFF_WO_R  (OFF_WT + 4194304ull)
#define OFF_WCR_R (OFF_WT + 5242880ull)
#define OFF_WCK_R (OFF_WT + 6291456ull)
#define OFF_WCV_R (OFF_WT + 9437184ull)

// ---------------- helpers ----------------
__device__ __forceinline__ uint32_t smem_u32(const void* p) {
    uint32_t a;
    asm("{ .reg .u64 t; cvta.to.shared.u64 t, %1; cvt.u32.u64 %0, t; }" : "=r"(a) : "l"(p));
    return a;
}

__device__ __forceinline__ uint32_t pack_f16(float a, float b) {
    __half2 h = __floats2half2_rn(a, b);
    return *(uint32_t*)&h;
}

__device__ __forceinline__ float2 h2f(uint32_t h) {
    __half2 v = *(__half2*)&h;
    return __half22float2(v);
}

// ---- packed f32x2 math ----
__device__ __forceinline__ uint64_t bcast2(float s) {
    uint64_t r;
    asm("mov.b64 %0, {%1, %1};" : "=l"(r) : "r"(__float_as_uint(s)));
    return r;
}
__device__ __forceinline__ void fma2(uint64_t& d, uint64_t a, uint64_t b) {
    asm("fma.rn.f32x2 %0, %1, %2, %0;" : "+l"(d) : "l"(a), "l"(b));
}
__device__ __forceinline__ void fma2w(uint64_t& d, uint64_t w, uint64_t c) {
    asm("fma.rn.f32x2 %0, %0, %1, %2;" : "+l"(d) : "l"(w), "l"(c));
}
__device__ __forceinline__ void mul2(uint64_t& d, uint64_t b) {
    asm("mul.rn.f32x2 %0, %0, %1;" : "+l"(d) : "l"(b));
}
__device__ __forceinline__ float2 unpk2(uint64_t v) {
    float lo, hi;
    asm("mov.b64 {%0, %1}, %2;" : "=f"(lo), "=f"(hi) : "l"(v));
    return make_float2(lo, hi);
}

__device__ __forceinline__ void cp16(uint32_t dst, const void* src) {
    asm volatile("cp.async.cg.shared.global [%0], [%1], 16;" :: "r"(dst), "l"(src) : "memory");
}
#define CP_COMMIT() asm volatile("cp.async.commit_group;" ::: "memory")
#define CP_WAIT_1() asm volatile("cp.async.wait_group 1;" ::: "memory")

// ---------------- all-weight fp32 -> fp16 (single launch) ----------------
struct CvtArgs {
    const float* src[8];
    __half* dst[8];
    int end4[8];
};
__global__ __launch_bounds__(256) void cvt_all_kernel(CvtArgs a)
{
    int i = blockIdx.x * 256 + threadIdx.x;
    int seg = 0;
    #pragma unroll
    for (int s = 0; s < 7; s++) seg += (i >= a.end4[s]) ? 1 : 0;
    int base = (seg == 0) ? 0 : a.end4[seg - 1];
    int li = i - base;
    float4 v = ((const float4*)a.src[seg])[li];
    uint2 o;
    o.x = pack_f16(v.x, v.y);
    o.y = pack_f16(v.z, v.w);
    ((uint2*)a.dst[seg])[li] = o;
}

// ---------------- fused LayerNorm + time-shift mix (fp16 outputs) ----------------
template<int NOUT>
__global__ __launch_bounds__(256) void ln_mix_kernel(const float* __restrict__ x,
                                                     const float* __restrict__ w,
                                                     const float* __restrict__ b,
                                                     const float* __restrict__ m0,
                                                     const float* __restrict__ m1,
                                                     const float* __restrict__ m2,
                                                     const float* __restrict__ m3,
                                                     __half* __restrict__ o0,
                                                     __half* __restrict__ o1,
                                                     __half* __restrict__ o2,
                                                     __half* __restrict__ o3)
{
    int row = blockIdx.x;
    int t = row % TT;
    int tid = threadIdx.x;
    size_t off = (size_t)row * CC;
    float4 cur = ((const float4*)(x + off))[tid];
    float4 prv = make_float4(0.f, 0.f, 0.f, 0.f);
    if (t > 0) prv = ((const float4*)(x + off - CC))[tid];

    float s0 = cur.x + cur.y + cur.z + cur.w;
    float q0 = cur.x*cur.x + cur.y*cur.y + cur.z*cur.z + cur.w*cur.w;
    float s1 = prv.x + prv.y + prv.z + prv.w;
    float q1 = prv.x*prv.x + prv.y*prv.y + prv.z*prv.z + prv.w*prv.w;
    #pragma unroll
    for (int o = 16; o >= 1; o >>= 1) {
        s0 += __shfl_xor_sync(0xffffffffu, s0, o);
        q0 += __shfl_xor_sync(0xffffffffu, q0, o);
        s1 += __shfl_xor_sync(0xffffffffu, s1, o);
        q1 += __shfl_xor_sync(0xffffffffu, q1, o);
    }
    __shared__ float red[4][8];
    int wid = tid >> 5, lane = tid & 31;
    if (lane == 0) { red[0][wid] = s0; red[1][wid] = q0; red[2][wid] = s1; red[3][wid] = q1; }
    __syncthreads();
    if (tid == 0) {
        float a0 = 0, a1 = 0, a2 = 0, a3 = 0;
        #pragma unroll
        for (int i = 0; i < 8; i++) { a0 += red[0][i]; a1 += red[1][i]; a2 += red[2][i]; a3 += red[3][i]; }
        red[0][0] = a0; red[1][0] = a1; red[2][0] = a2; red[3][0] = a3;
    }
    __syncthreads();
    float mu0 = red[0][0] * (1.0f / CC);
    float rs0 = rsqrtf(red[1][0] * (1.0f / CC) - mu0 * mu0 + EPS_LN);
    float mu1 = red[2][0] * (1.0f / CC);
    float rs1 = rsqrtf(red[3][0] * (1.0f / CC) - mu1 * mu1 + EPS_LN);

    float4 ww = ((const float4*)w)[tid];
    float4 bb = ((const float4*)b)[tid];
    float4 lc, lp;
    lc.x = (cur.x - mu0) * rs0 * ww.x + bb.x;
    lc.y = (cur.y - mu0) * rs0 * ww.y + bb.y;
    lc.z = (cur.z - mu0) * rs0 * ww.z + bb.z;
    lc.w = (cur.w - mu0) * rs0 * ww.w + bb.w;
    if (t > 0) {
        lp.x = (prv.x - mu1) * rs1 * ww.x + bb.x;
        lp.y = (prv.y - mu1) * rs1 * ww.y + bb.y;
        lp.z = (prv.z - mu1) * rs1 * ww.z + bb.z;
        lp.w = (prv.w - mu1) * rs1 * ww.w + bb.w;
    } else {
        lp = make_float4(0.f, 0.f, 0.f, 0.f);
    }
    float4 xx = make_float4(lp.x - lc.x, lp.y - lc.y, lp.z - lc.z, lp.w - lc.w);

    float4 a;
    uint2 o;
    a = ((const float4*)m0)[tid];
    o.x = pack_f16(lc.x + xx.x * a.x, lc.y + xx.y * a.y);
    o.y = pack_f16(lc.z + xx.z * a.z, lc.w + xx.w * a.w);
    ((uint2*)(o0 + off))[tid] = o;
    a = ((const float4*)m1)[tid];
    o.x = pack_f16(lc.x + xx.x * a.x, lc.y + xx.y * a.y);
    o.y = pack_f16(lc.z + xx.z * a.z, lc.w + xx.w * a.w);
    ((uint2*)(o1 + off))[tid] = o;
    if (NOUT == 4) {
        a = ((const float4*)m2)[tid];
        o.x = pack_f16(lc.x + xx.x * a.x, lc.y + xx.y * a.y);
        o.y = pack_f16(lc.z + xx.z * a.z, lc.w + xx.w * a.w);
        ((uint2*)(o2 + off))[tid] = o;
        a = ((const float4*)m3)[tid];
        o.x = pack_f16(lc.x + xx.x * a.x, lc.y + xx.y * a.y);
        o.y = pack_f16(lc.z + xx.z * a.z, lc.w + xx.w * a.w);
        ((uint2*)(o3 + off))[tid] = o;
    }
}

// ---------------- fp16 tensor-core GEMM core ----------------
#define STG_WORDS 9216
#define GEMM_SMEM (2 * STG_WORDS * 4)

__device__ __forceinline__ void mma_f16(float c[4],
                                        const uint32_t a[4],
                                        const uint32_t b[2])
{
    asm volatile(
        "mma.sync.aligned.m16n8k16.row.col.f32.f16.f16.f32 "
        "{%0,%1,%2,%3}, {%4,%5,%6,%7}, {%8,%9}, {%0,%1,%2,%3};\n"
        : "+f"(c[0]), "+f"(c[1]), "+f"(c[2]), "+f"(c[3])
        : "r"(a[0]), "r"(a[1]), "r"(a[2]), "r"(a[3]),
          "r"(b[0]), "r"(b[1]));
}

#define LDMATRIX_X4(r0, r1, r2, r3, addr) \
    asm volatile("ldmatrix.sync.aligned.m8n8.x4.shared.b16 {%0,%1,%2,%3}, [%4];" \
        : "=r"(r0), "=r"(r1), "=r"(r2), "=r"(r3) : "r"(addr))

__device__ __forceinline__ void gemm_mainloop(const __half* __restrict__ A,
                                              const __half* __restrict__ W,
                                              int K, int m0, int n0,
                                              uint32_t* smw, int tid,
                                              float acc[4][4][4])
{
    int lane = tid & 31;
    int j  = tid & 7;
    int r0 = tid >> 3;
    const __half* pA = A + ((size_t)m0 + r0) * K + j * 8;
    const __half* pW = W + ((size_t)n0 + r0) * K + j * 8;
    uint32_t smb = smem_u32(smw);
    uint32_t dstA = smb + (uint32_t)(r0 * 36 + j * 4) * 4u;
    uint32_t dstW = dstA + 4608u * 4u;
    int wid = tid >> 5;
    int wm = wid >> 2, wn = wid & 3;

    uint32_t aAddr[4], bAddr[2];
    #pragma unroll
    for (int mi = 0; mi < 4; mi++)
        aAddr[mi] = smb + (uint32_t)((wm * 64 + mi * 16 + (lane & 15)) * 36) * 4u
                        + (uint32_t)(lane >> 4) * 16u;
    #pragma unroll
    for (int p = 0; p < 2; p++)
        bAddr[p] = smb + 4608u * 4u
                 + (uint32_t)((wn * 32 + (p * 2 + (lane >> 4)) * 8 + (lane & 7)) * 36) * 4u
                 + (uint32_t)((lane >> 3) & 1) * 16u;

    int NC = K >> 6;

    #pragma unroll
    for (int s = 0; s < 2; s++) {
        uint32_t so = (uint32_t)(s * STG_WORDS) * 4u;
        int kf = s * 64;
        #pragma unroll
        for (int i = 0; i < 4; i++) {
            cp16(dstA + so + (uint32_t)(i * 32 * 36) * 4u, pA + (size_t)(i * 32) * K + kf);
            cp16(dstW + so + (uint32_t)(i * 32 * 36) * 4u, pW + (size_t)(i * 32) * K + kf);
        }
        CP_COMMIT();
    }

    for (int t = 0; t < NC; t++) {
        CP_WAIT_1();
        __syncthreads();
        uint32_t so = (uint32_t)((t & 1) * STG_WORDS) * 4u;

        #pragma unroll
        for (int kk = 0; kk < 4; kk++) {
            uint32_t ko = so + (uint32_t)kk * 32u;
            uint32_t af[4][4];
            uint32_t bf[4][2];
            #pragma unroll
            for (int mi = 0; mi < 4; mi++)
                LDMATRIX_X4(af[mi][0], af[mi][1], af[mi][2], af[mi][3], aAddr[mi] + ko);
            #pragma unroll
            for (int p = 0; p < 2; p++)
                LDMATRIX_X4(bf[2*p][0], bf[2*p][1], bf[2*p+1][0], bf[2*p+1][1], bAddr[p] + ko);
            #pragma unroll
            for (int mi = 0; mi < 4; mi++)
                #pragma unroll
                for (int ni = 0; ni < 4; ni++)
                    mma_f16(acc[mi][ni], af[mi], bf[ni]);
        }
        __syncthreads();

        int lc = t + 2;
        if (lc < NC) {
            uint32_t so2 = (uint32_t)((t & 1) * STG_WORDS) * 4u;
            int kf = lc * 64;
            #pragma unroll
            for (int i = 0; i < 4; i++) {
                cp16(dstA + so2 + (uint32_t)(i * 32 * 36) * 4u, pA + (size_t)(i * 32) * K + kf);
                cp16(dstW + so2 + (uint32_t)(i * 32 * 36) * 4u, pW + (size_t)(i * 32) * K + kf);
            }
        }
        CP_COMMIT();
    }
}

__device__ __forceinline__ float gemm_epi(float vv, int epi, const float* aux1,
                                          const float* aux2, size_t o)
{
    if (epi == 1) {
        vv = vv / (1.f + expf(-vv));
    } else if (epi == 3) {
        vv = 1.f / (1.f + expf(-vv));
        vv = vv * aux1[o] + aux2[o];
    } else if (epi == 4) {
        vv = vv + aux1[o];
    }
    return vv;
}

__global__ void __launch_bounds__(256, 2)
gemm_hf_kernel(const __half* __restrict__ A, const __half* __restrict__ W,
               float* __restrict__ Co, __half* __restrict__ Coh,
               int Nn, int K, int epi,
               const float* __restrict__ aux1, const float* __restrict__ aux2)
{
    extern __shared__ uint32_t smw[];
    int tid = threadIdx.x;
    int n0 = blockIdx.x * 128;
    int m0 = blockIdx.y * 128;
    int wid = tid >> 5, lane = tid & 31;
    int wm = wid >> 2, wn = wid & 3;
    int gid = lane >> 2, tg = lane & 3;

    float acc[4][4][4];
    #pragma unroll
    for (int mi = 0; mi < 4; mi++)
        #pragma unroll
        for (int ni = 0; ni < 4; ni++)
            #pragma unroll
            for (int e = 0; e < 4; e++) acc[mi][ni][e] = 0.f;

    gemm_mainloop(A, W, K, m0, n0, smw, tid, acc);

    #pragma unroll
    for (int mi = 0; mi < 4; mi++) {
        int row0 = m0 + wm * 64 + mi * 16 + gid;
        #pragma unroll
        for (int ni = 0; ni < 4; ni++) {
            int col0 = n0 + wn * 32 + ni * 8 + tg * 2;
            size_t o0 = (size_t)row0 * Nn + col0;
            size_t o1 = (size_t)(row0 + 8) * Nn + col0;
            if (epi == 2) {
                float a0 = fmaxf(acc[mi][ni][0], 0.f); a0 *= a0;
                float a1 = fmaxf(acc[mi][ni][1], 0.f); a1 *= a1;
                float a2 = fmaxf(acc[mi][ni][2], 0.f); a2 *= a2;
                float a3 = fmaxf(acc[mi][ni][3], 0.f); a3 *= a3;
                *(uint32_t*)(Coh + o0) = pack_f16(a0, a1);
                *(uint32_t*)(Coh + o1) = pack_f16(a2, a3);
            } else {
                float2 v0, v1;
                v0.x = gemm_epi(acc[mi][ni][0], epi, aux1, aux2, o0);
                v0.y = gemm_epi(acc[mi][ni][1], epi, aux1, aux2, o0 + 1);
                v1.x = gemm_epi(acc[mi][ni][2], epi, aux1, aux2, o1);
                v1.y = gemm_epi(acc[mi][ni][3], epi, aux1, aux2, o1 + 1);
                *(float2*)(Co + o0) = v0;
                *(float2*)(Co + o1) = v1;
            }
        }
    }
}

// merged 4-GEMM kernel for tmix
struct Gemm4Args {
    const __half* A[4];
    const __half* W[4];
    __half* O[4];
    int silu[4];
};
__global__ void __launch_bounds__(256, 2)
gemm_hf4_kernel(Gemm4Args args)
{
    extern __shared__ uint32_t smw[];
    int z = blockIdx.z;
    const __half* A = args.A[z];
    const __half* W = args.W[z];
    __half* O = args.O[z];
    int silu = args.silu[z];

    int tid = threadIdx.x;
    int n0 = blockIdx.x * 128;
    int m0 = blockIdx.y * 128;
    int wid = tid >> 5, lane = tid & 31;
    int wm = wid >> 2, wn = wid & 3;
    int gid = lane >> 2, tg = lane & 3;

    float acc[4][4][4];
    #pragma unroll
    for (int mi = 0; mi < 4; mi++)
        #pragma unroll
        for (int ni = 0; ni < 4; ni++)
            #pragma unroll
            for (int e = 0; e < 4; e++) acc[mi][ni][e] = 0.f;

    gemm_mainloop(A, W, 1024, m0, n0, smw, tid, acc);

    #pragma unroll
    for (int mi = 0; mi < 4; mi++) {
        int row0 = m0 + wm * 64 + mi * 16 + gid;
        #pragma unroll
        for (int ni = 0; ni < 4; ni++) {
            int col0 = n0 + wn * 32 + ni * 8 + tg * 2;
            size_t o0 = (size_t)row0 * 1024 + col0;
            size_t o1 = (size_t)(row0 + 8) * 1024 + col0;
            float a0 = acc[mi][ni][0], a1 = acc[mi][ni][1];
            float a2 = acc[mi][ni][2], a3 = acc[mi][ni][3];
            if (silu) {
                a0 = a0 / (1.f + expf(-a0));
                a1 = a1 / (1.f + expf(-a1));
                a2 = a2 / (1.f + expf(-a2));
                a3 = a3 / (1.f + expf(-a3));
            }
            *(uint32_t*)(O + o0) = pack_f16(a0, a1);
            *(uint32_t*)(O + o1) = pack_f16(a2, a3);
        }
    }
}

// ---------------- WKV: per-subchunk contributions + chunk state ----------------
__global__ __launch_bounds__(256) void wkv_s_kernel(const __half* __restrict__ k,
                                                    const __half* __restrict__ v,
                                                    const float* __restrict__ decay,
                                                    float* __restrict__ S,
                                                    float* __restrict__ C)
{
    int blk = blockIdx.x;
    int c = blk % NCK;
    int h = (blk / NCK) % HH;
    int b = blk / (NCK * HH);
    __shared__ float ksm[64][64];
    __shared__ float vsm[64][64];
    __shared__ float wpow[128];
    int tid = threadIdx.x;
    float ew = expf(decay[h]);
    if (tid < 128) wpow[tid] = expf(-ew * (float)tid);
    int n0 = (tid >> 4) * 4;
    int m0 = (tid & 15) * 4;
    uint64_t Sacc[4][2];
    #pragma unroll
    for (int i = 0; i < 4; i++) { Sacc[i][0] = 0; Sacc[i][1] = 0; }

    size_t base = ((size_t)b * TT + (size_t)c * QQ) * CC + (size_t)h * NHD;
    float w64 = 0.f;

    for (int qc = 0; qc < 4; qc++) {
        __syncthreads();
        for (int l = tid; l < 64 * 16; l += 256) {
            int qq = l >> 4;
            int f  = (l & 15) * 4;
            uint2 kk = *(const uint2*)(k + base + (size_t)(qc * 64 + qq) * CC + f);
            uint2 vv = *(const uint2*)(v + base + (size_t)(qc * 64 + qq) * CC + f);
            float2 ka = h2f(kk.x), kb2 = h2f(kk.y);
            float2 va = h2f(vv.x), vb2 = h2f(vv.y);
            ksm[qq][f] = ka.x; ksm[qq][f+1] = ka.y; ksm[qq][f+2] = kb2.x; ksm[qq][f+3] = kb2.y;
            vsm[qq][f] = va.x; vsm[qq][f+1] = va.y; vsm[qq][f+2] = vb2.x; vsm[qq][f+3] = vb2.y;
        }
        __syncthreads();
        if (qc == 0) w64 = wpow[64];

        uint64_t acc2[4][2];
        #pragma unroll
        for (int i = 0; i < 4; i++) { acc2[i][0] = 0; acc2[i][1] = 0; }

        #pragma unroll 4
        for (int jl = 0; jl < 64; jl++) {
            float wq = wpow[63 - jl];
            float4 kk = *(const float4*)&ksm[jl][n0];
            ulonglong2 vp = *(const ulonglong2*)&vsm[jl][m0];
            uint64_t kb0 = bcast2(kk.x * wq);
            uint64_t kb1 = bcast2(kk.y * wq);
            uint64_t kb2 = bcast2(kk.z * wq);
            uint64_t kb3 = bcast2(kk.w * wq);
            fma2(acc2[0][0], kb0, vp.x); fma2(acc2[0][1], kb0, vp.y);
            fma2(acc2[1][0], kb1, vp.x); fma2(acc2[1][1], kb1, vp.y);
            fma2(acc2[2][0], kb2, vp.x); fma2(acc2[2][1], kb2, vp.y);
            fma2(acc2[3][0], kb3, vp.x); fma2(acc2[3][1], kb3, vp.y);
        }

        uint64_t wb = bcast2(w64);
        #pragma unroll
        for (int i = 0; i < 4; i++) {
            fma2w(Sacc[i][0], wb, acc2[i][0]);
            fma2w(Sacc[i][1], wb, acc2[i][1]);
        }

        if (qc < 3) {
            float* Cp = C + (size_t)blk * 12288 + (size_t)qc * 4096;
            #pragma unroll
            for (int i = 0; i < 4; i++) {
                float2 p0 = unpk2(acc2[i][0]);
                float2 p1 = unpk2(acc2[i][1]);
                *(float4*)(Cp + (n0 + i) * 64 + m0) = make_float4(p0.x, p0.y, p1.x, p1.y);
            }
        }
    }

    float* Sp = S + (size_t)blk * 4096;
    #pragma unroll
    for (int i = 0; i < 4; i++) {
        float2 p0 = unpk2(Sacc[i][0]);
        float2 p1 = unpk2(Sacc[i][1]);
        *(float4*)(Sp + (n0 + i) * 64 + m0) = make_float4(p0.x, p0.y, p1.x, p1.y);
    }
}

// ---------------- WKV: inter-chunk prefix scan (wide grid) ----------------
__global__ __launch_bounds__(256) void wkv_scan_kernel(const float* __restrict__ S,
                                                       const float* __restrict__ decay,
                                                       float* __restrict__ ST)
{
    int bh = blockIdx.x >> 4;
    int part = blockIdx.x & 15;
    int h = bh % HH;
    float ws = expf(-expf(decay[h]) * 256.0f);
    int e = part * 256 + threadIdx.x;
    size_t b0 = (size_t)bh * NCK * 4096;
    float st = 0.f;
    #pragma unroll
    for (int c = 0; c < NCK; c++) {
        ST[b0 + (size_t)c * 4096 + e] = st;
        st = ws * st + S[b0 + (size_t)c * 4096 + e];
    }
}

// ---------------- WKV: per-chunk output + fused GroupNorm*g (fp16 out) ----------------
#define WKV_Y_SMEM ((16384 + 16384 + 16384 + 256 + 128) * 4)
__global__ __launch_bounds__(256) void wkv_y_kernel(const __half* __restrict__ r,
                                                    const __half* __restrict__ k,
                                                    const __half* __restrict__ v,
                                                    const float* __restrict__ ST,
                                                    const float* __restrict__ C,
                                                    const float* __restrict__ decay,
                                                    const float* __restrict__ faaaa,
                                                    const float* __restrict__ gnw,
                                                    const float* __restrict__ gnb,
                                                    const __half* __restrict__ g,
                                                    __half* __restrict__ yg)
{
    extern __shared__ float sm[];
    float* ksm  = sm;
    float* vsm  = sm + 16384;
    float* sst  = sm + 32768;
    float* wpow = sm + 49152;
    float* gnsm = sm + 49408;          // gnw[64] then gnb[64] for this head

    int blk = blockIdx.x;
    int c = blk % NCK;
    int h = (blk / NCK) % HH;
    int b = blk / (NCK * HH);
    int tid = threadIdx.x;

    float ew = expf(decay[h]);
    float u  = faaaa[h];
    wpow[tid] = expf(-ew * (float)tid);
    if (tid < 64) gnsm[tid] = gnw[h * 64 + tid];
    else if (tid < 128) gnsm[tid] = gnb[h * 64 + tid - 64];

    size_t base = ((size_t)b * TT + (size_t)c * QQ) * CC + (size_t)h * NHD;

    for (int l = tid; l < 256 * 16; l += 256) {
        int qq = l >> 4;
        int f  = (l & 15) * 4;
        uint2 kk = *(const uint2*)(k + base + (size_t)qq * CC + f);
        uint2 vv = *(const uint2*)(v + base + (size_t)qq * CC + f);
        float2 ka = h2f(kk.x), kb2 = h2f(kk.y);
        float2 va = h2f(vv.x), vb2 = h2f(vv.y);
        ksm[qq * 64 + f] = ka.x; ksm[qq * 64 + f + 1] = ka.y;
        ksm[qq * 64 + f + 2] = kb2.x; ksm[qq * 64 + f + 3] = kb2.y;
        vsm[qq * 64 + f] = va.x; vsm[qq * 64 + f + 1] = va.y;
        vsm[qq * 64 + f + 2] = vb2.x; vsm[qq * 64 + f + 3] = vb2.y;
    }
    size_t sbase = (size_t)blk * 4096;
    for (int l = tid; l < 1024; l += 256)
        *(float4*)&sst[l * 4] = *(const float4*)(ST + sbase + (size_t)l * 4);
    __syncthreads();

    // build sub-chunk states
    {
        float w64v = wpow[64];
        const float* Cp = C + (size_t)blk * 12288;
        #pragma unroll
        for (int s = 1; s < 4; s++) {
            for (int l = tid; l < 1024; l += 256) {
                float4 p4 = *(const float4*)&sst[(s - 1) * 4096 + l * 4];
                float4 c4 = *(const float4*)(Cp + (size_t)(s - 1) * 4096 + l * 4);
                float4 o4 = make_float4(w64v * p4.x + c4.x, w64v * p4.y + c4.y,
                                        w64v * p4.z + c4.z, w64v * p4.w + c4.w);
                *(float4*)&sst[s * 4096 + l * 4] = o4;
            }
        }
    }
    __syncthreads();

    int q  = tid;
    int qs = q >> 6;
    int ql = q & 63;
    float rrow[64];
    {
        const uint4* rg = (const uint4*)(r + base + (size_t)q * CC);
        #pragma unroll
        for (int f = 0; f < 8; f++) {
            uint4 t4 = rg[f];
            float2 p0 = h2f(t4.x), p1 = h2f(t4.y), p2 = h2f(t4.z), p3 = h2f(t4.w);
            rrow[f * 8 + 0] = p0.x; rrow[f * 8 + 1] = p0.y;
            rrow[f * 8 + 2] = p1.x; rrow[f * 8 + 3] = p1.y;
            rrow[f * 8 + 4] = p2.x; rrow[f * 8 + 5] = p2.y;
            rrow[f * 8 + 6] = p3.x; rrow[f * 8 + 7] = p3.y;
        }
    }
    uint64_t acc2[32];
    #pragma unroll
    for (int m = 0; m < 32; m++) acc2[m] = 0;

    const float* stq = sst + qs * 4096;
    #pragma unroll 8
    for (int n = 0; n < 64; n++) {
        uint64_t rb = bcast2(rrow[n]);
        const ulonglong2* srow = (const ulonglong2*)&stq[n * 64];
        #pragma unroll
        for (int m2 = 0; m2 < 16; m2++) {
            ulonglong2 s2 = srow[m2];
            fma2(acc2[2 * m2],     rb, s2.x);
            fma2(acc2[2 * m2 + 1], rb, s2.y);
        }
    }
    {
        uint64_t wb = bcast2(wpow[ql]);
        #pragma unroll
        for (int m = 0; m < 32; m++) mul2(acc2[m], wb);
    }

    int j0 = qs * 64;
    int jend = ql | 31;
    for (int jl = 0; jl <= jend; jl++) {
        float a = 0.f;
        const float4* krow = (const float4*)&ksm[(j0 + jl) * 64];
        #pragma unroll
        for (int n4 = 0; n4 < 16; n4++) {
            float4 k4 = krow[n4];
            a += rrow[n4 * 4 + 0] * k4.x + rrow[n4 * 4 + 1] * k4.y
               + rrow[n4 * 4 + 2] * k4.z + rrow[n4 * 4 + 3] * k4.w;
        }
        float coef = (jl < ql) ? wpow[ql - jl - 1] : ((jl == ql) ? u : 0.0f);
        uint64_t ab = bcast2(a * coef);
        const ulonglong2* vrow = (const ulonglong2*)&vsm[(j0 + jl) * 64];
        #pragma unroll
        for (int m2 = 0; m2 < 16; m2++) {
            ulonglong2 v2 = vrow[m2];
            fma2(acc2[2 * m2],     ab, v2.x);
            fma2(acc2[2 * m2 + 1], ab, v2.y);
        }
    }

    // ---- fused GroupNorm (over the 64 in-register channels) * g -> fp16 ----
    float yv[64];
    float ssum = 0.f, ssq = 0.f;
    #pragma unroll
    for (int m = 0; m < 32; m++) {
        float2 p = unpk2(acc2[m]);
        yv[2 * m] = p.x; yv[2 * m + 1] = p.y;
        ssum += p.x + p.y;
        ssq  += p.x * p.x + p.y * p.y;
    }
    float mu   = ssum * (1.0f / 64.0f);
    float var  = ssq * (1.0f / 64.0f) - mu * mu;
    float rstd = rsqrtf(var + EPS_GN);

    __half* yo = yg + base + (size_t)q * CC;
    const uint2* gg = (const uint2*)(g + base + (size_t)q * CC);
    #pragma unroll
    for (int m4 = 0; m4 < 16; m4++) {
        uint2 g2 = gg[m4];
        float2 g0 = h2f(g2.x), g1 = h2f(g2.y);
        float o0 = ((yv[m4 * 4 + 0] - mu) * rstd * gnsm[m4 * 4 + 0] + gnsm[64 + m4 * 4 + 0]) * g0.x;
        float o1 = ((yv[m4 * 4 + 1] - mu) * rstd * gnsm[m4 * 4 + 1] + gnsm[64 + m4 * 4 + 1]) * g0.y;
        float o2 = ((yv[m4 * 4 + 2] - mu) * rstd * gnsm[m4 * 4 + 2] + gnsm[64 + m4 * 4 + 2]) * g1.x;
        float o3 = ((yv[m4 * 4 + 3] - mu) * rstd * gnsm[m4 * 4 + 3] + gnsm[64 + m4 * 4 + 3]) * g1.y;
        uint2 ow;
        ow.x = pack_f16(o0, o1);
        ow.y = pack_f16(o2, o3);
        *(uint2*)(yo + m4 * 4) = ow;
    }
}

// ---------------- host launcher ----------------
extern "C" void kernel_launch(void* const* d_in, const int* in_sizes, int n_in,
                              void* d_out, int out_size)
{
    const float* x      = (const float*)d_in[0];
    const float* ln1w   = (const float*)d_in[1];
    const float* ln1b   = (const float*)d_in[2];
    const float* maak   = (const float*)d_in[3];
    const float* maav   = (const float*)d_in[4];
    const float* maar   = (const float*)d_in[5];
    const float* maag   = (const float*)d_in[6];
    const float* decay  = (const float*)d_in[7];
    const float* faaaa  = (const float*)d_in[8];
    const float* Wr     = (const float*)d_in[9];
    const float* Wk     = (const float*)d_in[10];
    const float* Wv     = (const float*)d_in[11];
    const float* Wg     = (const float*)d_in[12];
    const float* Wo     = (const float*)d_in[13];
    const float* gnw    = (const float*)d_in[14];
    const float* gnb    = (const float*)d_in[15];
    const float* ln2w   = (const float*)d_in[16];
    const float* ln2b   = (const float*)d_in[17];
    const float* cmaak  = (const float*)d_in[18];
    const float* cmaar  = (const float*)d_in[19];
    const float* Wck    = (const float*)d_in[20];
    const float* Wcv    = (const float*)d_in[21];
    const float* Wcr    = (const float*)d_in[22];
    float* out = (float*)d_out;

    float* sc = nullptr;
    cudaGetSymbolAddress((void**)&sc, g_scratch);

    __half* xk   = (__half*)(sc + OFF_XK);
    __half* xv   = (__half*)(sc + OFF_XV);
    __half* xr   = (__half*)(sc + OFF_XR);
    __half* xg   = (__half*)(sc + OFF_XG);
    __half* rb   = (__half*)(sc + OFF_R);
    __half* kb   = (__half*)(sc + OFF_K);
    __half* vb   = (__half*)(sc + OFF_V);
    __half* gb   = (__half*)(sc + OFF_G);
    __half* ygb = (__half*)(sc + OFF_YG);
    float* x1   = sc + OFF_X1;
    __half* xk2 = (__half*)(sc + OFF_XK2);
    __half* xr2 = (__half*)(sc + OFF_XR2);
    float* hv   = sc + OFF_HV;
    __half* hb  = (__half*)(sc + OFF_H);
    float* Sb   = sc + OFF_S;
    float* STb  = sc + OFF_ST;
    float* Cb   = sc + OFF_C;
    __half* WrR  = (__half*)(sc + OFF_WR_R);
    __half* WkR  = (__half*)(sc + OFF_WK_R);
    __half* WvR  = (__half*)(sc + OFF_WV_R);
    __half* WgR  = (__half*)(sc + OFF_WG_R);
    __half* WoR  = (__half*)(sc + OFF_WO_R);
    __half* WcrR = (__half*)(sc + OFF_WCR_R);
    __half* WckR = (__half*)(sc + OFF_WCK_R);
    __half* WcvR = (__half*)(sc + OFF_WCV_R);

    cudaFuncSetAttribute(wkv_y_kernel, cudaFuncAttributeMaxDynamicSharedMemorySize, WKV_Y_SMEM);
    cudaFuncSetAttribute(gemm_hf_kernel, cudaFuncAttributeMaxDynamicSharedMemorySize, GEMM_SMEM);
    cudaFuncSetAttribute(gemm_hf4_kernel, cudaFuncAttributeMaxDynamicSharedMemorySize, GEMM_SMEM);

    dim3 g1024(1024 / 128, MTOT / 128);
    dim3 g1024z4(1024 / 128, MTOT / 128, 4);
    dim3 g3072(3072 / 128, MTOT / 128);

    // ---- weight conversion: single launch ----
    {
        CvtArgs ca;
        const float* srcs[8] = {Wr, Wk, Wv, Wg, Wo, Wcr, Wck, Wcv};
        __half* dsts[8] = {WrR, WkR, WvR, WgR, WoR, WcrR, WckR, WcvR};
        int sz4[8] = {262144, 262144, 262144, 262144, 262144, 262144, 786432, 786432};
        int acc4 = 0;
        for (int i = 0; i < 8; i++) { ca.src[i] = srcs[i]; ca.dst[i] = dsts[i]; acc4 += sz4[i]; ca.end4[i] = acc4; }
        cvt_all_kernel<<<acc4 / 256, 256>>>(ca);
    }

    // ---- time mix ----
    ln_mix_kernel<4><<<MTOT, 256>>>(x, ln1w, ln1b, maak, maav, maar, maag, xk, xv, xr, xg);
    {
        Gemm4Args ga;
        ga.A[0] = xr; ga.W[0] = WrR; ga.O[0] = rb; ga.silu[0] = 0;
        ga.A[1] = xk; ga.W[1] = WkR; ga.O[1] = kb; ga.silu[1] = 0;
        ga.A[2] = xv; ga.W[2] = WvR; ga.O[2] = vb; ga.silu[2] = 0;
        ga.A[3] = xg; ga.W[3] = WgR; ga.O[3] = gb; ga.silu[3] = 1;
        gemm_hf4_kernel<<<g1024z4, 256, GEMM_SMEM>>>(ga);
    }

    wkv_s_kernel<<<BB * HH * NCK, 256>>>(kb, vb, decay, Sb, Cb);
    wkv_scan_kernel<<<BB * HH * 16, 256>>>(Sb, decay, STb);
    wkv_y_kernel<<<BB * HH * NCK, 256, WKV_Y_SMEM>>>(rb, kb, vb, STb, Cb, decay, faaaa,
                                                     gnw, gnb, gb, ygb);

    gemm_hf_kernel<<<g1024, 256, GEMM_SMEM>>>(ygb, WoR, x1, nullptr, 1024, 1024, 4, x, nullptr); // + residual

    // ---- channel mix ----
    ln_mix_kernel<2><<<MTOT, 256>>>(x1, ln2w, ln2b, cmaak, cmaar, nullptr, nullptr,
                                    xk2, xr2, nullptr, nullptr);
    gemm_hf_kernel<<<g3072, 256, GEMM_SMEM>>>(xk2, WckR, nullptr, hb, 3072, 1024, 2, nullptr, nullptr); // relu^2
    gemm_hf_kernel<<<g1024, 256, GEMM_SMEM>>>(hb, WcvR, hv, nullptr, 1024, 3072, 0, nullptr, nullptr);
    gemm_hf_kernel<<<g1024, 256, GEMM_SMEM>>>(xr2, WcrR, out, nullptr, 1024, 1024, 3, hv, x1); // sigmoid*hv + x1
}

// round 15
// speedup vs baseline: 1.4431x; 1.0107x over previous
#include <cuda_runtime.h>
#include <cuda_fp16.h>
#include <math.h>
#include <stdint.h>

// ---------------- problem constants ----------------
#define BB 4
#define TT 4096
#define CC 1024
#define HH 16
#define NHD 64
#define QQ 256
#define NCK 16
#define MTOT (BB*TT)          // 16384
#define BTC (BB*TT*CC)        // 16777216
#define EPS_LN 1e-5f
#define EPS_GN (1e-5f*64.0f)

// ---------------- scratch ----------------
#define SCR_TOTAL (19ull*BTC + 8388608ull + 12582912ull + 12582912ull)
__device__ float g_scratch[SCR_TOTAL];

#define OFF_XK   (1ull*BTC)      // fp16
#define OFF_XV   (2ull*BTC)
#define OFF_XR   (3ull*BTC)
#define OFF_XG   (4ull*BTC)
#define OFF_R    (5ull*BTC)      // fp16
#define OFF_K    (6ull*BTC)      // fp16
#define OFF_V    (7ull*BTC)      // fp16
#define OFF_G    (8ull*BTC)      // fp16
#define OFF_YG   (10ull*BTC)     // fp16
#define OFF_X1   (11ull*BTC)     // fp32
#define OFF_XK2  (13ull*BTC)     // fp16
#define OFF_XR2  (14ull*BTC)     // fp16
#define OFF_SIG  (15ull*BTC)     // fp16 sigmoid(xr2@Wcr)
#define OFF_H    (16ull*BTC)     // fp16 [16384,3072]
#define OFF_S    (19ull*BTC)
#define OFF_ST   (19ull*BTC + 4194304ull)
#define OFF_C    (19ull*BTC + 8388608ull)
#define OFF_WT   (19ull*BTC + 8388608ull + 12582912ull)
#define OFF_WR_R  (OFF_WT + 0ull)
#define OFF_WK_R  (OFF_WT + 1048576ull)
#define OFF_WV_R  (OFF_WT + 2097152ull)
#define OFF_WG_R  (OFF_WT + 3145728ull)
#define OFF_WO_R  (OFF_WT + 4194304ull)
#define OFF_WCR_R (OFF_WT + 5242880ull)
#define OFF_WCK_R (OFF_WT + 6291456ull)
#define OFF_WCV_R (OFF_WT + 9437184ull)

// ---------------- helpers ----------------
__device__ __forceinline__ uint32_t smem_u32(const void* p) {
    uint32_t a;
    asm("{ .reg .u64 t; cvta.to.shared.u64 t, %1; cvt.u32.u64 %0, t; }" : "=r"(a) : "l"(p));
    return a;
}

__device__ __forceinline__ uint32_t pack_f16(float a, float b) {
    __half2 h = __floats2half2_rn(a, b);
    return *(uint32_t*)&h;
}

__device__ __forceinline__ float2 h2f(uint32_t h) {
    __half2 v = *(__half2*)&h;
    return __half22float2(v);
}

// ---- packed f32x2 math ----
__device__ __forceinline__ uint64_t bcast2(float s) {
    uint64_t r;
    asm("mov.b64 %0, {%1, %1};" : "=l"(r) : "r"(__float_as_uint(s)));
    return r;
}
__device__ __forceinline__ void fma2(uint64_t& d, uint64_t a, uint64_t b) {
    asm("fma.rn.f32x2 %0, %1, %2, %0;" : "+l"(d) : "l"(a), "l"(b));
}
__device__ __forceinline__ void fma2w(uint64_t& d, uint64_t w, uint64_t c) {
    asm("fma.rn.f32x2 %0, %0, %1, %2;" : "+l"(d) : "l"(w), "l"(c));
}
__device__ __forceinline__ void mul2(uint64_t& d, uint64_t b) {
    asm("mul.rn.f32x2 %0, %0, %1;" : "+l"(d) : "l"(b));
}
__device__ __forceinline__ float2 unpk2(uint64_t v) {
    float lo, hi;
    asm("mov.b64 {%0, %1}, %2;" : "=f"(lo), "=f"(hi) : "l"(v));
    return make_float2(lo, hi);
}

__device__ __forceinline__ void cp16(uint32_t dst, const void* src) {
    asm volatile("cp.async.cg.shared.global [%0], [%1], 16;" :: "r"(dst), "l"(src) : "memory");
}
#define CP_COMMIT() asm volatile("cp.async.commit_group;" ::: "memory")
#define CP_WAIT_1() asm volatile("cp.async.wait_group 1;" ::: "memory")

// ---------------- all-weight fp32 -> fp16 (single launch) ----------------
struct CvtArgs {
    const float* src[8];
    __half* dst[8];
    int end4[8];
};
__global__ __launch_bounds__(256) void cvt_all_kernel(CvtArgs a)
{
    int i = blockIdx.x * 256 + threadIdx.x;
    int seg = 0;
    #pragma unroll
    for (int s = 0; s < 7; s++) seg += (i >= a.end4[s]) ? 1 : 0;
    int base = (seg == 0) ? 0 : a.end4[seg - 1];
    int li = i - base;
    float4 v = ((const float4*)a.src[seg])[li];
    uint2 o;
    o.x = pack_f16(v.x, v.y);
    o.y = pack_f16(v.z, v.w);
    ((uint2*)a.dst[seg])[li] = o;
}

// ---------------- fused LayerNorm + time-shift mix (fp16 outputs) ----------------
template<int NOUT>
__global__ __launch_bounds__(256) void ln_mix_kernel(const float* __restrict__ x,
                                                     const float* __restrict__ w,
                                                     const float* __restrict__ b,
                                                     const float* __restrict__ m0,
                                                     const float* __restrict__ m1,
                                                     const float* __restrict__ m2,
                                                     const float* __restrict__ m3,
                                                     __half* __restrict__ o0,
                                                     __half* __restrict__ o1,
                                                     __half* __restrict__ o2,
                                                     __half* __restrict__ o3)
{
    int row = blockIdx.x;
    int t = row % TT;
    int tid = threadIdx.x;
    size_t off = (size_t)row * CC;
    float4 cur = ((const float4*)(x + off))[tid];
    float4 prv = make_float4(0.f, 0.f, 0.f, 0.f);
    if (t > 0) prv = ((const float4*)(x + off - CC))[tid];

    float s0 = cur.x + cur.y + cur.z + cur.w;
    float q0 = cur.x*cur.x + cur.y*cur.y + cur.z*cur.z + cur.w*cur.w;
    float s1 = prv.x + prv.y + prv.z + prv.w;
    float q1 = prv.x*prv.x + prv.y*prv.y + prv.z*prv.z + prv.w*prv.w;
    #pragma unroll
    for (int o = 16; o >= 1; o >>= 1) {
        s0 += __shfl_xor_sync(0xffffffffu, s0, o);
        q0 += __shfl_xor_sync(0xffffffffu, q0, o);
        s1 += __shfl_xor_sync(0xffffffffu, s1, o);
        q1 += __shfl_xor_sync(0xffffffffu, q1, o);
    }
    __shared__ float red[4][8];
    int wid = tid >> 5, lane = tid & 31;
    if (lane == 0) { red[0][wid] = s0; red[1][wid] = q0; red[2][wid] = s1; red[3][wid] = q1; }
    __syncthreads();
    if (tid == 0) {
        float a0 = 0, a1 = 0, a2 = 0, a3 = 0;
        #pragma unroll
        for (int i = 0; i < 8; i++) { a0 += red[0][i]; a1 += red[1][i]; a2 += red[2][i]; a3 += red[3][i]; }
        red[0][0] = a0; red[1][0] = a1; red[2][0] = a2; red[3][0] = a3;
    }
    __syncthreads();
    float mu0 = red[0][0] * (1.0f / CC);
    float rs0 = rsqrtf(red[1][0] * (1.0f / CC) - mu0 * mu0 + EPS_LN);
    float mu1 = red[2][0] * (1.0f / CC);
    float rs1 = rsqrtf(red[3][0] * (1.0f / CC) - mu1 * mu1 + EPS_LN);

    float4 ww = ((const float4*)w)[tid];
    float4 bb = ((const float4*)b)[tid];
    float4 lc, lp;
    lc.x = (cur.x - mu0) * rs0 * ww.x + bb.x;
    lc.y = (cur.y - mu0) * rs0 * ww.y + bb.y;
    lc.z = (cur.z - mu0) * rs0 * ww.z + bb.z;
    lc.w = (cur.w - mu0) * rs0 * ww.w + bb.w;
    if (t > 0) {
        lp.x = (prv.x - mu1) * rs1 * ww.x + bb.x;
        lp.y = (prv.y - mu1) * rs1 * ww.y + bb.y;
        lp.z = (prv.z - mu1) * rs1 * ww.z + bb.z;
        lp.w = (prv.w - mu1) * rs1 * ww.w + bb.w;
    } else {
        lp = make_float4(0.f, 0.f, 0.f, 0.f);
    }
    float4 xx = make_float4(lp.x - lc.x, lp.y - lc.y, lp.z - lc.z, lp.w - lc.w);

    float4 a;
    uint2 o;
    a = ((const float4*)m0)[tid];
    o.x = pack_f16(lc.x + xx.x * a.x, lc.y + xx.y * a.y);
    o.y = pack_f16(lc.z + xx.z * a.z, lc.w + xx.w * a.w);
    ((uint2*)(o0 + off))[tid] = o;
    a = ((const float4*)m1)[tid];
    o.x = pack_f16(lc.x + xx.x * a.x, lc.y + xx.y * a.y);
    o.y = pack_f16(lc.z + xx.z * a.z, lc.w + xx.w * a.w);
    ((uint2*)(o1 + off))[tid] = o;
    if (NOUT == 4) {
        a = ((const float4*)m2)[tid];
        o.x = pack_f16(lc.x + xx.x * a.x, lc.y + xx.y * a.y);
        o.y = pack_f16(lc.z + xx.z * a.z, lc.w + xx.w * a.w);
        ((uint2*)(o2 + off))[tid] = o;
        a = ((const float4*)m3)[tid];
        o.x = pack_f16(lc.x + xx.x * a.x, lc.y + xx.y * a.y);
        o.y = pack_f16(lc.z + xx.z * a.z, lc.w + xx.w * a.w);
        ((uint2*)(o3 + off))[tid] = o;
    }
}

// ---------------- fp16 tensor-core GEMM core ----------------
#define STG_WORDS 9216
#define GEMM_SMEM (2 * STG_WORDS * 4)

__device__ __forceinline__ void mma_f16(float c[4],
                                        const uint32_t a[4],
                                        const uint32_t b[2])
{
    asm volatile(
        "mma.sync.aligned.m16n8k16.row.col.f32.f16.f16.f32 "
        "{%0,%1,%2,%3}, {%4,%5,%6,%7}, {%8,%9}, {%0,%1,%2,%3};\n"
        : "+f"(c[0]), "+f"(c[1]), "+f"(c[2]), "+f"(c[3])
        : "r"(a[0]), "r"(a[1]), "r"(a[2]), "r"(a[3]),
          "r"(b[0]), "r"(b[1]));
}

#define LDMATRIX_X4(r0, r1, r2, r3, addr) \
    asm volatile("ldmatrix.sync.aligned.m8n8.x4.shared.b16 {%0,%1,%2,%3}, [%4];" \
        : "=r"(r0), "=r"(r1), "=r"(r2), "=r"(r3) : "r"(addr))

__device__ __forceinline__ void gemm_mainloop(const __half* __restrict__ A,
                                              const __half* __restrict__ W,
                                              int K, int m0, int n0,
                                              uint32_t* smw, int tid,
                                              float acc[4][4][4])
{
    int lane = tid & 31;
    int j  = tid & 7;
    int r0 = tid >> 3;
    const __half* pA = A + ((size_t)m0 + r0) * K + j * 8;
    const __half* pW = W + ((size_t)n0 + r0) * K + j * 8;
    uint32_t smb = smem_u32(smw);
    uint32_t dstA = smb + (uint32_t)(r0 * 36 + j * 4) * 4u;
    uint32_t dstW = dstA + 4608u * 4u;
    int wid = tid >> 5;
    int wm = wid >> 2, wn = wid & 3;

    uint32_t aAddr[4], bAddr[2];
    #pragma unroll
    for (int mi = 0; mi < 4; mi++)
        aAddr[mi] = smb + (uint32_t)((wm * 64 + mi * 16 + (lane & 15)) * 36) * 4u
                        + (uint32_t)(lane >> 4) * 16u;
    #pragma unroll
    for (int p = 0; p < 2; p++)
        bAddr[p] = smb + 4608u * 4u
                 + (uint32_t)((wn * 32 + (p * 2 + (lane >> 4)) * 8 + (lane & 7)) * 36) * 4u
                 + (uint32_t)((lane >> 3) & 1) * 16u;

    int NC = K >> 6;

    #pragma unroll
    for (int s = 0; s < 2; s++) {
        uint32_t so = (uint32_t)(s * STG_WORDS) * 4u;
        int kf = s * 64;
        #pragma unroll
        for (int i = 0; i < 4; i++) {
            cp16(dstA + so + (uint32_t)(i * 32 * 36) * 4u, pA + (size_t)(i * 32) * K + kf);
            cp16(dstW + so + (uint32_t)(i * 32 * 36) * 4u, pW + (size_t)(i * 32) * K + kf);
        }
        CP_COMMIT();
    }

    for (int t = 0; t < NC; t++) {
        CP_WAIT_1();
        __syncthreads();
        uint32_t so = (uint32_t)((t & 1) * STG_WORDS) * 4u;

        #pragma unroll
        for (int kk = 0; kk < 4; kk++) {
            uint32_t ko = so + (uint32_t)kk * 32u;
            uint32_t af[4][4];
            uint32_t bf[4][2];
            #pragma unroll
            for (int mi = 0; mi < 4; mi++)
                LDMATRIX_X4(af[mi][0], af[mi][1], af[mi][2], af[mi][3], aAddr[mi] + ko);
            #pragma unroll
            for (int p = 0; p < 2; p++)
                LDMATRIX_X4(bf[2*p][0], bf[2*p][1], bf[2*p+1][0], bf[2*p+1][1], bAddr[p] + ko);
            #pragma unroll
            for (int mi = 0; mi < 4; mi++)
                #pragma unroll
                for (int ni = 0; ni < 4; ni++)
                    mma_f16(acc[mi][ni], af[mi], bf[ni]);
        }
        __syncthreads();

        int lc = t + 2;
        if (lc < NC) {
            uint32_t so2 = (uint32_t)((t & 1) * STG_WORDS) * 4u;
            int kf = lc * 64;
            #pragma unroll
            for (int i = 0; i < 4; i++) {
                cp16(dstA + so2 + (uint32_t)(i * 32 * 36) * 4u, pA + (size_t)(i * 32) * K + kf);
                cp16(dstW + so2 + (uint32_t)(i * 32 * 36) * 4u, pW + (size_t)(i * 32) * K + kf);
            }
        }
        CP_COMMIT();
    }
}

// epi codes: 0 plain f32, 2 relu^2 -> fp16, 4 +aux1 -> f32, 5 sigmoid -> fp16,
//            6 acc*auxh + aux1 -> f32 (final channel-mix output)
__global__ void __launch_bounds__(256, 2)
gemm_hf_kernel(const __half* __restrict__ A, const __half* __restrict__ W,
               float* __restrict__ Co, __half* __restrict__ Coh,
               int Nn, int K, int epi,
               const float* __restrict__ aux1, const __half* __restrict__ auxh)
{
    extern __shared__ uint32_t smw[];
    int tid = threadIdx.x;
    int n0 = blockIdx.x * 128;
    int m0 = blockIdx.y * 128;
    int wid = tid >> 5, lane = tid & 31;
    int wm = wid >> 2, wn = wid & 3;
    int gid = lane >> 2, tg = lane & 3;

    float acc[4][4][4];
    #pragma unroll
    for (int mi = 0; mi < 4; mi++)
        #pragma unroll
        for (int ni = 0; ni < 4; ni++)
            #pragma unroll
            for (int e = 0; e < 4; e++) acc[mi][ni][e] = 0.f;

    gemm_mainloop(A, W, K, m0, n0, smw, tid, acc);

    #pragma unroll
    for (int mi = 0; mi < 4; mi++) {
        int row0 = m0 + wm * 64 + mi * 16 + gid;
        #pragma unroll
        for (int ni = 0; ni < 4; ni++) {
            int col0 = n0 + wn * 32 + ni * 8 + tg * 2;
            size_t o0 = (size_t)row0 * Nn + col0;
            size_t o1 = (size_t)(row0 + 8) * Nn + col0;
            float a0 = acc[mi][ni][0], a1 = acc[mi][ni][1];
            float a2 = acc[mi][ni][2], a3 = acc[mi][ni][3];
            if (epi == 2) {
                a0 = fmaxf(a0, 0.f); a0 *= a0;
                a1 = fmaxf(a1, 0.f); a1 *= a1;
                a2 = fmaxf(a2, 0.f); a2 *= a2;
                a3 = fmaxf(a3, 0.f); a3 *= a3;
                *(uint32_t*)(Coh + o0) = pack_f16(a0, a1);
                *(uint32_t*)(Coh + o1) = pack_f16(a2, a3);
            } else if (epi == 5) {
                a0 = 1.f / (1.f + expf(-a0));
                a1 = 1.f / (1.f + expf(-a1));
                a2 = 1.f / (1.f + expf(-a2));
                a3 = 1.f / (1.f + expf(-a3));
                *(uint32_t*)(Coh + o0) = pack_f16(a0, a1);
                *(uint32_t*)(Coh + o1) = pack_f16(a2, a3);
            } else if (epi == 6) {
                float2 s0 = h2f(*(const uint32_t*)(auxh + o0));
                float2 s1 = h2f(*(const uint32_t*)(auxh + o1));
                float2 v0, v1;
                v0.x = a0 * s0.x + aux1[o0];
                v0.y = a1 * s0.y + aux1[o0 + 1];
                v1.x = a2 * s1.x + aux1[o1];
                v1.y = a3 * s1.y + aux1[o1 + 1];
                *(float2*)(Co + o0) = v0;
                *(float2*)(Co + o1) = v1;
            } else {
                if (epi == 4) {
                    a0 += aux1[o0]; a1 += aux1[o0 + 1];
                    a2 += aux1[o1]; a3 += aux1[o1 + 1];
                }
                *(float2*)(Co + o0) = make_float2(a0, a1);
                *(float2*)(Co + o1) = make_float2(a2, a3);
            }
        }
    }
}

// merged 4-GEMM kernel for tmix
struct Gemm4Args {
    const __half* A[4];
    const __half* W[4];
    __half* O[4];
    int silu[4];
};
__global__ void __launch_bounds__(256, 2)
gemm_hf4_kernel(Gemm4Args args)
{
    extern __shared__ uint32_t smw[];
    int z = blockIdx.z;
    const __half* A = args.A[z];
    const __half* W = args.W[z];
    __half* O = args.O[z];
    int silu = args.silu[z];

    int tid = threadIdx.x;
    int n0 = blockIdx.x * 128;
    int m0 = blockIdx.y * 128;
    int wid = tid >> 5, lane = tid & 31;
    int wm = wid >> 2, wn = wid & 3;
    int gid = lane >> 2, tg = lane & 3;

    float acc[4][4][4];
    #pragma unroll
    for (int mi = 0; mi < 4; mi++)
        #pragma unroll
        for (int ni = 0; ni < 4; ni++)
            #pragma unroll
            for (int e = 0; e < 4; e++) acc[mi][ni][e] = 0.f;

    gemm_mainloop(A, W, 1024, m0, n0, smw, tid, acc);

    #pragma unroll
    for (int mi = 0; mi < 4; mi++) {
        int row0 = m0 + wm * 64 + mi * 16 + gid;
        #pragma unroll
        for (int ni = 0; ni < 4; ni++) {
            int col0 = n0 + wn * 32 + ni * 8 + tg * 2;
            size_t o0 = (size_t)row0 * 1024 + col0;
            size_t o1 = (size_t)(row0 + 8) * 1024 + col0;
            float a0 = acc[mi][ni][0], a1 = acc[mi][ni][1];
            float a2 = acc[mi][ni][2], a3 = acc[mi][ni][3];
            if (silu) {
                a0 = a0 / (1.f + expf(-a0));
                a1 = a1 / (1.f + expf(-a1));
                a2 = a2 / (1.f + expf(-a2));
                a3 = a3 / (1.f + expf(-a3));
            }
            *(uint32_t*)(O + o0) = pack_f16(a0, a1);
            *(uint32_t*)(O + o1) = pack_f16(a2, a3);
        }
    }
}

// merged channel-mix pair: z=0 Wck (relu^2 -> hb, N=3072), z=1 Wcr (sigmoid -> sig, N=1024)
struct GemmCM2Args {
    const __half* A[2];
    const __half* W[2];
    __half* O[2];
    int Nn[2];
};
__global__ void __launch_bounds__(256, 2)
gemm_cm2_kernel(GemmCM2Args args)
{
    extern __shared__ uint32_t smw[];
    int z = blockIdx.z;
    int Nn = args.Nn[z];
    if (blockIdx.x * 128 >= Nn) return;     // z=1 uses only 8 of 24 x-blocks
    const __half* A = args.A[z];
    const __half* W = args.W[z];
    __half* O = args.O[z];

    int tid = threadIdx.x;
    int n0 = blockIdx.x * 128;
    int m0 = blockIdx.y * 128;
    int wid = tid >> 5, lane = tid & 31;
    int wm = wid >> 2, wn = wid & 3;
    int gid = lane >> 2, tg = lane & 3;

    float acc[4][4][4];
    #pragma unroll
    for (int mi = 0; mi < 4; mi++)
        #pragma unroll
        for (int ni = 0; ni < 4; ni++)
            #pragma unroll
            for (int e = 0; e < 4; e++) acc[mi][ni][e] = 0.f;

    gemm_mainloop(A, W, 1024, m0, n0, smw, tid, acc);

    #pragma unroll
    for (int mi = 0; mi < 4; mi++) {
        int row0 = m0 + wm * 64 + mi * 16 + gid;
        #pragma unroll
        for (int ni = 0; ni < 4; ni++) {
            int col0 = n0 + wn * 32 + ni * 8 + tg * 2;
            size_t o0 = (size_t)row0 * Nn + col0;
            size_t o1 = (size_t)(row0 + 8) * Nn + col0;
            float a0 = acc[mi][ni][0], a1 = acc[mi][ni][1];
            float a2 = acc[mi][ni][2], a3 = acc[mi][ni][3];
            if (z == 0) {
                a0 = fmaxf(a0, 0.f); a0 *= a0;
                a1 = fmaxf(a1, 0.f); a1 *= a1;
                a2 = fmaxf(a2, 0.f); a2 *= a2;
                a3 = fmaxf(a3, 0.f); a3 *= a3;
            } else {
                a0 = 1.f / (1.f + expf(-a0));
                a1 = 1.f / (1.f + expf(-a1));
                a2 = 1.f / (1.f + expf(-a2));
                a3 = 1.f / (1.f + expf(-a3));
            }
            *(uint32_t*)(O + o0) = pack_f16(a0, a1);
            *(uint32_t*)(O + o1) = pack_f16(a2, a3);
        }
    }
}

// ---------------- WKV: per-subchunk contributions + chunk state ----------------
__global__ __launch_bounds__(256) void wkv_s_kernel(const __half* __restrict__ k,
                                                    const __half* __restrict__ v,
                                                    const float* __restrict__ decay,
                                                    float* __restrict__ S,
                                                    float* __restrict__ C)
{
    int blk = blockIdx.x;
    int c = blk % NCK;
    int h = (blk / NCK) % HH;
    int b = blk / (NCK * HH);
    __shared__ float ksm[64][64];
    __shared__ float vsm[64][64];
    __shared__ float wpow[128];
    int tid = threadIdx.x;
    float ew = expf(decay[h]);
    if (tid < 128) wpow[tid] = expf(-ew * (float)tid);
    int n0 = (tid >> 4) * 4;
    int m0 = (tid & 15) * 4;
    uint64_t Sacc[4][2];
    #pragma unroll
    for (int i = 0; i < 4; i++) { Sacc[i][0] = 0; Sacc[i][1] = 0; }

    size_t base = ((size_t)b * TT + (size_t)c * QQ) * CC + (size_t)h * NHD;
    float w64 = 0.f;

    for (int qc = 0; qc < 4; qc++) {
        __syncthreads();
        for (int l = tid; l < 64 * 16; l += 256) {
            int qq = l >> 4;
            int f  = (l & 15) * 4;
            uint2 kk = *(const uint2*)(k + base + (size_t)(qc * 64 + qq) * CC + f);
            uint2 vv = *(const uint2*)(v + base + (size_t)(qc * 64 + qq) * CC + f);
            float2 ka = h2f(kk.x), kb2 = h2f(kk.y);
            float2 va = h2f(vv.x), vb2 = h2f(vv.y);
            ksm[qq][f] = ka.x; ksm[qq][f+1] = ka.y; ksm[qq][f+2] = kb2.x; ksm[qq][f+3] = kb2.y;
            vsm[qq][f] = va.x; vsm[qq][f+1] = va.y; vsm[qq][f+2] = vb2.x; vsm[qq][f+3] = vb2.y;
        }
        __syncthreads();
        if (qc == 0) w64 = wpow[64];

        uint64_t acc2[4][2];
        #pragma unroll
        for (int i = 0; i < 4; i++) { acc2[i][0] = 0; acc2[i][1] = 0; }

        #pragma unroll 4
        for (int jl = 0; jl < 64; jl++) {
            float wq = wpow[63 - jl];
            float4 kk = *(const float4*)&ksm[jl][n0];
            ulonglong2 vp = *(const ulonglong2*)&vsm[jl][m0];
            uint64_t kb0 = bcast2(kk.x * wq);
            uint64_t kb1 = bcast2(kk.y * wq);
            uint64_t kb2 = bcast2(kk.z * wq);
            uint64_t kb3 = bcast2(kk.w * wq);
            fma2(acc2[0][0], kb0, vp.x); fma2(acc2[0][1], kb0, vp.y);
            fma2(acc2[1][0], kb1, vp.x); fma2(acc2[1][1], kb1, vp.y);
            fma2(acc2[2][0], kb2, vp.x); fma2(acc2[2][1], kb2, vp.y);
            fma2(acc2[3][0], kb3, vp.x); fma2(acc2[3][1], kb3, vp.y);
        }

        uint64_t wb = bcast2(w64);
        #pragma unroll
        for (int i = 0; i < 4; i++) {
            fma2w(Sacc[i][0], wb, acc2[i][0]);
            fma2w(Sacc[i][1], wb, acc2[i][1]);
        }

        if (qc < 3) {
            float* Cp = C + (size_t)blk * 12288 + (size_t)qc * 4096;
            #pragma unroll
            for (int i = 0; i < 4; i++) {
                float2 p0 = unpk2(acc2[i][0]);
                float2 p1 = unpk2(acc2[i][1]);
                *(float4*)(Cp + (n0 + i) * 64 + m0) = make_float4(p0.x, p0.y, p1.x, p1.y);
            }
        }
    }

    float* Sp = S + (size_t)blk * 4096;
    #pragma unroll
    for (int i = 0; i < 4; i++) {
        float2 p0 = unpk2(Sacc[i][0]);
        float2 p1 = unpk2(Sacc[i][1]);
        *(float4*)(Sp + (n0 + i) * 64 + m0) = make_float4(p0.x, p0.y, p1.x, p1.y);
    }
}

// ---------------- WKV: inter-chunk prefix scan (wide grid) ----------------
__global__ __launch_bounds__(256) void wkv_scan_kernel(const float* __restrict__ S,
                                                       const float* __restrict__ decay,
                                                       float* __restrict__ ST)
{
    int bh = blockIdx.x >> 4;
    int part = blockIdx.x & 15;
    int h = bh % HH;
    float ws = expf(-expf(decay[h]) * 256.0f);
    int e = part * 256 + threadIdx.x;
    size_t b0 = (size_t)bh * NCK * 4096;
    float st = 0.f;
    #pragma unroll
    for (int c = 0; c < NCK; c++) {
        ST[b0 + (size_t)c * 4096 + e] = st;
        st = ws * st + S[b0 + (size_t)c * 4096 + e];
    }
}

// ---------------- WKV: per-chunk output + fused GroupNorm*g (fp16 out) ----------------
#define WKV_Y_SMEM ((16384 + 16384 + 16384 + 256 + 128) * 4)
__global__ __launch_bounds__(256) void wkv_y_kernel(const __half* __restrict__ r,
                                                    const __half* __restrict__ k,
                                                    const __half* __restrict__ v,
                                                    const float* __restrict__ ST,
                                                    const float* __restrict__ C,
                                                    const float* __restrict__ decay,
                                                    const float* __restrict__ faaaa,
                                                    const float* __restrict__ gnw,
                                                    const float* __restrict__ gnb,
                                                    const __half* __restrict__ g,
                                                    __half* __restrict__ yg)
{
    extern __shared__ float sm[];
    float* ksm  = sm;
    float* vsm  = sm + 16384;
    float* sst  = sm + 32768;
    float* wpow = sm + 49152;
    float* gnsm = sm + 49408;

    int blk = blockIdx.x;
    int c = blk % NCK;
    int h = (blk / NCK) % HH;
    int b = blk / (NCK * HH);
    int tid = threadIdx.x;

    float ew = expf(decay[h]);
    float u  = faaaa[h];
    wpow[tid] = expf(-ew * (float)tid);
    if (tid < 64) gnsm[tid] = gnw[h * 64 + tid];
    else if (tid < 128) gnsm[tid] = gnb[h * 64 + tid - 64];

    size_t base = ((size_t)b * TT + (size_t)c * QQ) * CC + (size_t)h * NHD;

    for (int l = tid; l < 256 * 16; l += 256) {
        int qq = l >> 4;
        int f  = (l & 15) * 4;
        uint2 kk = *(const uint2*)(k + base + (size_t)qq * CC + f);
        uint2 vv = *(const uint2*)(v + base + (size_t)qq * CC + f);
        float2 ka = h2f(kk.x), kb2 = h2f(kk.y);
        float2 va = h2f(vv.x), vb2 = h2f(vv.y);
        ksm[qq * 64 + f] = ka.x; ksm[qq * 64 + f + 1] = ka.y;
        ksm[qq * 64 + f + 2] = kb2.x; ksm[qq * 64 + f + 3] = kb2.y;
        vsm[qq * 64 + f] = va.x; vsm[qq * 64 + f + 1] = va.y;
        vsm[qq * 64 + f + 2] = vb2.x; vsm[qq * 64 + f + 3] = vb2.y;
    }
    size_t sbase = (size_t)blk * 4096;
    for (int l = tid; l < 1024; l += 256)
        *(float4*)&sst[l * 4] = *(const float4*)(ST + sbase + (size_t)l * 4);
    __syncthreads();

    // build sub-chunk states
    {
        float w64v = wpow[64];
        const float* Cp = C + (size_t)blk * 12288;
        #pragma unroll
        for (int s = 1; s < 4; s++) {
            for (int l = tid; l < 1024; l += 256) {
                float4 p4 = *(const float4*)&sst[(s - 1) * 4096 + l * 4];
                float4 c4 = *(const float4*)(Cp + (size_t)(s - 1) * 4096 + l * 4);
                float4 o4 = make_float4(w64v * p4.x + c4.x, w64v * p4.y + c4.y,
                                        w64v * p4.z + c4.z, w64v * p4.w + c4.w);
                *(float4*)&sst[s * 4096 + l * 4] = o4;
            }
        }
    }
    __syncthreads();

    int q  = tid;
    int qs = q >> 6;
    int ql = q & 63;
    float rrow[64];
    {
        const uint4* rg = (const uint4*)(r + base + (size_t)q * CC);
        #pragma unroll
        for (int f = 0; f < 8; f++) {
            uint4 t4 = rg[f];
            float2 p0 = h2f(t4.x), p1 = h2f(t4.y), p2 = h2f(t4.z), p3 = h2f(t4.w);
            rrow[f * 8 + 0] = p0.x; rrow[f * 8 + 1] = p0.y;
            rrow[f * 8 + 2] = p1.x; rrow[f * 8 + 3] = p1.y;
            rrow[f * 8 + 4] = p2.x; rrow[f * 8 + 5] = p2.y;
            rrow[f * 8 + 6] = p3.x; rrow[f * 8 + 7] = p3.y;
        }
    }
    uint64_t acc2[32];
    #pragma unroll
    for (int m = 0; m < 32; m++) acc2[m] = 0;

    const float* stq = sst + qs * 4096;
    #pragma unroll 8
    for (int n = 0; n < 64; n++) {
        uint64_t rb = bcast2(rrow[n]);
        const ulonglong2* srow = (const ulonglong2*)&stq[n * 64];
        #pragma unroll
        for (int m2 = 0; m2 < 16; m2++) {
            ulonglong2 s2 = srow[m2];
            fma2(acc2[2 * m2],     rb, s2.x);
            fma2(acc2[2 * m2 + 1], rb, s2.y);
        }
    }
    {
        uint64_t wb = bcast2(wpow[ql]);
        #pragma unroll
        for (int m = 0; m < 32; m++) mul2(acc2[m], wb);
    }

    int j0 = qs * 64;
    int jend = ql | 31;
    for (int jl = 0; jl <= jend; jl++) {
        float a = 0.f;
        const float4* krow = (const float4*)&ksm[(j0 + jl) * 64];
        #pragma unroll
        for (int n4 = 0; n4 < 16; n4++) {
            float4 k4 = krow[n4];
            a += rrow[n4 * 4 + 0] * k4.x + rrow[n4 * 4 + 1] * k4.y
               + rrow[n4 * 4 + 2] * k4.z + rrow[n4 * 4 + 3] * k4.w;
        }
        float coef = (jl < ql) ? wpow[ql - jl - 1] : ((jl == ql) ? u : 0.0f);
        uint64_t ab = bcast2(a * coef);
        const ulonglong2* vrow = (const ulonglong2*)&vsm[(j0 + jl) * 64];
        #pragma unroll
        for (int m2 = 0; m2 < 16; m2++) {
            ulonglong2 v2 = vrow[m2];
            fma2(acc2[2 * m2],     ab, v2.x);
            fma2(acc2[2 * m2 + 1], ab, v2.y);
        }
    }

    // fused GroupNorm * g -> fp16
    float yv[64];
    float ssum = 0.f, ssq = 0.f;
    #pragma unroll
    for (int m = 0; m < 32; m++) {
        float2 p = unpk2(acc2[m]);
        yv[2 * m] = p.x; yv[2 * m + 1] = p.y;
        ssum += p.x + p.y;
        ssq  += p.x * p.x + p.y * p.y;
    }
    float mu   = ssum * (1.0f / 64.0f);
    float var  = ssq * (1.0f / 64.0f) - mu * mu;
    float rstd = rsqrtf(var + EPS_GN);

    __half* yo = yg + base + (size_t)q * CC;
    const uint2* gg = (const uint2*)(g + base + (size_t)q * CC);
    #pragma unroll
    for (int m4 = 0; m4 < 16; m4++) {
        uint2 g2 = gg[m4];
        float2 g0 = h2f(g2.x), g1 = h2f(g2.y);
        float o0 = ((yv[m4 * 4 + 0] - mu) * rstd * gnsm[m4 * 4 + 0] + gnsm[64 + m4 * 4 + 0]) * g0.x;
        float o1 = ((yv[m4 * 4 + 1] - mu) * rstd * gnsm[m4 * 4 + 1] + gnsm[64 + m4 * 4 + 1]) * g0.y;
        float o2 = ((yv[m4 * 4 + 2] - mu) * rstd * gnsm[m4 * 4 + 2] + gnsm[64 + m4 * 4 + 2]) * g1.x;
        float o3 = ((yv[m4 * 4 + 3] - mu) * rstd * gnsm[m4 * 4 + 3] + gnsm[64 + m4 * 4 + 3]) * g1.y;
        uint2 ow;
        ow.x = pack_f16(o0, o1);
        ow.y = pack_f16(o2, o3);
        *(uint2*)(yo + m4 * 4) = ow;
    }
}

// ---------------- host launcher ----------------
extern "C" void kernel_launch(void* const* d_in, const int* in_sizes, int n_in,
                              void* d_out, int out_size)
{
    const float* x      = (const float*)d_in[0];
    const float* ln1w   = (const float*)d_in[1];
    const float* ln1b   = (const float*)d_in[2];
    const float* maak   = (const float*)d_in[3];
    const float* maav   = (const float*)d_in[4];
    const float* maar   = (const float*)d_in[5];
    const float* maag   = (const float*)d_in[6];
    const float* decay  = (const float*)d_in[7];
    const float* faaaa  = (const float*)d_in[8];
    const float* Wr     = (const float*)d_in[9];
    const float* Wk     = (const float*)d_in[10];
    const float* Wv     = (const float*)d_in[11];
    const float* Wg     = (const float*)d_in[12];
    const float* Wo     = (const float*)d_in[13];
    const float* gnw    = (const float*)d_in[14];
    const float* gnb    = (const float*)d_in[15];
    const float* ln2w   = (const float*)d_in[16];
    const float* ln2b   = (const float*)d_in[17];
    const float* cmaak  = (const float*)d_in[18];
    const float* cmaar  = (const float*)d_in[19];
    const float* Wck    = (const float*)d_in[20];
    const float* Wcv    = (const float*)d_in[21];
    const float* Wcr    = (const float*)d_in[22];
    float* out = (float*)d_out;

    float* sc = nullptr;
    cudaGetSymbolAddress((void**)&sc, g_scratch);

    __half* xk   = (__half*)(sc + OFF_XK);
    __half* xv   = (__half*)(sc + OFF_XV);
    __half* xr   = (__half*)(sc + OFF_XR);
    __half* xg   = (__half*)(sc + OFF_XG);
    __half* rb   = (__half*)(sc + OFF_R);
    __half* kb   = (__half*)(sc + OFF_K);
    __half* vb   = (__half*)(sc + OFF_V);
    __half* gb   = (__half*)(sc + OFF_G);
    __half* ygb = (__half*)(sc + OFF_YG);
    float* x1   = sc + OFF_X1;
    __half* xk2 = (__half*)(sc + OFF_XK2);
    __half* xr2 = (__half*)(sc + OFF_XR2);
    __half* sig = (__half*)(sc + OFF_SIG);
    __half* hb  = (__half*)(sc + OFF_H);
    float* Sb   = sc + OFF_S;
    float* STb  = sc + OFF_ST;
    float* Cb   = sc + OFF_C;
    __half* WrR  = (__half*)(sc + OFF_WR_R);
    __half* WkR  = (__half*)(sc + OFF_WK_R);
    __half* WvR  = (__half*)(sc + OFF_WV_R);
    __half* WgR  = (__half*)(sc + OFF_WG_R);
    __half* WoR  = (__half*)(sc + OFF_WO_R);
    __half* WcrR = (__half*)(sc + OFF_WCR_R);
    __half* WckR = (__half*)(sc + OFF_WCK_R);
    __half* WcvR = (__half*)(sc + OFF_WCV_R);

    cudaFuncSetAttribute(wkv_y_kernel, cudaFuncAttributeMaxDynamicSharedMemorySize, WKV_Y_SMEM);
    cudaFuncSetAttribute(gemm_hf_kernel, cudaFuncAttributeMaxDynamicSharedMemorySize, GEMM_SMEM);
    cudaFuncSetAttribute(gemm_hf4_kernel, cudaFuncAttributeMaxDynamicSharedMemorySize, GEMM_SMEM);
    cudaFuncSetAttribute(gemm_cm2_kernel, cudaFuncAttributeMaxDynamicSharedMemorySize, GEMM_SMEM);

    dim3 g1024(1024 / 128, MTOT / 128);
    dim3 g1024z4(1024 / 128, MTOT / 128, 4);
    dim3 gcm2(3072 / 128, MTOT / 128, 2);

    // ---- weight conversion: single launch ----
    {
        CvtArgs ca;
        const float* srcs[8] = {Wr, Wk, Wv, Wg, Wo, Wcr, Wck, Wcv};
        __half* dsts[8] = {WrR, WkR, WvR, WgR, WoR, WcrR, WckR, WcvR};
        int sz4[8] = {262144, 262144, 262144, 262144, 262144, 262144, 786432, 786432};
        int acc4 = 0;
        for (int i = 0; i < 8; i++) { ca.src[i] = srcs[i]; ca.dst[i] = dsts[i]; acc4 += sz4[i]; ca.end4[i] = acc4; }
        cvt_all_kernel<<<acc4 / 256, 256>>>(ca);
    }

    // ---- time mix ----
    ln_mix_kernel<4><<<MTOT, 256>>>(x, ln1w, ln1b, maak, maav, maar, maag, xk, xv, xr, xg);
    {
        Gemm4Args ga;
        ga.A[0] = xr; ga.W[0] = WrR; ga.O[0] = rb; ga.silu[0] = 0;
        ga.A[1] = xk; ga.W[1] = WkR; ga.O[1] = kb; ga.silu[1] = 0;
        ga.A[2] = xv; ga.W[2] = WvR; ga.O[2] = vb; ga.silu[2] = 0;
        ga.A[3] = xg; ga.W[3] = WgR; ga.O[3] = gb; ga.silu[3] = 1;
        gemm_hf4_kernel<<<g1024z4, 256, GEMM_SMEM>>>(ga);
    }

    wkv_s_kernel<<<BB * HH * NCK, 256>>>(kb, vb, decay, Sb, Cb);
    wkv_scan_kernel<<<BB * HH * 16, 256>>>(Sb, decay, STb);
    wkv_y_kernel<<<BB * HH * NCK, 256, WKV_Y_SMEM>>>(rb, kb, vb, STb, Cb, decay, faaaa,
                                                     gnw, gnb, gb, ygb);

    gemm_hf_kernel<<<g1024, 256, GEMM_SMEM>>>(ygb, WoR, x1, nullptr, 1024, 1024, 4, x, nullptr); // + residual

    // ---- channel mix ----
    ln_mix_kernel<2><<<MTOT, 256>>>(x1, ln2w, ln2b, cmaak, cmaar, nullptr, nullptr,
                                    xk2, xr2, nullptr, nullptr);
    {
        GemmCM2Args gc;
        gc.A[0] = xk2; gc.W[0] = WckR; gc.O[0] = hb;  gc.Nn[0] = 3072;  // relu^2
        gc.A[1] = xr2; gc.W[1] = WcrR; gc.O[1] = sig; gc.Nn[1] = 1024;  // sigmoid
        gemm_cm2_kernel<<<gcm2, 256, GEMM_SMEM>>>(gc);
    }
    gemm_hf_kernel<<<g1024, 256, GEMM_SMEM>>>(hb, WcvR, out, nullptr, 1024, 3072, 6, x1, sig); // sig*acc + x1
}

// round 16
// speedup vs baseline: 1.4456x; 1.0017x over previous
#include <cuda_runtime.h>
#include <cuda_fp16.h>
#include <math.h>
#include <stdint.h>

// ---------------- problem constants ----------------
#define BB 4
#define TT 4096
#define CC 1024
#define HH 16
#define NHD 64
#define QQ 256
#define NCK 16
#define MTOT (BB*TT)          // 16384
#define BTC (BB*TT*CC)        // 16777216
#define EPS_LN 1e-5f
#define EPS_GN (1e-5f*64.0f)

// ---------------- scratch ----------------
#define SCR_TOTAL (19ull*BTC + 8388608ull + 12582912ull + 12582912ull)
__device__ float g_scratch[SCR_TOTAL];

#define OFF_XK   (1ull*BTC)      // fp16
#define OFF_XV   (2ull*BTC)
#define OFF_XR   (3ull*BTC)
#define OFF_XG   (4ull*BTC)
#define OFF_R    (5ull*BTC)      // fp16
#define OFF_K    (6ull*BTC)      // fp16
#define OFF_V    (7ull*BTC)      // fp16
#define OFF_G    (8ull*BTC)      // fp16
#define OFF_YG   (10ull*BTC)     // fp16
#define OFF_X1   (11ull*BTC)     // fp16 now
#define OFF_XK2  (13ull*BTC)     // fp16
#define OFF_XR2  (14ull*BTC)     // fp16
#define OFF_SIG  (15ull*BTC)     // fp16
#define OFF_H    (16ull*BTC)     // fp16 [16384,3072]
#define OFF_S    (19ull*BTC)
#define OFF_ST   (19ull*BTC + 4194304ull)
#define OFF_C    (19ull*BTC + 8388608ull)
#define OFF_WT   (19ull*BTC + 8388608ull + 12582912ull)
#define OFF_WR_R  (OFF_WT + 0ull)
#define OFF_WK_R  (OFF_WT + 1048576ull)
#define OFF_WV_R  (OFF_WT + 2097152ull)
#define OFF_WG_R  (OFF_WT + 3145728ull)
#define OFF_WO_R  (OFF_WT + 4194304ull)
#define OFF_WCR_R (OFF_WT + 5242880ull)
#define OFF_WCK_R (OFF_WT + 6291456ull)
#define OFF_WCV_R (OFF_WT + 9437184ull)

// ---------------- helpers ----------------
__device__ __forceinline__ uint32_t smem_u32(const void* p) {
    uint32_t a;
    asm("{ .reg .u64 t; cvta.to.shared.u64 t, %1; cvt.u32.u64 %0, t; }" : "=r"(a) : "l"(p));
    return a;
}

__device__ __forceinline__ uint32_t pack_f16(float a, float b) {
    __half2 h = __floats2half2_rn(a, b);
    return *(uint32_t*)&h;
}

__device__ __forceinline__ float2 h2f(uint32_t h) {
    __half2 v = *(__half2*)&h;
    return __half22float2(v);
}

// ---- packed f32x2 math ----
__device__ __forceinline__ uint64_t bcast2(float s) {
    uint64_t r;
    asm("mov.b64 %0, {%1, %1};" : "=l"(r) : "r"(__float_as_uint(s)));
    return r;
}
__device__ __forceinline__ void fma2(uint64_t& d, uint64_t a, uint64_t b) {
    asm("fma.rn.f32x2 %0, %1, %2, %0;" : "+l"(d) : "l"(a), "l"(b));
}
__device__ __forceinline__ void fma2w(uint64_t& d, uint64_t w, uint64_t c) {
    asm("fma.rn.f32x2 %0, %0, %1, %2;" : "+l"(d) : "l"(w), "l"(c));
}
__device__ __forceinline__ void mul2(uint64_t& d, uint64_t b) {
    asm("mul.rn.f32x2 %0, %0, %1;" : "+l"(d) : "l"(b));
}
__device__ __forceinline__ float2 unpk2(uint64_t v) {
    float lo, hi;
    asm("mov.b64 {%0, %1}, %2;" : "=f"(lo), "=f"(hi) : "l"(v));
    return make_float2(lo, hi);
}

__device__ __forceinline__ void cp16(uint32_t dst, const void* src) {
    asm volatile("cp.async.cg.shared.global [%0], [%1], 16;" :: "r"(dst), "l"(src) : "memory");
}
#define CP_COMMIT() asm volatile("cp.async.commit_group;" ::: "memory")
#define CP_WAIT_1() asm volatile("cp.async.wait_group 1;" ::: "memory")

// ---------------- all-weight fp32 -> fp16 (single launch) ----------------
struct CvtArgs {
    const float* src[8];
    __half* dst[8];
    int end4[8];
};
__global__ __launch_bounds__(256) void cvt_all_kernel(CvtArgs a)
{
    int i = blockIdx.x * 256 + threadIdx.x;
    int seg = 0;
    #pragma unroll
    for (int s = 0; s < 7; s++) seg += (i >= a.end4[s]) ? 1 : 0;
    int base = (seg == 0) ? 0 : a.end4[seg - 1];
    int li = i - base;
    float4 v = ((const float4*)a.src[seg])[li];
    uint2 o;
    o.x = pack_f16(v.x, v.y);
    o.y = pack_f16(v.z, v.w);
    ((uint2*)a.dst[seg])[li] = o;
}

// ---------------- fused LayerNorm + time-shift mix (fp32 input) ----------------
template<int NOUT>
__global__ __launch_bounds__(256) void ln_mix_kernel(const float* __restrict__ x,
                                                     const float* __restrict__ w,
                                                     const float* __restrict__ b,
                                                     const float* __restrict__ m0,
                                                     const float* __restrict__ m1,
                                                     const float* __restrict__ m2,
                                                     const float* __restrict__ m3,
                                                     __half* __restrict__ o0,
                                                     __half* __restrict__ o1,
                                                     __half* __restrict__ o2,
                                                     __half* __restrict__ o3)
{
    int row = blockIdx.x;
    int t = row % TT;
    int tid = threadIdx.x;
    size_t off = (size_t)row * CC;
    float4 cur = ((const float4*)(x + off))[tid];
    float4 prv = make_float4(0.f, 0.f, 0.f, 0.f);
    if (t > 0) prv = ((const float4*)(x + off - CC))[tid];

    float s0 = cur.x + cur.y + cur.z + cur.w;
    float q0 = cur.x*cur.x + cur.y*cur.y + cur.z*cur.z + cur.w*cur.w;
    float s1 = prv.x + prv.y + prv.z + prv.w;
    float q1 = prv.x*prv.x + prv.y*prv.y + prv.z*prv.z + prv.w*prv.w;
    #pragma unroll
    for (int o = 16; o >= 1; o >>= 1) {
        s0 += __shfl_xor_sync(0xffffffffu, s0, o);
        q0 += __shfl_xor_sync(0xffffffffu, q0, o);
        s1 += __shfl_xor_sync(0xffffffffu, s1, o);
        q1 += __shfl_xor_sync(0xffffffffu, q1, o);
    }
    __shared__ float red[4][8];
    int wid = tid >> 5, lane = tid & 31;
    if (lane == 0) { red[0][wid] = s0; red[1][wid] = q0; red[2][wid] = s1; red[3][wid] = q1; }
    __syncthreads();
    if (tid == 0) {
        float a0 = 0, a1 = 0, a2 = 0, a3 = 0;
        #pragma unroll
        for (int i = 0; i < 8; i++) { a0 += red[0][i]; a1 += red[1][i]; a2 += red[2][i]; a3 += red[3][i]; }
        red[0][0] = a0; red[1][0] = a1; red[2][0] = a2; red[3][0] = a3;
    }
    __syncthreads();
    float mu0 = red[0][0] * (1.0f / CC);
    float rs0 = rsqrtf(red[1][0] * (1.0f / CC) - mu0 * mu0 + EPS_LN);
    float mu1 = red[2][0] * (1.0f / CC);
    float rs1 = rsqrtf(red[3][0] * (1.0f / CC) - mu1 * mu1 + EPS_LN);

    float4 ww = ((const float4*)w)[tid];
    float4 bb = ((const float4*)b)[tid];
    float4 lc, lp;
    lc.x = (cur.x - mu0) * rs0 * ww.x + bb.x;
    lc.y = (cur.y - mu0) * rs0 * ww.y + bb.y;
    lc.z = (cur.z - mu0) * rs0 * ww.z + bb.z;
    lc.w = (cur.w - mu0) * rs0 * ww.w + bb.w;
    if (t > 0) {
        lp.x = (prv.x - mu1) * rs1 * ww.x + bb.x;
        lp.y = (prv.y - mu1) * rs1 * ww.y + bb.y;
        lp.z = (prv.z - mu1) * rs1 * ww.z + bb.z;
        lp.w = (prv.w - mu1) * rs1 * ww.w + bb.w;
    } else {
        lp = make_float4(0.f, 0.f, 0.f, 0.f);
    }
    float4 xx = make_float4(lp.x - lc.x, lp.y - lc.y, lp.z - lc.z, lp.w - lc.w);

    float4 a;
    uint2 o;
    a = ((const float4*)m0)[tid];
    o.x = pack_f16(lc.x + xx.x * a.x, lc.y + xx.y * a.y);
    o.y = pack_f16(lc.z + xx.z * a.z, lc.w + xx.w * a.w);
    ((uint2*)(o0 + off))[tid] = o;
    a = ((const float4*)m1)[tid];
    o.x = pack_f16(lc.x + xx.x * a.x, lc.y + xx.y * a.y);
    o.y = pack_f16(lc.z + xx.z * a.z, lc.w + xx.w * a.w);
    ((uint2*)(o1 + off))[tid] = o;
    if (NOUT == 4) {
        a = ((const float4*)m2)[tid];
        o.x = pack_f16(lc.x + xx.x * a.x, lc.y + xx.y * a.y);
        o.y = pack_f16(lc.z + xx.z * a.z, lc.w + xx.w * a.w);
        ((uint2*)(o2 + off))[tid] = o;
        a = ((const float4*)m3)[tid];
        o.x = pack_f16(lc.x + xx.x * a.x, lc.y + xx.y * a.y);
        o.y = pack_f16(lc.z + xx.z * a.z, lc.w + xx.w * a.w);
        ((uint2*)(o3 + off))[tid] = o;
    }
}

// ---------------- fused LayerNorm + time-shift mix (fp16 input, 2 outputs) ----------------
__global__ __launch_bounds__(256) void ln_mix_h_kernel(const __half* __restrict__ x,
                                                       const float* __restrict__ w,
                                                       const float* __restrict__ b,
                                                       const float* __restrict__ m0,
                                                       const float* __restrict__ m1,
                                                       __half* __restrict__ o0,
                                                       __half* __restrict__ o1)
{
    int row = blockIdx.x;
    int t = row % TT;
    int tid = threadIdx.x;
    size_t off = (size_t)row * CC;
    uint2 c2 = ((const uint2*)(x + off))[tid];
    float2 ca = h2f(c2.x), cb = h2f(c2.y);
    float4 cur = make_float4(ca.x, ca.y, cb.x, cb.y);
    float4 prv = make_float4(0.f, 0.f, 0.f, 0.f);
    if (t > 0) {
        uint2 p2 = ((const uint2*)(x + off - CC))[tid];
        float2 pa = h2f(p2.x), pb = h2f(p2.y);
        prv = make_float4(pa.x, pa.y, pb.x, pb.y);
    }

    float s0 = cur.x + cur.y + cur.z + cur.w;
    float q0 = cur.x*cur.x + cur.y*cur.y + cur.z*cur.z + cur.w*cur.w;
    float s1 = prv.x + prv.y + prv.z + prv.w;
    float q1 = prv.x*prv.x + prv.y*prv.y + prv.z*prv.z + prv.w*prv.w;
    #pragma unroll
    for (int o = 16; o >= 1; o >>= 1) {
        s0 += __shfl_xor_sync(0xffffffffu, s0, o);
        q0 += __shfl_xor_sync(0xffffffffu, q0, o);
        s1 += __shfl_xor_sync(0xffffffffu, s1, o);
        q1 += __shfl_xor_sync(0xffffffffu, q1, o);
    }
    __shared__ float red[4][8];
    int wid = tid >> 5, lane = tid & 31;
    if (lane == 0) { red[0][wid] = s0; red[1][wid] = q0; red[2][wid] = s1; red[3][wid] = q1; }
    __syncthreads();
    if (tid == 0) {
        float a0 = 0, a1 = 0, a2 = 0, a3 = 0;
        #pragma unroll
        for (int i = 0; i < 8; i++) { a0 += red[0][i]; a1 += red[1][i]; a2 += red[2][i]; a3 += red[3][i]; }
        red[0][0] = a0; red[1][0] = a1; red[2][0] = a2; red[3][0] = a3;
    }
    __syncthreads();
    float mu0 = red[0][0] * (1.0f / CC);
    float rs0 = rsqrtf(red[1][0] * (1.0f / CC) - mu0 * mu0 + EPS_LN);
    float mu1 = red[2][0] * (1.0f / CC);
    float rs1 = rsqrtf(red[3][0] * (1.0f / CC) - mu1 * mu1 + EPS_LN);

    float4 ww = ((const float4*)w)[tid];
    float4 bb = ((const float4*)b)[tid];
    float4 lc, lp;
    lc.x = (cur.x - mu0) * rs0 * ww.x + bb.x;
    lc.y = (cur.y - mu0) * rs0 * ww.y + bb.y;
    lc.z = (cur.z - mu0) * rs0 * ww.z + bb.z;
    lc.w = (cur.w - mu0) * rs0 * ww.w + bb.w;
    if (t > 0) {
        lp.x = (prv.x - mu1) * rs1 * ww.x + bb.x;
        lp.y = (prv.y - mu1) * rs1 * ww.y + bb.y;
        lp.z = (prv.z - mu1) * rs1 * ww.z + bb.z;
        lp.w = (prv.w - mu1) * rs1 * ww.w + bb.w;
    } else {
        lp = make_float4(0.f, 0.f, 0.f, 0.f);
    }
    float4 xx = make_float4(lp.x - lc.x, lp.y - lc.y, lp.z - lc.z, lp.w - lc.w);

    float4 a;
    uint2 o;
    a = ((const float4*)m0)[tid];
    o.x = pack_f16(lc.x + xx.x * a.x, lc.y + xx.y * a.y);
    o.y = pack_f16(lc.z + xx.z * a.z, lc.w + xx.w * a.w);
    ((uint2*)(o0 + off))[tid] = o;
    a = ((const float4*)m1)[tid];
    o.x = pack_f16(lc.x + xx.x * a.x, lc.y + xx.y * a.y);
    o.y = pack_f16(lc.z + xx.z * a.z, lc.w + xx.w * a.w);
    ((uint2*)(o1 + off))[tid] = o;
}

// ---------------- fp16 tensor-core GEMM core ----------------
#define STG_WORDS 9216
#define GEMM_SMEM (2 * STG_WORDS * 4)

__device__ __forceinline__ void mma_f16(float c[4],
                                        const uint32_t a[4],
                                        const uint32_t b[2])
{
    asm volatile(
        "mma.sync.aligned.m16n8k16.row.col.f32.f16.f16.f32 "
        "{%0,%1,%2,%3}, {%4,%5,%6,%7}, {%8,%9}, {%0,%1,%2,%3};\n"
        : "+f"(c[0]), "+f"(c[1]), "+f"(c[2]), "+f"(c[3])
        : "r"(a[0]), "r"(a[1]), "r"(a[2]), "r"(a[3]),
          "r"(b[0]), "r"(b[1]));
}

#define LDMATRIX_X4(r0, r1, r2, r3, addr) \
    asm volatile("ldmatrix.sync.aligned.m8n8.x4.shared.b16 {%0,%1,%2,%3}, [%4];" \
        : "=r"(r0), "=r"(r1), "=r"(r2), "=r"(r3) : "r"(addr))

__device__ __forceinline__ void gemm_mainloop(const __half* __restrict__ A,
                                              const __half* __restrict__ W,
                                              int K, int m0, int n0,
                                              uint32_t* smw, int tid,
                                              float acc[4][4][4])
{
    int lane = tid & 31;
    int j  = tid & 7;
    int r0 = tid >> 3;
    const __half* pA = A + ((size_t)m0 + r0) * K + j * 8;
    const __half* pW = W + ((size_t)n0 + r0) * K + j * 8;
    uint32_t smb = smem_u32(smw);
    uint32_t dstA = smb + (uint32_t)(r0 * 36 + j * 4) * 4u;
    uint32_t dstW = dstA + 4608u * 4u;
    int wid = tid >> 5;
    int wm = wid >> 2, wn = wid & 3;

    uint32_t aAddr[4], bAddr[2];
    #pragma unroll
    for (int mi = 0; mi < 4; mi++)
        aAddr[mi] = smb + (uint32_t)((wm * 64 + mi * 16 + (lane & 15)) * 36) * 4u
                        + (uint32_t)(lane >> 4) * 16u;
    #pragma unroll
    for (int p = 0; p < 2; p++)
        bAddr[p] = smb + 4608u * 4u
                 + (uint32_t)((wn * 32 + (p * 2 + (lane >> 4)) * 8 + (lane & 7)) * 36) * 4u
                 + (uint32_t)((lane >> 3) & 1) * 16u;

    int NC = K >> 6;

    #pragma unroll
    for (int s = 0; s < 2; s++) {
        uint32_t so = (uint32_t)(s * STG_WORDS) * 4u;
        int kf = s * 64;
        #pragma unroll
        for (int i = 0; i < 4; i++) {
            cp16(dstA + so + (uint32_t)(i * 32 * 36) * 4u, pA + (size_t)(i * 32) * K + kf);
            cp16(dstW + so + (uint32_t)(i * 32 * 36) * 4u, pW + (size_t)(i * 32) * K + kf);
        }
        CP_COMMIT();
    }

    for (int t = 0; t < NC; t++) {
        CP_WAIT_1();
        __syncthreads();
        uint32_t so = (uint32_t)((t & 1) * STG_WORDS) * 4u;

        #pragma unroll
        for (int kk = 0; kk < 4; kk++) {
            uint32_t ko = so + (uint32_t)kk * 32u;
            uint32_t af[4][4];
            uint32_t bf[4][2];
            #pragma unroll
            for (int mi = 0; mi < 4; mi++)
                LDMATRIX_X4(af[mi][0], af[mi][1], af[mi][2], af[mi][3], aAddr[mi] + ko);
            #pragma unroll
            for (int p = 0; p < 2; p++)
                LDMATRIX_X4(bf[2*p][0], bf[2*p][1], bf[2*p+1][0], bf[2*p+1][1], bAddr[p] + ko);
            #pragma unroll
            for (int mi = 0; mi < 4; mi++)
                #pragma unroll
                for (int ni = 0; ni < 4; ni++)
                    mma_f16(acc[mi][ni], af[mi], bf[ni]);
        }
        __syncthreads();

        int lc = t + 2;
        if (lc < NC) {
            uint32_t so2 = (uint32_t)((t & 1) * STG_WORDS) * 4u;
            int kf = lc * 64;
            #pragma unroll
            for (int i = 0; i < 4; i++) {
                cp16(dstA + so2 + (uint32_t)(i * 32 * 36) * 4u, pA + (size_t)(i * 32) * K + kf);
                cp16(dstW + so2 + (uint32_t)(i * 32 * 36) * 4u, pW + (size_t)(i * 32) * K + kf);
            }
        }
        CP_COMMIT();
    }
}

// epi codes: 2 relu^2 -> fp16, 5 sigmoid -> fp16,
//            6 acc*auxh + auxh2 -> f32 (final output), 7 acc + aux1(f32) -> fp16
__global__ void __launch_bounds__(256, 2)
gemm_hf_kernel(const __half* __restrict__ A, const __half* __restrict__ W,
               float* __restrict__ Co, __half* __restrict__ Coh,
               int Nn, int K, int epi,
               const float* __restrict__ aux1, const __half* __restrict__ auxh,
               const __half* __restrict__ auxh2)
{
    extern __shared__ uint32_t smw[];
    int tid = threadIdx.x;
    int n0 = blockIdx.x * 128;
    int m0 = blockIdx.y * 128;
    int wid = tid >> 5, lane = tid & 31;
    int wm = wid >> 2, wn = wid & 3;
    int gid = lane >> 2, tg = lane & 3;

    float acc[4][4][4];
    #pragma unroll
    for (int mi = 0; mi < 4; mi++)
        #pragma unroll
        for (int ni = 0; ni < 4; ni++)
            #pragma unroll
            for (int e = 0; e < 4; e++) acc[mi][ni][e] = 0.f;

    gemm_mainloop(A, W, K, m0, n0, smw, tid, acc);

    #pragma unroll
    for (int mi = 0; mi < 4; mi++) {
        int row0 = m0 + wm * 64 + mi * 16 + gid;
        #pragma unroll
        for (int ni = 0; ni < 4; ni++) {
            int col0 = n0 + wn * 32 + ni * 8 + tg * 2;
            size_t o0 = (size_t)row0 * Nn + col0;
            size_t o1 = (size_t)(row0 + 8) * Nn + col0;
            float a0 = acc[mi][ni][0], a1 = acc[mi][ni][1];
            float a2 = acc[mi][ni][2], a3 = acc[mi][ni][3];
            if (epi == 2) {
                a0 = fmaxf(a0, 0.f); a0 *= a0;
                a1 = fmaxf(a1, 0.f); a1 *= a1;
                a2 = fmaxf(a2, 0.f); a2 *= a2;
                a3 = fmaxf(a3, 0.f); a3 *= a3;
                *(uint32_t*)(Coh + o0) = pack_f16(a0, a1);
                *(uint32_t*)(Coh + o1) = pack_f16(a2, a3);
            } else if (epi == 5) {
                a0 = 1.f / (1.f + expf(-a0));
                a1 = 1.f / (1.f + expf(-a1));
                a2 = 1.f / (1.f + expf(-a2));
                a3 = 1.f / (1.f + expf(-a3));
                *(uint32_t*)(Coh + o0) = pack_f16(a0, a1);
                *(uint32_t*)(Coh + o1) = pack_f16(a2, a3);
            } else if (epi == 6) {
                float2 s0 = h2f(*(const uint32_t*)(auxh + o0));
                float2 s1 = h2f(*(const uint32_t*)(auxh + o1));
                float2 x0 = h2f(*(const uint32_t*)(auxh2 + o0));
                float2 x1v = h2f(*(const uint32_t*)(auxh2 + o1));
                float2 v0, v1;
                v0.x = a0 * s0.x + x0.x;
                v0.y = a1 * s0.y + x0.y;
                v1.x = a2 * s1.x + x1v.x;
                v1.y = a3 * s1.y + x1v.y;
                *(float2*)(Co + o0) = v0;
                *(float2*)(Co + o1) = v1;
            } else if (epi == 7) {
                a0 += aux1[o0]; a1 += aux1[o0 + 1];
                a2 += aux1[o1]; a3 += aux1[o1 + 1];
                *(uint32_t*)(Coh + o0) = pack_f16(a0, a1);
                *(uint32_t*)(Coh + o1) = pack_f16(a2, a3);
            }
        }
    }
}

// merged 4-GEMM kernel for tmix
struct Gemm4Args {
    const __half* A[4];
    const __half* W[4];
    __half* O[4];
    int silu[4];
};
__global__ void __launch_bounds__(256, 2)
gemm_hf4_kernel(Gemm4Args args)
{
    extern __shared__ uint32_t smw[];
    int z = blockIdx.z;
    const __half* A = args.A[z];
    const __half* W = args.W[z];
    __half* O = args.O[z];
    int silu = args.silu[z];

    int tid = threadIdx.x;
    int n0 = blockIdx.x * 128;
    int m0 = blockIdx.y * 128;
    int wid = tid >> 5, lane = tid & 31;
    int wm = wid >> 2, wn = wid & 3;
    int gid = lane >> 2, tg = lane & 3;

    float acc[4][4][4];
    #pragma unroll
    for (int mi = 0; mi < 4; mi++)
        #pragma unroll
        for (int ni = 0; ni < 4; ni++)
            #pragma unroll
            for (int e = 0; e < 4; e++) acc[mi][ni][e] = 0.f;

    gemm_mainloop(A, W, 1024, m0, n0, smw, tid, acc);

    #pragma unroll
    for (int mi = 0; mi < 4; mi++) {
        int row0 = m0 + wm * 64 + mi * 16 + gid;
        #pragma unroll
        for (int ni = 0; ni < 4; ni++) {
            int col0 = n0 + wn * 32 + ni * 8 + tg * 2;
            size_t o0 = (size_t)row0 * 1024 + col0;
            size_t o1 = (size_t)(row0 + 8) * 1024 + col0;
            float a0 = acc[mi][ni][0], a1 = acc[mi][ni][1];
            float a2 = acc[mi][ni][2], a3 = acc[mi][ni][3];
            if (silu) {
                a0 = a0 / (1.f + expf(-a0));
                a1 = a1 / (1.f + expf(-a1));
                a2 = a2 / (1.f + expf(-a2));
                a3 = a3 / (1.f + expf(-a3));
            }
            *(uint32_t*)(O + o0) = pack_f16(a0, a1);
            *(uint32_t*)(O + o1) = pack_f16(a2, a3);
        }
    }
}

// merged channel-mix pair: z=0 Wck (relu^2 -> hb, N=3072), z=1 Wcr (sigmoid -> sig, N=1024)
struct GemmCM2Args {
    const __half* A[2];
    const __half* W[2];
    __half* O[2];
    int Nn[2];
};
__global__ void __launch_bounds__(256, 2)
gemm_cm2_kernel(GemmCM2Args args)
{
    extern __shared__ uint32_t smw[];
    int z = blockIdx.z;
    int Nn = args.Nn[z];
    if (blockIdx.x * 128 >= Nn) return;
    const __half* A = args.A[z];
    const __half* W = args.W[z];
    __half* O = args.O[z];

    int tid = threadIdx.x;
    int n0 = blockIdx.x * 128;
    int m0 = blockIdx.y * 128;
    int wid = tid >> 5, lane = tid & 31;
    int wm = wid >> 2, wn = wid & 3;
    int gid = lane >> 2, tg = lane & 3;

    float acc[4][4][4];
    #pragma unroll
    for (int mi = 0; mi < 4; mi++)
        #pragma unroll
        for (int ni = 0; ni < 4; ni++)
            #pragma unroll
            for (int e = 0; e < 4; e++) acc[mi][ni][e] = 0.f;

    gemm_mainloop(A, W, 1024, m0, n0, smw, tid, acc);

    #pragma unroll
    for (int mi = 0; mi < 4; mi++) {
        int row0 = m0 + wm * 64 + mi * 16 + gid;
        #pragma unroll
        for (int ni = 0; ni < 4; ni++) {
            int col0 = n0 + wn * 32 + ni * 8 + tg * 2;
            size_t o0 = (size_t)row0 * Nn + col0;
            size_t o1 = (size_t)(row0 + 8) * Nn + col0;
            float a0 = acc[mi][ni][0], a1 = acc[mi][ni][1];
            float a2 = acc[mi][ni][2], a3 = acc[mi][ni][3];
            if (z == 0) {
                a0 = fmaxf(a0, 0.f); a0 *= a0;
                a1 = fmaxf(a1, 0.f); a1 *= a1;
                a2 = fmaxf(a2, 0.f); a2 *= a2;
                a3 = fmaxf(a3, 0.f); a3 *= a3;
            } else {
                a0 = 1.f / (1.f + expf(-a0));
                a1 = 1.f / (1.f + expf(-a1));
                a2 = 1.f / (1.f + expf(-a2));
                a3 = 1.f / (1.f + expf(-a3));
            }
            *(uint32_t*)(O + o0) = pack_f16(a0, a1);
            *(uint32_t*)(O + o1) = pack_f16(a2, a3);
        }
    }
}

// ---------------- WKV: per-subchunk contributions + chunk state ----------------
__global__ __launch_bounds__(256) void wkv_s_kernel(const __half* __restrict__ k,
                                                    const __half* __restrict__ v,
                                                    const float* __restrict__ decay,
                                                    float* __restrict__ S,
                                                    float* __restrict__ C)
{
    int blk = blockIdx.x;
    int c = blk % NCK;
    int h = (blk / NCK) % HH;
    int b = blk / (NCK * HH);
    __shared__ float ksm[64][64];
    __shared__ float vsm[64][64];
    __shared__ float wpow[128];
    int tid = threadIdx.x;
    float ew = expf(decay[h]);
    if (tid < 128) wpow[tid] = expf(-ew * (float)tid);
    int n0 = (tid >> 4) * 4;
    int m0 = (tid & 15) * 4;
    uint64_t Sacc[4][2];
    #pragma unroll
    for (int i = 0; i < 4; i++) { Sacc[i][0] = 0; Sacc[i][1] = 0; }

    size_t base = ((size_t)b * TT + (size_t)c * QQ) * CC + (size_t)h * NHD;
    float w64 = 0.f;

    for (int qc = 0; qc < 4; qc++) {
        __syncthreads();
        for (int l = tid; l < 64 * 16; l += 256) {
            int qq = l >> 4;
            int f  = (l & 15) * 4;
            uint2 kk = *(const uint2*)(k + base + (size_t)(qc * 64 + qq) * CC + f);
            uint2 vv = *(const uint2*)(v + base + (size_t)(qc * 64 + qq) * CC + f);
            float2 ka = h2f(kk.x), kb2 = h2f(kk.y);
            float2 va = h2f(vv.x), vb2 = h2f(vv.y);
            ksm[qq][f] = ka.x; ksm[qq][f+1] = ka.y; ksm[qq][f+2] = kb2.x; ksm[qq][f+3] = kb2.y;
            vsm[qq][f] = va.x; vsm[qq][f+1] = va.y; vsm[qq][f+2] = vb2.x; vsm[qq][f+3] = vb2.y;
        }
        __syncthreads();
        if (qc == 0) w64 = wpow[64];

        uint64_t acc2[4][2];
        #pragma unroll
        for (int i = 0; i < 4; i++) { acc2[i][0] = 0; acc2[i][1] = 0; }

        #pragma unroll 4
        for (int jl = 0; jl < 64; jl++) {
            float wq = wpow[63 - jl];
            float4 kk = *(const float4*)&ksm[jl][n0];
            ulonglong2 vp = *(const ulonglong2*)&vsm[jl][m0];
            uint64_t kb0 = bcast2(kk.x * wq);
            uint64_t kb1 = bcast2(kk.y * wq);
            uint64_t kb2 = bcast2(kk.z * wq);
            uint64_t kb3 = bcast2(kk.w * wq);
            fma2(acc2[0][0], kb0, vp.x); fma2(acc2[0][1], kb0, vp.y);
            fma2(acc2[1][0], kb1, vp.x); fma2(acc2[1][1], kb1, vp.y);
            fma2(acc2[2][0], kb2, vp.x); fma2(acc2[2][1], kb2, vp.y);
            fma2(acc2[3][0], kb3, vp.x); fma2(acc2[3][1], kb3, vp.y);
        }

        uint64_t wb = bcast2(w64);
        #pragma unroll
        for (int i = 0; i < 4; i++) {
            fma2w(Sacc[i][0], wb, acc2[i][0]);
            fma2w(Sacc[i][1], wb, acc2[i][1]);
        }

        if (qc < 3) {
            float* Cp = C + (size_t)blk * 12288 + (size_t)qc * 4096;
            #pragma unroll
            for (int i = 0; i < 4; i++) {
                float2 p0 = unpk2(acc2[i][0]);
                float2 p1 = unpk2(acc2[i][1]);
                *(float4*)(Cp + (n0 + i) * 64 + m0) = make_float4(p0.x, p0.y, p1.x, p1.y);
            }
        }
    }

    float* Sp = S + (size_t)blk * 4096;
    #pragma unroll
    for (int i = 0; i < 4; i++) {
        float2 p0 = unpk2(Sacc[i][0]);
        float2 p1 = unpk2(Sacc[i][1]);
        *(float4*)(Sp + (n0 + i) * 64 + m0) = make_float4(p0.x, p0.y, p1.x, p1.y);
    }
}

// ---------------- WKV: inter-chunk prefix scan (wide grid) ----------------
__global__ __launch_bounds__(256) void wkv_scan_kernel(const float* __restrict__ S,
                                                       const float* __restrict__ decay,
                                                       float* __restrict__ ST)
{
    int bh = blockIdx.x >> 4;
    int part = blockIdx.x & 15;
    int h = bh % HH;
    float ws = expf(-expf(decay[h]) * 256.0f);
    int e = part * 256 + threadIdx.x;
    size_t b0 = (size_t)bh * NCK * 4096;
    float st = 0.f;
    #pragma unroll
    for (int c = 0; c < NCK; c++) {
        ST[b0 + (size_t)c * 4096 + e] = st;
        st = ws * st + S[b0 + (size_t)c * 4096 + e];
    }
}

// ---------------- WKV: per-chunk output + fused GroupNorm*g (fp16 out) ----------------
#define WKV_Y_SMEM ((16384 + 16384 + 16384 + 256 + 128) * 4)
__global__ __launch_bounds__(256) void wkv_y_kernel(const __half* __restrict__ r,
                                                    const __half* __restrict__ k,
                                                    const __half* __restrict__ v,
                                                    const float* __restrict__ ST,
                                                    const float* __restrict__ C,
                                                    const float* __restrict__ decay,
                                                    const float* __restrict__ faaaa,
                                                    const float* __restrict__ gnw,
                                                    const float* __restrict__ gnb,
                                                    const __half* __restrict__ g,
                                                    __half* __restrict__ yg)
{
    extern __shared__ float sm[];
    float* ksm  = sm;
    float* vsm  = sm + 16384;
    float* sst  = sm + 32768;
    float* wpow = sm + 49152;
    float* gnsm = sm + 49408;

    int blk = blockIdx.x;
    int c = blk % NCK;
    int h = (blk / NCK) % HH;
    int b = blk / (NCK * HH);
    int tid = threadIdx.x;

    float ew = expf(decay[h]);
    float u  = faaaa[h];
    wpow[tid] = expf(-ew * (float)tid);
    if (tid < 64) gnsm[tid] = gnw[h * 64 + tid];
    else if (tid < 128) gnsm[tid] = gnb[h * 64 + tid - 64];

    size_t base = ((size_t)b * TT + (size_t)c * QQ) * CC + (size_t)h * NHD;

    for (int l = tid; l < 256 * 16; l += 256) {
        int qq = l >> 4;
        int f  = (l & 15) * 4;
        uint2 kk = *(const uint2*)(k + base + (size_t)qq * CC + f);
        uint2 vv = *(const uint2*)(v + base + (size_t)qq * CC + f);
        float2 ka = h2f(kk.x), kb2 = h2f(kk.y);
        float2 va = h2f(vv.x), vb2 = h2f(vv.y);
        ksm[qq * 64 + f] = ka.x; ksm[qq * 64 + f + 1] = ka.y;
        ksm[qq * 64 + f + 2] = kb2.x; ksm[qq * 64 + f + 3] = kb2.y;
        vsm[qq * 64 + f] = va.x; vsm[qq * 64 + f + 1] = va.y;
        vsm[qq * 64 + f + 2] = vb2.x; vsm[qq * 64 + f + 3] = vb2.y;
    }
    size_t sbase = (size_t)blk * 4096;
    for (int l = tid; l < 1024; l += 256)
        *(float4*)&sst[l * 4] = *(const float4*)(ST + sbase + (size_t)l * 4);
    __syncthreads();

    {
        float w64v = wpow[64];
        const float* Cp = C + (size_t)blk * 12288;
        #pragma unroll
        for (int s = 1; s < 4; s++) {
            for (int l = tid; l < 1024; l += 256) {
                float4 p4 = *(const float4*)&sst[(s - 1) * 4096 + l * 4];
                float4 c4 = *(const float4*)(Cp + (size_t)(s - 1) * 4096 + l * 4);
                float4 o4 = make_float4(w64v * p4.x + c4.x, w64v * p4.y + c4.y,
                                        w64v * p4.z + c4.z, w64v * p4.w + c4.w);
                *(float4*)&sst[s * 4096 + l * 4] = o4;
            }
        }
    }
    __syncthreads();

    int q  = tid;
    int qs = q >> 6;
    int ql = q & 63;
    float rrow[64];
    {
        const uint4* rg = (const uint4*)(r + base + (size_t)q * CC);
        #pragma unroll
        for (int f = 0; f < 8; f++) {
            uint4 t4 = rg[f];
            float2 p0 = h2f(t4.x), p1 = h2f(t4.y), p2 = h2f(t4.z), p3 = h2f(t4.w);
            rrow[f * 8 + 0] = p0.x; rrow[f * 8 + 1] = p0.y;
            rrow[f * 8 + 2] = p1.x; rrow[f * 8 + 3] = p1.y;
            rrow[f * 8 + 4] = p2.x; rrow[f * 8 + 5] = p2.y;
            rrow[f * 8 + 6] = p3.x; rrow[f * 8 + 7] = p3.y;
        }
    }
    uint64_t acc2[32];
    #pragma unroll
    for (int m = 0; m < 32; m++) acc2[m] = 0;

    const float* stq = sst + qs * 4096;
    #pragma unroll 8
    for (int n = 0; n < 64; n++) {
        uint64_t rb = bcast2(rrow[n]);
        const ulonglong2* srow = (const ulonglong2*)&stq[n * 64];
        #pragma unroll
        for (int m2 = 0; m2 < 16; m2++) {
            ulonglong2 s2 = srow[m2];
            fma2(acc2[2 * m2],     rb, s2.x);
            fma2(acc2[2 * m2 + 1], rb, s2.y);
        }
    }
    {
        uint64_t wb = bcast2(wpow[ql]);
        #pragma unroll
        for (int m = 0; m < 32; m++) mul2(acc2[m], wb);
    }

    int j0 = qs * 64;
    int jend = ql | 31;
    for (int jl = 0; jl <= jend; jl++) {
        float a = 0.f;
        const float4* krow = (const float4*)&ksm[(j0 + jl) * 64];
        #pragma unroll
        for (int n4 = 0; n4 < 16; n4++) {
            float4 k4 = krow[n4];
            a += rrow[n4 * 4 + 0] * k4.x + rrow[n4 * 4 + 1] * k4.y
               + rrow[n4 * 4 + 2] * k4.z + rrow[n4 * 4 + 3] * k4.w;
        }
        float coef = (jl < ql) ? wpow[ql - jl - 1] : ((jl == ql) ? u : 0.0f);
        uint64_t ab = bcast2(a * coef);
        const ulonglong2* vrow = (const ulonglong2*)&vsm[(j0 + jl) * 64];
        #pragma unroll
        for (int m2 = 0; m2 < 16; m2++) {
            ulonglong2 v2 = vrow[m2];
            fma2(acc2[2 * m2],     ab, v2.x);
            fma2(acc2[2 * m2 + 1], ab, v2.y);
        }
    }

    float yv[64];
    float ssum = 0.f, ssq = 0.f;
    #pragma unroll
    for (int m = 0; m < 32; m++) {
        float2 p = unpk2(acc2[m]);
        yv[2 * m] = p.x; yv[2 * m + 1] = p.y;
        ssum += p.x + p.y;
        ssq  += p.x * p.x + p.y * p.y;
    }
    float mu   = ssum * (1.0f / 64.0f);
    float var  = ssq * (1.0f / 64.0f) - mu * mu;
    float rstd = rsqrtf(var + EPS_GN);

    __half* yo = yg + base + (size_t)q * CC;
    const uint2* gg = (const uint2*)(g + base + (size_t)q * CC);
    #pragma unroll
    for (int m4 = 0; m4 < 16; m4++) {
        uint2 g2 = gg[m4];
        float2 g0 = h2f(g2.x), g1 = h2f(g2.y);
        float o0 = ((yv[m4 * 4 + 0] - mu) * rstd * gnsm[m4 * 4 + 0] + gnsm[64 + m4 * 4 + 0]) * g0.x;
        float o1 = ((yv[m4 * 4 + 1] - mu) * rstd * gnsm[m4 * 4 + 1] + gnsm[64 + m4 * 4 + 1]) * g0.y;
        float o2 = ((yv[m4 * 4 + 2] - mu) * rstd * gnsm[m4 * 4 + 2] + gnsm[64 + m4 * 4 + 2]) * g1.x;
        float o3 = ((yv[m4 * 4 + 3] - mu) * rstd * gnsm[m4 * 4 + 3] + gnsm[64 + m4 * 4 + 3]) * g1.y;
        uint2 ow;
        ow.x = pack_f16(o0, o1);
        ow.y = pack_f16(o2, o3);
        *(uint2*)(yo + m4 * 4) = ow;
    }
}

// ---------------- host launcher ----------------
extern "C" void kernel_launch(void* const* d_in, const int* in_sizes, int n_in,
                              void* d_out, int out_size)
{
    const float* x      = (const float*)d_in[0];
    const float* ln1w   = (const float*)d_in[1];
    const float* ln1b   = (const float*)d_in[2];
    const float* maak   = (const float*)d_in[3];
    const float* maav   = (const float*)d_in[4];
    const float* maar   = (const float*)d_in[5];
    const float* maag   = (const float*)d_in[6];
    const float* decay  = (const float*)d_in[7];
    const float* faaaa  = (const float*)d_in[8];
    const float* Wr     = (const float*)d_in[9];
    const float* Wk     = (const float*)d_in[10];
    const float* Wv     = (const float*)d_in[11];
    const float* Wg     = (const float*)d_in[12];
    const float* Wo     = (const float*)d_in[13];
    const float* gnw    = (const float*)d_in[14];
    const float* gnb    = (const float*)d_in[15];
    const float* ln2w   = (const float*)d_in[16];
    const float* ln2b   = (const float*)d_in[17];
    const float* cmaak  = (const float*)d_in[18];
    const float* cmaar  = (const float*)d_in[19];
    const float* Wck    = (const float*)d_in[20];
    const float* Wcv    = (const float*)d_in[21];
    const float* Wcr    = (const float*)d_in[22];
    float* out = (float*)d_out;

    float* sc = nullptr;
    cudaGetSymbolAddress((void**)&sc, g_scratch);

    __half* xk   = (__half*)(sc + OFF_XK);
    __half* xv   = (__half*)(sc + OFF_XV);
    __half* xr   = (__half*)(sc + OFF_XR);
    __half* xg   = (__half*)(sc + OFF_XG);
    __half* rb   = (__half*)(sc + OFF_R);
    __half* kb   = (__half*)(sc + OFF_K);
    __half* vb   = (__half*)(sc + OFF_V);
    __half* gb   = (__half*)(sc + OFF_G);
    __half* ygb  = (__half*)(sc + OFF_YG);
    __half* x1h  = (__half*)(sc + OFF_X1);
    __half* xk2  = (__half*)(sc + OFF_XK2);
    __half* xr2  = (__half*)(sc + OFF_XR2);
    __half* sig  = (__half*)(sc + OFF_SIG);
    __half* hb   = (__half*)(sc + OFF_H);
    float* Sb   = sc + OFF_S;
    float* STb  = sc + OFF_ST;
    float* Cb   = sc + OFF_C;
    __half* WrR  = (__half*)(sc + OFF_WR_R);
    __half* WkR  = (__half*)(sc + OFF_WK_R);
    __half* WvR  = (__half*)(sc + OFF_WV_R);
    __half* WgR  = (__half*)(sc + OFF_WG_R);
    __half* WoR  = (__half*)(sc + OFF_WO_R);
    __half* WcrR = (__half*)(sc + OFF_WCR_R);
    __half* WckR = (__half*)(sc + OFF_WCK_R);
    __half* WcvR = (__half*)(sc + OFF_WCV_R);

    cudaFuncSetAttribute(wkv_y_kernel, cudaFuncAttributeMaxDynamicSharedMemorySize, WKV_Y_SMEM);
    cudaFuncSetAttribute(gemm_hf_kernel, cudaFuncAttributeMaxDynamicSharedMemorySize, GEMM_SMEM);
    cudaFuncSetAttribute(gemm_hf4_kernel, cudaFuncAttributeMaxDynamicSharedMemorySize, GEMM_SMEM);
    cudaFuncSetAttribute(gemm_cm2_kernel, cudaFuncAttributeMaxDynamicSharedMemorySize, GEMM_SMEM);

    dim3 g1024(1024 / 128, MTOT / 128);
    dim3 g1024z4(1024 / 128, MTOT / 128, 4);
    dim3 gcm2(3072 / 128, MTOT / 128, 2);

    // ---- weight conversion: single launch ----
    {
        CvtArgs ca;
        const float* srcs[8] = {Wr, Wk, Wv, Wg, Wo, Wcr, Wck, Wcv};
        __half* dsts[8] = {WrR, WkR, WvR, WgR, WoR, WcrR, WckR, WcvR};
        int sz4[8] = {262144, 262144, 262144, 262144, 262144, 262144, 786432, 786432};
        int acc4 = 0;
        for (int i = 0; i < 8; i++) { ca.src[i] = srcs[i]; ca.dst[i] = dsts[i]; acc4 += sz4[i]; ca.end4[i] = acc4; }
        cvt_all_kernel<<<acc4 / 256, 256>>>(ca);
    }

    // ---- time mix ----
    ln_mix_kernel<4><<<MTOT, 256>>>(x, ln1w, ln1b, maak, maav, maar, maag, xk, xv, xr, xg);
    {
        Gemm4Args ga;
        ga.A[0] = xr; ga.W[0] = WrR; ga.O[0] = rb; ga.silu[0] = 0;
        ga.A[1] = xk; ga.W[1] = WkR; ga.O[1] = kb; ga.silu[1] = 0;
        ga.A[2] = xv; ga.W[2] = WvR; ga.O[2] = vb; ga.silu[2] = 0;
        ga.A[3] = xg; ga.W[3] = WgR; ga.O[3] = gb; ga.silu[3] = 1;
        gemm_hf4_kernel<<<g1024z4, 256, GEMM_SMEM>>>(ga);
    }

    wkv_s_kernel<<<BB * HH * NCK, 256>>>(kb, vb, decay, Sb, Cb);
    wkv_scan_kernel<<<BB * HH * 16, 256>>>(Sb, decay, STb);
    wkv_y_kernel<<<BB * HH * NCK, 256, WKV_Y_SMEM>>>(rb, kb, vb, STb, Cb, decay, faaaa,
                                                     gnw, gnb, gb, ygb);

    // x1h = tmix_out + x   (fp16 residual)
    gemm_hf_kernel<<<g1024, 256, GEMM_SMEM>>>(ygb, WoR, nullptr, x1h, 1024, 1024, 7, x, nullptr, nullptr);

    // ---- channel mix ----
    ln_mix_h_kernel<<<MTOT, 256>>>(x1h, ln2w, ln2b, cmaak, cmaar, xk2, xr2);
    {
        GemmCM2Args gc;
        gc.A[0] = xk2; gc.W[0] = WckR; gc.O[0] = hb;  gc.Nn[0] = 3072;  // relu^2
        gc.A[1] = xr2; gc.W[1] = WcrR; gc.O[1] = sig; gc.Nn[1] = 1024;  // sigmoid
        gemm_cm2_kernel<<<gcm2, 256, GEMM_SMEM>>>(gc);
    }
    gemm_hf_kernel<<<g1024, 256, GEMM_SMEM>>>(hb, WcvR, out, nullptr, 1024, 3072, 6,
                                              nullptr, sig, x1h); // sig*acc + x1h
}

// round 17
// speedup vs baseline: 1.5327x; 1.0602x over previous
#include <cuda_runtime.h>
#include <cuda_fp16.h>
#include <math.h>
#include <stdint.h>

// ---------------- problem constants ----------------
#define BB 4
#define TT 4096
#define CC 1024
#define HH 16
#define NHD 64
#define QQ 256
#define NCK 16
#define MTOT (BB*TT)          // 16384
#define BTC (BB*TT*CC)        // 16777216
#define EPS_LN 1e-5f
#define EPS_GN (1e-5f*64.0f)

// ---------------- scratch ----------------
#define SCR_TOTAL (19ull*BTC + 8388608ull + 12582912ull + 12582912ull)
__device__ float g_scratch[SCR_TOTAL];

#define OFF_XK   (1ull*BTC)      // fp16
#define OFF_XV   (2ull*BTC)
#define OFF_XR   (3ull*BTC)
#define OFF_XG   (4ull*BTC)
#define OFF_R    (5ull*BTC)      // fp16
#define OFF_K    (6ull*BTC)      // fp16
#define OFF_V    (7ull*BTC)      // fp16
#define OFF_G    (8ull*BTC)      // fp16
#define OFF_YG   (10ull*BTC)     // fp16
#define OFF_X1   (11ull*BTC)     // fp16
#define OFF_XK2  (13ull*BTC)     // fp16
#define OFF_XR2  (14ull*BTC)     // fp16
#define OFF_SIG  (15ull*BTC)     // fp16
#define OFF_H    (16ull*BTC)     // fp16 [16384,3072]
#define OFF_S    (19ull*BTC)
#define OFF_ST   (19ull*BTC + 4194304ull)
#define OFF_C    (19ull*BTC + 8388608ull)
#define OFF_WT   (19ull*BTC + 8388608ull + 12582912ull)
#define OFF_WR_R  (OFF_WT + 0ull)
#define OFF_WK_R  (OFF_WT + 1048576ull)
#define OFF_WV_R  (OFF_WT + 2097152ull)
#define OFF_WG_R  (OFF_WT + 3145728ull)
#define OFF_WO_R  (OFF_WT + 4194304ull)
#define OFF_WCR_R (OFF_WT + 5242880ull)
#define OFF_WCK_R (OFF_WT + 6291456ull)
#define OFF_WCV_R (OFF_WT + 9437184ull)

// ---------------- helpers ----------------
__device__ __forceinline__ uint32_t smem_u32(const void* p) {
    uint32_t a;
    asm("{ .reg .u64 t; cvta.to.shared.u64 t, %1; cvt.u32.u64 %0, t; }" : "=r"(a) : "l"(p));
    return a;
}

__device__ __forceinline__ uint32_t pack_f16(float a, float b) {
    __half2 h = __floats2half2_rn(a, b);
    return *(uint32_t*)&h;
}

__device__ __forceinline__ float2 h2f(uint32_t h) {
    __half2 v = *(__half2*)&h;
    return __half22float2(v);
}

// ---- packed f32x2 math ----
__device__ __forceinline__ uint64_t bcast2(float s) {
    uint64_t r;
    asm("mov.b64 %0, {%1, %1};" : "=l"(r) : "r"(__float_as_uint(s)));
    return r;
}
__device__ __forceinline__ uint64_t pk2(float a, float b) {
    uint64_t r;
    asm("mov.b64 %0, {%1, %2};" : "=l"(r) : "f"(a), "f"(b));
    return r;
}
__device__ __forceinline__ void fma2(uint64_t& d, uint64_t a, uint64_t b) {
    asm("fma.rn.f32x2 %0, %1, %2, %0;" : "+l"(d) : "l"(a), "l"(b));
}
__device__ __forceinline__ void fma2w(uint64_t& d, uint64_t w, uint64_t c) {
    asm("fma.rn.f32x2 %0, %0, %1, %2;" : "+l"(d) : "l"(w), "l"(c));
}
__device__ __forceinline__ void mul2(uint64_t& d, uint64_t b) {
    asm("mul.rn.f32x2 %0, %0, %1;" : "+l"(d) : "l"(b));
}
__device__ __forceinline__ float2 unpk2(uint64_t v) {
    float lo, hi;
    asm("mov.b64 {%0, %1}, %2;" : "=f"(lo), "=f"(hi) : "l"(v));
    return make_float2(lo, hi);
}

__device__ __forceinline__ void cp16(uint32_t dst, const void* src) {
    asm volatile("cp.async.cg.shared.global [%0], [%1], 16;" :: "r"(dst), "l"(src) : "memory");
}
#define CP_COMMIT() asm volatile("cp.async.commit_group;" ::: "memory")
#define CP_WAIT_1() asm volatile("cp.async.wait_group 1;" ::: "memory")

// ---------------- all-weight fp32 -> fp16 (single launch) ----------------
struct CvtArgs {
    const float* src[8];
    __half* dst[8];
    int end4[8];
};
__global__ __launch_bounds__(256) void cvt_all_kernel(CvtArgs a)
{
    int i = blockIdx.x * 256 + threadIdx.x;
    int seg = 0;
    #pragma unroll
    for (int s = 0; s < 7; s++) seg += (i >= a.end4[s]) ? 1 : 0;
    int base = (seg == 0) ? 0 : a.end4[seg - 1];
    int li = i - base;
    float4 v = ((const float4*)a.src[seg])[li];
    uint2 o;
    o.x = pack_f16(v.x, v.y);
    o.y = pack_f16(v.z, v.w);
    ((uint2*)a.dst[seg])[li] = o;
}

// ---------------- fused LayerNorm + time-shift mix (fp32 input) ----------------
template<int NOUT>
__global__ __launch_bounds__(256) void ln_mix_kernel(const float* __restrict__ x,
                                                     const float* __restrict__ w,
                                                     const float* __restrict__ b,
                                                     const float* __restrict__ m0,
                                                     const float* __restrict__ m1,
                                                     const float* __restrict__ m2,
                                                     const float* __restrict__ m3,
                                                     __half* __restrict__ o0,
                                                     __half* __restrict__ o1,
                                                     __half* __restrict__ o2,
                                                     __half* __restrict__ o3)
{
    int row = blockIdx.x;
    int t = row % TT;
    int tid = threadIdx.x;
    size_t off = (size_t)row * CC;
    float4 cur = ((const float4*)(x + off))[tid];
    float4 prv = make_float4(0.f, 0.f, 0.f, 0.f);
    if (t > 0) prv = ((const float4*)(x + off - CC))[tid];

    float s0 = cur.x + cur.y + cur.z + cur.w;
    float q0 = cur.x*cur.x + cur.y*cur.y + cur.z*cur.z + cur.w*cur.w;
    float s1 = prv.x + prv.y + prv.z + prv.w;
    float q1 = prv.x*prv.x + prv.y*prv.y + prv.z*prv.z + prv.w*prv.w;
    #pragma unroll
    for (int o = 16; o >= 1; o >>= 1) {
        s0 += __shfl_xor_sync(0xffffffffu, s0, o);
        q0 += __shfl_xor_sync(0xffffffffu, q0, o);
        s1 += __shfl_xor_sync(0xffffffffu, s1, o);
        q1 += __shfl_xor_sync(0xffffffffu, q1, o);
    }
    __shared__ float red[4][8];
    int wid = tid >> 5, lane = tid & 31;
    if (lane == 0) { red[0][wid] = s0; red[1][wid] = q0; red[2][wid] = s1; red[3][wid] = q1; }
    __syncthreads();
    if (tid == 0) {
        float a0 = 0, a1 = 0, a2 = 0, a3 = 0;
        #pragma unroll
        for (int i = 0; i < 8; i++) { a0 += red[0][i]; a1 += red[1][i]; a2 += red[2][i]; a3 += red[3][i]; }
        red[0][0] = a0; red[1][0] = a1; red[2][0] = a2; red[3][0] = a3;
    }
    __syncthreads();
    float mu0 = red[0][0] * (1.0f / CC);
    float rs0 = rsqrtf(red[1][0] * (1.0f / CC) - mu0 * mu0 + EPS_LN);
    float mu1 = red[2][0] * (1.0f / CC);
    float rs1 = rsqrtf(red[3][0] * (1.0f / CC) - mu1 * mu1 + EPS_LN);

    float4 ww = ((const float4*)w)[tid];
    float4 bb = ((const float4*)b)[tid];
    float4 lc, lp;
    lc.x = (cur.x - mu0) * rs0 * ww.x + bb.x;
    lc.y = (cur.y - mu0) * rs0 * ww.y + bb.y;
    lc.z = (cur.z - mu0) * rs0 * ww.z + bb.z;
    lc.w = (cur.w - mu0) * rs0 * ww.w + bb.w;
    if (t > 0) {
        lp.x = (prv.x - mu1) * rs1 * ww.x + bb.x;
        lp.y = (prv.y - mu1) * rs1 * ww.y + bb.y;
        lp.z = (prv.z - mu1) * rs1 * ww.z + bb.z;
        lp.w = (prv.w - mu1) * rs1 * ww.w + bb.w;
    } else {
        lp = make_float4(0.f, 0.f, 0.f, 0.f);
    }
    float4 xx = make_float4(lp.x - lc.x, lp.y - lc.y, lp.z - lc.z, lp.w - lc.w);

    float4 a;
    uint2 o;
    a = ((const float4*)m0)[tid];
    o.x = pack_f16(lc.x + xx.x * a.x, lc.y + xx.y * a.y);
    o.y = pack_f16(lc.z + xx.z * a.z, lc.w + xx.w * a.w);
    ((uint2*)(o0 + off))[tid] = o;
    a = ((const float4*)m1)[tid];
    o.x = pack_f16(lc.x + xx.x * a.x, lc.y + xx.y * a.y);
    o.y = pack_f16(lc.z + xx.z * a.z, lc.w + xx.w * a.w);
    ((uint2*)(o1 + off))[tid] = o;
    if (NOUT == 4) {
        a = ((const float4*)m2)[tid];
        o.x = pack_f16(lc.x + xx.x * a.x, lc.y + xx.y * a.y);
        o.y = pack_f16(lc.z + xx.z * a.z, lc.w + xx.w * a.w);
        ((uint2*)(o2 + off))[tid] = o;
        a = ((const float4*)m3)[tid];
        o.x = pack_f16(lc.x + xx.x * a.x, lc.y + xx.y * a.y);
        o.y = pack_f16(lc.z + xx.z * a.z, lc.w + xx.w * a.w);
        ((uint2*)(o3 + off))[tid] = o;
    }
}

// ---------------- fused LayerNorm + time-shift mix (fp16 input, 2 outputs) ----------------
__global__ __launch_bounds__(256) void ln_mix_h_kernel(const __half* __restrict__ x,
                                                       const float* __restrict__ w,
                                                       const float* __restrict__ b,
                                                       const float* __restrict__ m0,
                                                       const float* __restrict__ m1,
                                                       __half* __restrict__ o0,
                                                       __half* __restrict__ o1)
{
    int row = blockIdx.x;
    int t = row % TT;
    int tid = threadIdx.x;
    size_t off = (size_t)row * CC;
    uint2 c2 = ((const uint2*)(x + off))[tid];
    float2 ca = h2f(c2.x), cb = h2f(c2.y);
    float4 cur = make_float4(ca.x, ca.y, cb.x, cb.y);
    float4 prv = make_float4(0.f, 0.f, 0.f, 0.f);
    if (t > 0) {
        uint2 p2 = ((const uint2*)(x + off - CC))[tid];
        float2 pa = h2f(p2.x), pb = h2f(p2.y);
        prv = make_float4(pa.x, pa.y, pb.x, pb.y);
    }

    float s0 = cur.x + cur.y + cur.z + cur.w;
    float q0 = cur.x*cur.x + cur.y*cur.y + cur.z*cur.z + cur.w*cur.w;
    float s1 = prv.x + prv.y + prv.z + prv.w;
    float q1 = prv.x*prv.x + prv.y*prv.y + prv.z*prv.z + prv.w*prv.w;
    #pragma unroll
    for (int o = 16; o >= 1; o >>= 1) {
        s0 += __shfl_xor_sync(0xffffffffu, s0, o);
        q0 += __shfl_xor_sync(0xffffffffu, q0, o);
        s1 += __shfl_xor_sync(0xffffffffu, s1, o);
        q1 += __shfl_xor_sync(0xffffffffu, q1, o);
    }
    __shared__ float red[4][8];
    int wid = tid >> 5, lane = tid & 31;
    if (lane == 0) { red[0][wid] = s0; red[1][wid] = q0; red[2][wid] = s1; red[3][wid] = q1; }
    __syncthreads();
    if (tid == 0) {
        float a0 = 0, a1 = 0, a2 = 0, a3 = 0;
        #pragma unroll
        for (int i = 0; i < 8; i++) { a0 += red[0][i]; a1 += red[1][i]; a2 += red[2][i]; a3 += red[3][i]; }
        red[0][0] = a0; red[1][0] = a1; red[2][0] = a2; red[3][0] = a3;
    }
    __syncthreads();
    float mu0 = red[0][0] * (1.0f / CC);
    float rs0 = rsqrtf(red[1][0] * (1.0f / CC) - mu0 * mu0 + EPS_LN);
    float mu1 = red[2][0] * (1.0f / CC);
    float rs1 = rsqrtf(red[3][0] * (1.0f / CC) - mu1 * mu1 + EPS_LN);

    float4 ww = ((const float4*)w)[tid];
    float4 bb = ((const float4*)b)[tid];
    float4 lc, lp;
    lc.x = (cur.x - mu0) * rs0 * ww.x + bb.x;
    lc.y = (cur.y - mu0) * rs0 * ww.y + bb.y;
    lc.z = (cur.z - mu0) * rs0 * ww.z + bb.z;
    lc.w = (cur.w - mu0) * rs0 * ww.w + bb.w;
    if (t > 0) {
        lp.x = (prv.x - mu1) * rs1 * ww.x + bb.x;
        lp.y = (prv.y - mu1) * rs1 * ww.y + bb.y;
        lp.z = (prv.z - mu1) * rs1 * ww.z + bb.z;
        lp.w = (prv.w - mu1) * rs1 * ww.w + bb.w;
    } else {
        lp = make_float4(0.f, 0.f, 0.f, 0.f);
    }
    float4 xx = make_float4(lp.x - lc.x, lp.y - lc.y, lp.z - lc.z, lp.w - lc.w);

    float4 a;
    uint2 o;
    a = ((const float4*)m0)[tid];
    o.x = pack_f16(lc.x + xx.x * a.x, lc.y + xx.y * a.y);
    o.y = pack_f16(lc.z + xx.z * a.z, lc.w + xx.w * a.w);
    ((uint2*)(o0 + off))[tid] = o;
    a = ((const float4*)m1)[tid];
    o.x = pack_f16(lc.x + xx.x * a.x, lc.y + xx.y * a.y);
    o.y = pack_f16(lc.z + xx.z * a.z, lc.w + xx.w * a.w);
    ((uint2*)(o1 + off))[tid] = o;
}

// ---------------- fp16 tensor-core GEMM core ----------------
#define STG_WORDS 9216
#define GEMM_SMEM (2 * STG_WORDS * 4)

__device__ __forceinline__ void mma_f16(float c[4],
                                        const uint32_t a[4],
                                        const uint32_t b[2])
{
    asm volatile(
        "mma.sync.aligned.m16n8k16.row.col.f32.f16.f16.f32 "
        "{%0,%1,%2,%3}, {%4,%5,%6,%7}, {%8,%9}, {%0,%1,%2,%3};\n"
        : "+f"(c[0]), "+f"(c[1]), "+f"(c[2]), "+f"(c[3])
        : "r"(a[0]), "r"(a[1]), "r"(a[2]), "r"(a[3]),
          "r"(b[0]), "r"(b[1]));
}

#define LDMATRIX_X4(r0, r1, r2, r3, addr) \
    asm volatile("ldmatrix.sync.aligned.m8n8.x4.shared.b16 {%0,%1,%2,%3}, [%4];" \
        : "=r"(r0), "=r"(r1), "=r"(r2), "=r"(r3) : "r"(addr))

__device__ __forceinline__ void gemm_mainloop(const __half* __restrict__ A,
                                              const __half* __restrict__ W,
                                              int K, int m0, int n0,
                                              uint32_t* smw, int tid,
                                              float acc[4][4][4])
{
    int lane = tid & 31;
    int j  = tid & 7;
    int r0 = tid >> 3;
    const __half* pA = A + ((size_t)m0 + r0) * K + j * 8;
    const __half* pW = W + ((size_t)n0 + r0) * K + j * 8;
    uint32_t smb = smem_u32(smw);
    uint32_t dstA = smb + (uint32_t)(r0 * 36 + j * 4) * 4u;
    uint32_t dstW = dstA + 4608u * 4u;
    int wid = tid >> 5;
    int wm = wid >> 2, wn = wid & 3;

    uint32_t aAddr[4], bAddr[2];
    #pragma unroll
    for (int mi = 0; mi < 4; mi++)
        aAddr[mi] = smb + (uint32_t)((wm * 64 + mi * 16 + (lane & 15)) * 36) * 4u
                        + (uint32_t)(lane >> 4) * 16u;
    #pragma unroll
    for (int p = 0; p < 2; p++)
        bAddr[p] = smb + 4608u * 4u
                 + (uint32_t)((wn * 32 + (p * 2 + (lane >> 4)) * 8 + (lane & 7)) * 36) * 4u
                 + (uint32_t)((lane >> 3) & 1) * 16u;

    int NC = K >> 6;

    #pragma unroll
    for (int s = 0; s < 2; s++) {
        uint32_t so = (uint32_t)(s * STG_WORDS) * 4u;
        int kf = s * 64;
        #pragma unroll
        for (int i = 0; i < 4; i++) {
            cp16(dstA + so + (uint32_t)(i * 32 * 36) * 4u, pA + (size_t)(i * 32) * K + kf);
            cp16(dstW + so + (uint32_t)(i * 32 * 36) * 4u, pW + (size_t)(i * 32) * K + kf);
        }
        CP_COMMIT();
    }

    for (int t = 0; t < NC; t++) {
        CP_WAIT_1();
        __syncthreads();
        uint32_t so = (uint32_t)((t & 1) * STG_WORDS) * 4u;

        #pragma unroll
        for (int kk = 0; kk < 4; kk++) {
            uint32_t ko = so + (uint32_t)kk * 32u;
            uint32_t af[4][4];
            uint32_t bf[4][2];
            #pragma unroll
            for (int mi = 0; mi < 4; mi++)
                LDMATRIX_X4(af[mi][0], af[mi][1], af[mi][2], af[mi][3], aAddr[mi] + ko);
            #pragma unroll
            for (int p = 0; p < 2; p++)
                LDMATRIX_X4(bf[2*p][0], bf[2*p][1], bf[2*p+1][0], bf[2*p+1][1], bAddr[p] + ko);
            #pragma unroll
            for (int mi = 0; mi < 4; mi++)
                #pragma unroll
                for (int ni = 0; ni < 4; ni++)
                    mma_f16(acc[mi][ni], af[mi], bf[ni]);
        }
        __syncthreads();

        int lc = t + 2;
        if (lc < NC) {
            uint32_t so2 = (uint32_t)((t & 1) * STG_WORDS) * 4u;
            int kf = lc * 64;
            #pragma unroll
            for (int i = 0; i < 4; i++) {
                cp16(dstA + so2 + (uint32_t)(i * 32 * 36) * 4u, pA + (size_t)(i * 32) * K + kf);
                cp16(dstW + so2 + (uint32_t)(i * 32 * 36) * 4u, pW + (size_t)(i * 32) * K + kf);
            }
        }
        CP_COMMIT();
    }
}

// epi codes: 2 relu^2 -> fp16, 5 sigmoid -> fp16,
//            6 acc*auxh + auxh2 -> f32 (final output), 7 acc + aux1(f32) -> fp16
__global__ void __launch_bounds__(256, 2)
gemm_hf_kernel(const __half* __restrict__ A, const __half* __restrict__ W,
               float* __restrict__ Co, __half* __restrict__ Coh,
               int Nn, int K, int epi,
               const float* __restrict__ aux1, const __half* __restrict__ auxh,
               const __half* __restrict__ auxh2)
{
    extern __shared__ uint32_t smw[];
    int tid = threadIdx.x;
    int n0 = blockIdx.x * 128;
    int m0 = blockIdx.y * 128;
    int wid = tid >> 5, lane = tid & 31;
    int wm = wid >> 2, wn = wid & 3;
    int gid = lane >> 2, tg = lane & 3;

    float acc[4][4][4];
    #pragma unroll
    for (int mi = 0; mi < 4; mi++)
        #pragma unroll
        for (int ni = 0; ni < 4; ni++)
            #pragma unroll
            for (int e = 0; e < 4; e++) acc[mi][ni][e] = 0.f;

    gemm_mainloop(A, W, K, m0, n0, smw, tid, acc);

    #pragma unroll
    for (int mi = 0; mi < 4; mi++) {
        int row0 = m0 + wm * 64 + mi * 16 + gid;
        #pragma unroll
        for (int ni = 0; ni < 4; ni++) {
            int col0 = n0 + wn * 32 + ni * 8 + tg * 2;
            size_t o0 = (size_t)row0 * Nn + col0;
            size_t o1 = (size_t)(row0 + 8) * Nn + col0;
            float a0 = acc[mi][ni][0], a1 = acc[mi][ni][1];
            float a2 = acc[mi][ni][2], a3 = acc[mi][ni][3];
            if (epi == 2) {
                a0 = fmaxf(a0, 0.f); a0 *= a0;
                a1 = fmaxf(a1, 0.f); a1 *= a1;
                a2 = fmaxf(a2, 0.f); a2 *= a2;
                a3 = fmaxf(a3, 0.f); a3 *= a3;
                *(uint32_t*)(Coh + o0) = pack_f16(a0, a1);
                *(uint32_t*)(Coh + o1) = pack_f16(a2, a3);
            } else if (epi == 5) {
                a0 = 1.f / (1.f + expf(-a0));
                a1 = 1.f / (1.f + expf(-a1));
                a2 = 1.f / (1.f + expf(-a2));
                a3 = 1.f / (1.f + expf(-a3));
                *(uint32_t*)(Coh + o0) = pack_f16(a0, a1);
                *(uint32_t*)(Coh + o1) = pack_f16(a2, a3);
            } else if (epi == 6) {
                float2 s0 = h2f(*(const uint32_t*)(auxh + o0));
                float2 s1 = h2f(*(const uint32_t*)(auxh + o1));
                float2 x0 = h2f(*(const uint32_t*)(auxh2 + o0));
                float2 x1v = h2f(*(const uint32_t*)(auxh2 + o1));
                float2 v0, v1;
                v0.x = a0 * s0.x + x0.x;
                v0.y = a1 * s0.y + x0.y;
                v1.x = a2 * s1.x + x1v.x;
                v1.y = a3 * s1.y + x1v.y;
                *(float2*)(Co + o0) = v0;
                *(float2*)(Co + o1) = v1;
            } else if (epi == 7) {
                a0 += aux1[o0]; a1 += aux1[o0 + 1];
                a2 += aux1[o1]; a3 += aux1[o1 + 1];
                *(uint32_t*)(Coh + o0) = pack_f16(a0, a1);
                *(uint32_t*)(Coh + o1) = pack_f16(a2, a3);
            }
        }
    }
}

// merged 4-GEMM kernel for tmix
struct Gemm4Args {
    const __half* A[4];
    const __half* W[4];
    __half* O[4];
    int silu[4];
};
__global__ void __launch_bounds__(256, 2)
gemm_hf4_kernel(Gemm4Args args)
{
    extern __shared__ uint32_t smw[];
    int z = blockIdx.z;
    const __half* A = args.A[z];
    const __half* W = args.W[z];
    __half* O = args.O[z];
    int silu = args.silu[z];

    int tid = threadIdx.x;
    int n0 = blockIdx.x * 128;
    int m0 = blockIdx.y * 128;
    int wid = tid >> 5, lane = tid & 31;
    int wm = wid >> 2, wn = wid & 3;
    int gid = lane >> 2, tg = lane & 3;

    float acc[4][4][4];
    #pragma unroll
    for (int mi = 0; mi < 4; mi++)
        #pragma unroll
        for (int ni = 0; ni < 4; ni++)
            #pragma unroll
            for (int e = 0; e < 4; e++) acc[mi][ni][e] = 0.f;

    gemm_mainloop(A, W, 1024, m0, n0, smw, tid, acc);

    #pragma unroll
    for (int mi = 0; mi < 4; mi++) {
        int row0 = m0 + wm * 64 + mi * 16 + gid;
        #pragma unroll
        for (int ni = 0; ni < 4; ni++) {
            int col0 = n0 + wn * 32 + ni * 8 + tg * 2;
            size_t o0 = (size_t)row0 * 1024 + col0;
            size_t o1 = (size_t)(row0 + 8) * 1024 + col0;
            float a0 = acc[mi][ni][0], a1 = acc[mi][ni][1];
            float a2 = acc[mi][ni][2], a3 = acc[mi][ni][3];
            if (silu) {
                a0 = a0 / (1.f + expf(-a0));
                a1 = a1 / (1.f + expf(-a1));
                a2 = a2 / (1.f + expf(-a2));
                a3 = a3 / (1.f + expf(-a3));
            }
            *(uint32_t*)(O + o0) = pack_f16(a0, a1);
            *(uint32_t*)(O + o1) = pack_f16(a2, a3);
        }
    }
}

// merged channel-mix pair
struct GemmCM2Args {
    const __half* A[2];
    const __half* W[2];
    __half* O[2];
    int Nn[2];
};
__global__ void __launch_bounds__(256, 2)
gemm_cm2_kernel(GemmCM2Args args)
{
    extern __shared__ uint32_t smw[];
    int z = blockIdx.z;
    int Nn = args.Nn[z];
    if (blockIdx.x * 128 >= Nn) return;
    const __half* A = args.A[z];
    const __half* W = args.W[z];
    __half* O = args.O[z];

    int tid = threadIdx.x;
    int n0 = blockIdx.x * 128;
    int m0 = blockIdx.y * 128;
    int wid = tid >> 5, lane = tid & 31;
    int wm = wid >> 2, wn = wid & 3;
    int gid = lane >> 2, tg = lane & 3;

    float acc[4][4][4];
    #pragma unroll
    for (int mi = 0; mi < 4; mi++)
        #pragma unroll
        for (int ni = 0; ni < 4; ni++)
            #pragma unroll
            for (int e = 0; e < 4; e++) acc[mi][ni][e] = 0.f;

    gemm_mainloop(A, W, 1024, m0, n0, smw, tid, acc);

    #pragma unroll
    for (int mi = 0; mi < 4; mi++) {
        int row0 = m0 + wm * 64 + mi * 16 + gid;
        #pragma unroll
        for (int ni = 0; ni < 4; ni++) {
            int col0 = n0 + wn * 32 + ni * 8 + tg * 2;
            size_t o0 = (size_t)row0 * Nn + col0;
            size_t o1 = (size_t)(row0 + 8) * Nn + col0;
            float a0 = acc[mi][ni][0], a1 = acc[mi][ni][1];
            float a2 = acc[mi][ni][2], a3 = acc[mi][ni][3];
            if (z == 0) {
                a0 = fmaxf(a0, 0.f); a0 *= a0;
                a1 = fmaxf(a1, 0.f); a1 *= a1;
                a2 = fmaxf(a2, 0.f); a2 *= a2;
                a3 = fmaxf(a3, 0.f); a3 *= a3;
            } else {
                a0 = 1.f / (1.f + expf(-a0));
                a1 = 1.f / (1.f + expf(-a1));
                a2 = 1.f / (1.f + expf(-a2));
                a3 = 1.f / (1.f + expf(-a3));
            }
            *(uint32_t*)(O + o0) = pack_f16(a0, a1);
            *(uint32_t*)(O + o1) = pack_f16(a2, a3);
        }
    }
}

// ---------------- WKV: per-subchunk contributions + chunk state ----------------
__global__ __launch_bounds__(256) void wkv_s_kernel(const __half* __restrict__ k,
                                                    const __half* __restrict__ v,
                                                    const float* __restrict__ decay,
                                                    float* __restrict__ S,
                                                    float* __restrict__ C)
{
    int blk = blockIdx.x;
    int c = blk % NCK;
    int h = (blk / NCK) % HH;
    int b = blk / (NCK * HH);
    __shared__ float ksm[64][64];
    __shared__ float vsm[64][64];
    __shared__ float wpow[128];
    int tid = threadIdx.x;
    float ew = expf(decay[h]);
    if (tid < 128) wpow[tid] = expf(-ew * (float)tid);
    int n0 = (tid >> 4) * 4;
    int m0 = (tid & 15) * 4;
    uint64_t Sacc[4][2];
    #pragma unroll
    for (int i = 0; i < 4; i++) { Sacc[i][0] = 0; Sacc[i][1] = 0; }

    size_t base = ((size_t)b * TT + (size_t)c * QQ) * CC + (size_t)h * NHD;
    float w64 = 0.f;

    for (int qc = 0; qc < 4; qc++) {
        __syncthreads();
        for (int l = tid; l < 64 * 16; l += 256) {
            int qq = l >> 4;
            int f  = (l & 15) * 4;
            uint2 kk = *(const uint2*)(k + base + (size_t)(qc * 64 + qq) * CC + f);
            uint2 vv = *(const uint2*)(v + base + (size_t)(qc * 64 + qq) * CC + f);
            float2 ka = h2f(kk.x), kb2 = h2f(kk.y);
            float2 va = h2f(vv.x), vb2 = h2f(vv.y);
            ksm[qq][f] = ka.x; ksm[qq][f+1] = ka.y; ksm[qq][f+2] = kb2.x; ksm[qq][f+3] = kb2.y;
            vsm[qq][f] = va.x; vsm[qq][f+1] = va.y; vsm[qq][f+2] = vb2.x; vsm[qq][f+3] = vb2.y;
        }
        __syncthreads();
        if (qc == 0) w64 = wpow[64];

        uint64_t acc2[4][2];
        #pragma unroll
        for (int i = 0; i < 4; i++) { acc2[i][0] = 0; acc2[i][1] = 0; }

        #pragma unroll 4
        for (int jl = 0; jl < 64; jl++) {
            float wq = wpow[63 - jl];
            float4 kk = *(const float4*)&ksm[jl][n0];
            ulonglong2 vp = *(const ulonglong2*)&vsm[jl][m0];
            uint64_t kb0 = bcast2(kk.x * wq);
            uint64_t kb1 = bcast2(kk.y * wq);
            uint64_t kb2 = bcast2(kk.z * wq);
            uint64_t kb3 = bcast2(kk.w * wq);
            fma2(acc2[0][0], kb0, vp.x); fma2(acc2[0][1], kb0, vp.y);
            fma2(acc2[1][0], kb1, vp.x); fma2(acc2[1][1], kb1, vp.y);
            fma2(acc2[2][0], kb2, vp.x); fma2(acc2[2][1], kb2, vp.y);
            fma2(acc2[3][0], kb3, vp.x); fma2(acc2[3][1], kb3, vp.y);
        }

        uint64_t wb = bcast2(w64);
        #pragma unroll
        for (int i = 0; i < 4; i++) {
            fma2w(Sacc[i][0], wb, acc2[i][0]);
            fma2w(Sacc[i][1], wb, acc2[i][1]);
        }

        if (qc < 3) {
            float* Cp = C + (size_t)blk * 12288 + (size_t)qc * 4096;
            #pragma unroll
            for (int i = 0; i < 4; i++) {
                float2 p0 = unpk2(acc2[i][0]);
                float2 p1 = unpk2(acc2[i][1]);
                *(float4*)(Cp + (n0 + i) * 64 + m0) = make_float4(p0.x, p0.y, p1.x, p1.y);
            }
        }
    }

    float* Sp = S + (size_t)blk * 4096;
    #pragma unroll
    for (int i = 0; i < 4; i++) {
        float2 p0 = unpk2(Sacc[i][0]);
        float2 p1 = unpk2(Sacc[i][1]);
        *(float4*)(Sp + (n0 + i) * 64 + m0) = make_float4(p0.x, p0.y, p1.x, p1.y);
    }
}

// ---------------- WKV: inter-chunk prefix scan (wide grid) ----------------
__global__ __launch_bounds__(256) void wkv_scan_kernel(const float* __restrict__ S,
                                                       const float* __restrict__ decay,
                                                       float* __restrict__ ST)
{
    int bh = blockIdx.x >> 4;
    int part = blockIdx.x & 15;
    int h = bh % HH;
    float ws = expf(-expf(decay[h]) * 256.0f);
    int e = part * 256 + threadIdx.x;
    size_t b0 = (size_t)bh * NCK * 4096;
    float st = 0.f;
    #pragma unroll
    for (int c = 0; c < NCK; c++) {
        ST[b0 + (size_t)c * 4096 + e] = st;
        st = ws * st + S[b0 + (size_t)c * 4096 + e];
    }
}

// ---------------- WKV: per-chunk output, tensorized state part + fused GN*g ----------------
// smem bytes layout:
//   [0,65536)        ksm fp32 [256][64]
//   [65536,131072)   vsm fp32 [256][64]
//   [131072,167936)  rsm fp16, 256 rows x 144B stride (GEMM A layout)
//   [167936,204800)  sstT fp16, 4 subchunks x 64 rows(m) x 144B (GEMM W layout, transposed state)
//   [131072,198656)  ysm fp32 [256][66]  (REUSED after state-mma completes)
//   [204800,205824)  wpow[256]
//   [205824,206336)  gnsm[128]
#define WKV_Y_SMEM 206336
__global__ __launch_bounds__(256) void wkv_y_kernel(const __half* __restrict__ r,
                                                    const __half* __restrict__ k,
                                                    const __half* __restrict__ v,
                                                    const float* __restrict__ ST,
                                                    const float* __restrict__ C,
                                                    const float* __restrict__ decay,
                                                    const float* __restrict__ faaaa,
                                                    const float* __restrict__ gnw,
                                                    const float* __restrict__ gnb,
                                                    const __half* __restrict__ g,
                                                    __half* __restrict__ yg)
{
    extern __shared__ float sm[];
    char* smc = (char*)sm;
    float* ksm  = sm;                      // [256*64]
    float* vsm  = sm + 16384;
    float* ysm  = sm + 32768;              // 256 x 66 (reuse region)
    float* wpow = sm + 51200;
    float* gnsm = sm + 51456;
    uint32_t smb = smem_u32(sm);

    int blk = blockIdx.x;
    int c = blk % NCK;
    int h = (blk / NCK) % HH;
    int b = blk / (NCK * HH);
    int tid = threadIdx.x;
    int lane = tid & 31;
    int w = tid >> 5;

    float ew = expf(decay[h]);
    float u  = faaaa[h];
    wpow[tid] = expf(-ew * (float)tid);
    if (tid < 64) gnsm[tid] = gnw[h * 64 + tid];
    else if (tid < 128) gnsm[tid] = gnb[h * 64 + tid - 64];

    size_t base = ((size_t)b * TT + (size_t)c * QQ) * CC + (size_t)h * NHD;

    // stage k,v -> fp32 smem
    for (int l = tid; l < 256 * 16; l += 256) {
        int qq = l >> 4;
        int f  = (l & 15) * 4;
        uint2 kk = *(const uint2*)(k + base + (size_t)qq * CC + f);
        uint2 vv = *(const uint2*)(v + base + (size_t)qq * CC + f);
        float2 ka = h2f(kk.x), kb2 = h2f(kk.y);
        float2 va = h2f(vv.x), vb2 = h2f(vv.y);
        ksm[qq * 64 + f] = ka.x; ksm[qq * 64 + f + 1] = ka.y;
        ksm[qq * 64 + f + 2] = kb2.x; ksm[qq * 64 + f + 3] = kb2.y;
        vsm[qq * 64 + f] = va.x; vsm[qq * 64 + f + 1] = va.y;
        vsm[qq * 64 + f + 2] = vb2.x; vsm[qq * 64 + f + 3] = vb2.y;
    }

    // stage r -> fp16 smem (GEMM A layout: 144B row stride)
    {
        int j = tid & 7;
        int rr = tid >> 3;
        const __half* pr = r + base + (size_t)rr * CC + j * 8;
        #pragma unroll
        for (int i = 0; i < 8; i++) {
            uint4 t4 = *(const uint4*)(pr + (size_t)(i * 32) * CC);
            *(uint4*)(smc + 131072 + (rr + i * 32) * 144 + j * 16) = t4;
        }
    }

    // build transposed sub-chunk states sstT (fp16), chained per-thread 4x4 tile
    {
        int n0 = (tid >> 4) * 4;
        int m0 = (tid & 15) * 4;
        float w64 = expf(-ew * 64.0f);
        float stp[4][4];
        const float* STp = ST + (size_t)blk * 4096;
        #pragma unroll
        for (int i = 0; i < 4; i++) {
            float4 s4 = *(const float4*)(STp + (n0 + i) * 64 + m0);
            stp[i][0] = s4.x; stp[i][1] = s4.y; stp[i][2] = s4.z; stp[i][3] = s4.w;
        }
        #pragma unroll
        for (int mj = 0; mj < 4; mj++) {
            uint2 w2;
            w2.x = pack_f16(stp[0][mj], stp[1][mj]);
            w2.y = pack_f16(stp[2][mj], stp[3][mj]);
            *(uint2*)(smc + 167936 + (m0 + mj) * 144 + n0 * 2) = w2;
        }
        const float* Cp = C + (size_t)blk * 12288;
        #pragma unroll
        for (int s = 1; s < 4; s++) {
            #pragma unroll
            for (int i = 0; i < 4; i++) {
                float4 c4 = *(const float4*)(Cp + (size_t)(s - 1) * 4096 + (n0 + i) * 64 + m0);
                stp[i][0] = w64 * stp[i][0] + c4.x;
                stp[i][1] = w64 * stp[i][1] + c4.y;
                stp[i][2] = w64 * stp[i][2] + c4.z;
                stp[i][3] = w64 * stp[i][3] + c4.w;
            }
            #pragma unroll
            for (int mj = 0; mj < 4; mj++) {
                uint2 w2;
                w2.x = pack_f16(stp[0][mj], stp[1][mj]);
                w2.y = pack_f16(stp[2][mj], stp[3][mj]);
                *(uint2*)(smc + 167936 + s * 9216 + (m0 + mj) * 144 + n0 * 2) = w2;
            }
        }
    }
    __syncthreads();

    // ---- state mma: y_state[64q x 64m] = r[64q x 64n] @ sstT[64m x 64n]^T per sub-chunk ----
    float acc[2][8][4];
    {
        int s = w >> 1;
        int qb = s * 64 + (w & 1) * 32;
        uint32_t aA[2], bA[4];
        #pragma unroll
        for (int mi = 0; mi < 2; mi++)
            aA[mi] = smb + 131072u + (uint32_t)((qb + mi * 16 + (lane & 15)) * 144)
                         + (uint32_t)(lane >> 4) * 16u;
        #pragma unroll
        for (int p = 0; p < 4; p++)
            bA[p] = smb + 167936u + (uint32_t)s * 9216u
                  + (uint32_t)(((p * 2 + (lane >> 4)) * 8 + (lane & 7)) * 144)
                  + (uint32_t)((lane >> 3) & 1) * 16u;

        #pragma unroll
        for (int mi = 0; mi < 2; mi++)
            #pragma unroll
            for (int ni = 0; ni < 8; ni++)
                #pragma unroll
                for (int e = 0; e < 4; e++) acc[mi][ni][e] = 0.f;

        #pragma unroll
        for (int kk = 0; kk < 4; kk++) {
            uint32_t ko = (uint32_t)kk * 32u;
            uint32_t bf[8][2];
            #pragma unroll
            for (int p = 0; p < 4; p++)
                LDMATRIX_X4(bf[2*p][0], bf[2*p][1], bf[2*p+1][0], bf[2*p+1][1], bA[p] + ko);
            #pragma unroll
            for (int mi = 0; mi < 2; mi++) {
                uint32_t af[4];
                LDMATRIX_X4(af[0], af[1], af[2], af[3], aA[mi] + ko);
                #pragma unroll
                for (int ni = 0; ni < 8; ni++)
                    mma_f16(acc[mi][ni], af, bf[ni]);
            }
        }
    }
    __syncthreads();   // all reads of rsm/sstT done; safe to overwrite with ysm
    {
        int s = w >> 1;
        int qb = s * 64 + (w & 1) * 32;
        int gid = lane >> 2, tg = lane & 3;
        #pragma unroll
        for (int mi = 0; mi < 2; mi++) {
            int row = qb + mi * 16 + gid;
            #pragma unroll
            for (int ni = 0; ni < 8; ni++) {
                float* yp = ysm + row * 66 + ni * 8 + tg * 2;
                *(float2*)yp = make_float2(acc[mi][ni][0], acc[mi][ni][1]);
                *(float2*)(yp + 8 * 66) = make_float2(acc[mi][ni][2], acc[mi][ni][3]);
            }
        }
    }
    __syncthreads();

    // ---- per-thread intra part ----
    int q  = tid;
    int qs = q >> 6;
    int ql = q & 63;
    float rrow[64];
    {
        const uint4* rg = (const uint4*)(r + base + (size_t)q * CC);
        #pragma unroll
        for (int f = 0; f < 8; f++) {
            uint4 t4 = rg[f];
            float2 p0 = h2f(t4.x), p1 = h2f(t4.y), p2 = h2f(t4.z), p3 = h2f(t4.w);
            rrow[f * 8 + 0] = p0.x; rrow[f * 8 + 1] = p0.y;
            rrow[f * 8 + 2] = p1.x; rrow[f * 8 + 3] = p1.y;
            rrow[f * 8 + 4] = p2.x; rrow[f * 8 + 5] = p2.y;
            rrow[f * 8 + 6] = p3.x; rrow[f * 8 + 7] = p3.y;
        }
    }
    uint64_t acc2[32];
    {
        uint64_t wb = bcast2(wpow[ql]);
        const float* yr = ysm + q * 66;
        #pragma unroll
        for (int m2 = 0; m2 < 32; m2++) {
            float2 p = *(const float2*)(yr + m2 * 2);
            acc2[m2] = pk2(p.x, p.y);
            mul2(acc2[m2], wb);
        }
    }

    int j0 = qs * 64;
    int jend = ql | 31;
    for (int jl = 0; jl <= jend; jl++) {
        float a = 0.f;
        const float4* krow = (const float4*)&ksm[(j0 + jl) * 64];
        #pragma unroll
        for (int n4 = 0; n4 < 16; n4++) {
            float4 k4 = krow[n4];
            a += rrow[n4 * 4 + 0] * k4.x + rrow[n4 * 4 + 1] * k4.y
               + rrow[n4 * 4 + 2] * k4.z + rrow[n4 * 4 + 3] * k4.w;
        }
        float coef = (jl < ql) ? wpow[ql - jl - 1] : ((jl == ql) ? u : 0.0f);
        uint64_t ab = bcast2(a * coef);
        const ulonglong2* vrow = (const ulonglong2*)&vsm[(j0 + jl) * 64];
        #pragma unroll
        for (int m2 = 0; m2 < 16; m2++) {
            ulonglong2 v2 = vrow[m2];
            fma2(acc2[2 * m2],     ab, v2.x);
            fma2(acc2[2 * m2 + 1], ab, v2.y);
        }
    }

    // fused GroupNorm * g -> fp16
    float yv[64];
    float ssum = 0.f, ssq = 0.f;
    #pragma unroll
    for (int m = 0; m < 32; m++) {
        float2 p = unpk2(acc2[m]);
        yv[2 * m] = p.x; yv[2 * m + 1] = p.y;
        ssum += p.x + p.y;
        ssq  += p.x * p.x + p.y * p.y;
    }
    float mu   = ssum * (1.0f / 64.0f);
    float var  = ssq * (1.0f / 64.0f) - mu * mu;
    float rstd = rsqrtf(var + EPS_GN);

    __half* yo = yg + base + (size_t)q * CC;
    const uint2* gg = (const uint2*)(g + base + (size_t)q * CC);
    #pragma unroll
    for (int m4 = 0; m4 < 16; m4++) {
        uint2 g2 = gg[m4];
        float2 g0 = h2f(g2.x), g1 = h2f(g2.y);
        float o0 = ((yv[m4 * 4 + 0] - mu) * rstd * gnsm[m4 * 4 + 0] + gnsm[64 + m4 * 4 + 0]) * g0.x;
        float o1 = ((yv[m4 * 4 + 1] - mu) * rstd * gnsm[m4 * 4 + 1] + gnsm[64 + m4 * 4 + 1]) * g0.y;
        float o2 = ((yv[m4 * 4 + 2] - mu) * rstd * gnsm[m4 * 4 + 2] + gnsm[64 + m4 * 4 + 2]) * g1.x;
        float o3 = ((yv[m4 * 4 + 3] - mu) * rstd * gnsm[m4 * 4 + 3] + gnsm[64 + m4 * 4 + 3]) * g1.y;
        uint2 ow;
        ow.x = pack_f16(o0, o1);
        ow.y = pack_f16(o2, o3);
        *(uint2*)(yo + m4 * 4) = ow;
    }
}

// ---------------- host launcher ----------------
extern "C" void kernel_launch(void* const* d_in, const int* in_sizes, int n_in,
                              void* d_out, int out_size)
{
    const float* x      = (const float*)d_in[0];
    const float* ln1w   = (const float*)d_in[1];
    const float* ln1b   = (const float*)d_in[2];
    const float* maak   = (const float*)d_in[3];
    const float* maav   = (const float*)d_in[4];
    const float* maar   = (const float*)d_in[5];
    const float* maag   = (const float*)d_in[6];
    const float* decay  = (const float*)d_in[7];
    const float* faaaa  = (const float*)d_in[8];
    const float* Wr     = (const float*)d_in[9];
    const float* Wk     = (const float*)d_in[10];
    const float* Wv     = (const float*)d_in[11];
    const float* Wg     = (const float*)d_in[12];
    const float* Wo     = (const float*)d_in[13];
    const float* gnw    = (const float*)d_in[14];
    const float* gnb    = (const float*)d_in[15];
    const float* ln2w   = (const float*)d_in[16];
    const float* ln2b   = (const float*)d_in[17];
    const float* cmaak  = (const float*)d_in[18];
    const float* cmaar  = (const float*)d_in[19];
    const float* Wck    = (const float*)d_in[20];
    const float* Wcv    = (const float*)d_in[21];
    const float* Wcr    = (const float*)d_in[22];
    float* out = (float*)d_out;

    float* sc = nullptr;
    cudaGetSymbolAddress((void**)&sc, g_scratch);

    __half* xk   = (__half*)(sc + OFF_XK);
    __half* xv   = (__half*)(sc + OFF_XV);
    __half* xr   = (__half*)(sc + OFF_XR);
    __half* xg   = (__half*)(sc + OFF_XG);
    __half* rb   = (__half*)(sc + OFF_R);
    __half* kb   = (__half*)(sc + OFF_K);
    __half* vb   = (__half*)(sc + OFF_V);
    __half* gb   = (__half*)(sc + OFF_G);
    __half* ygb  = (__half*)(sc + OFF_YG);
    __half* x1h  = (__half*)(sc + OFF_X1);
    __half* xk2  = (__half*)(sc + OFF_XK2);
    __half* xr2  = (__half*)(sc + OFF_XR2);
    __half* sig  = (__half*)(sc + OFF_SIG);
    __half* hb   = (__half*)(sc + OFF_H);
    float* Sb   = sc + OFF_S;
    float* STb  = sc + OFF_ST;
    float* Cb   = sc + OFF_C;
    __half* WrR  = (__half*)(sc + OFF_WR_R);
    __half* WkR  = (__half*)(sc + OFF_WK_R);
    __half* WvR  = (__half*)(sc + OFF_WV_R);
    __half* WgR  = (__half*)(sc + OFF_WG_R);
    __half* WoR  = (__half*)(sc + OFF_WO_R);
    __half* WcrR = (__half*)(sc + OFF_WCR_R);
    __half* WckR = (__half*)(sc + OFF_WCK_R);
    __half* WcvR = (__half*)(sc + OFF_WCV_R);

    cudaFuncSetAttribute(wkv_y_kernel, cudaFuncAttributeMaxDynamicSharedMemorySize, WKV_Y_SMEM);
    cudaFuncSetAttribute(gemm_hf_kernel, cudaFuncAttributeMaxDynamicSharedMemorySize, GEMM_SMEM);
    cudaFuncSetAttribute(gemm_hf4_kernel, cudaFuncAttributeMaxDynamicSharedMemorySize, GEMM_SMEM);
    cudaFuncSetAttribute(gemm_cm2_kernel, cudaFuncAttributeMaxDynamicSharedMemorySize, GEMM_SMEM);

    dim3 g1024(1024 / 128, MTOT / 128);
    dim3 g1024z4(1024 / 128, MTOT / 128, 4);
    dim3 gcm2(3072 / 128, MTOT / 128, 2);

    // ---- weight conversion: single launch ----
    {
        CvtArgs ca;
        const float* srcs[8] = {Wr, Wk, Wv, Wg, Wo, Wcr, Wck, Wcv};
        __half* dsts[8] = {WrR, WkR, WvR, WgR, WoR, WcrR, WckR, WcvR};
        int sz4[8] = {262144, 262144, 262144, 262144, 262144, 262144, 786432, 786432};
        int acc4 = 0;
        for (int i = 0; i < 8; i++) { ca.src[i] = srcs[i]; ca.dst[i] = dsts[i]; acc4 += sz4[i]; ca.end4[i] = acc4; }
        cvt_all_kernel<<<acc4 / 256, 256>>>(ca);
    }

    // ---- time mix ----
    ln_mix_kernel<4><<<MTOT, 256>>>(x, ln1w, ln1b, maak, maav, maar, maag, xk, xv, xr, xg);
    {
        Gemm4Args ga;
        ga.A[0] = xr; ga.W[0] = WrR; ga.O[0] = rb; ga.silu[0] = 0;
        ga.A[1] = xk; ga.W[1] = WkR; ga.O[1] = kb; ga.silu[1] = 0;
        ga.A[2] = xv; ga.W[2] = WvR; ga.O[2] = vb; ga.silu[2] = 0;
        ga.A[3] = xg; ga.W[3] = WgR; ga.O[3] = gb; ga.silu[3] = 1;
        gemm_hf4_kernel<<<g1024z4, 256, GEMM_SMEM>>>(ga);
    }

    wkv_s_kernel<<<BB * HH * NCK, 256>>>(kb, vb, decay, Sb, Cb);
    wkv_scan_kernel<<<BB * HH * 16, 256>>>(Sb, decay, STb);
    wkv_y_kernel<<<BB * HH * NCK, 256, WKV_Y_SMEM>>>(rb, kb, vb, STb, Cb, decay, faaaa,
                                                     gnw, gnb, gb, ygb);

    // x1h = tmix_out + x   (fp16 residual)
    gemm_hf_kernel<<<g1024, 256, GEMM_SMEM>>>(ygb, WoR, nullptr, x1h, 1024, 1024, 7, x, nullptr, nullptr);

    // ---- channel mix ----
    ln_mix_h_kernel<<<MTOT, 256>>>(x1h, ln2w, ln2b, cmaak, cmaar, xk2, xr2);
    {
        GemmCM2Args gc;
        gc.A[0] = xk2; gc.W[0] = WckR; gc.O[0] = hb;  gc.Nn[0] = 3072;  // relu^2
        gc.A[1] = xr2; gc.W[1] = WcrR; gc.O[1] = sig; gc.Nn[1] = 1024;  // sigmoid
        gemm_cm2_kernel<<<gcm2, 256, GEMM_SMEM>>>(gc);
    }
    gemm_hf_kernel<<<g1024, 256, GEMM_SMEM>>>(hb, WcvR, out, nullptr, 1024, 3072, 6,
                                              nullptr, sig, x1h); // sig*acc + x1h
}